// round 8
// baseline (speedup 1.0000x reference)
#include <cuda_runtime.h>
#include <stdint.h>
#include <math.h>

// ---------------------------------------------------------------------------
// Problem constants
// ---------------------------------------------------------------------------
#define BATCH   2
#define LSEQ    2048
#define DIMC    256
#define DI      512          // d_inner
#define DS      64           // d_state
#define DTR     16           // dt_rank
#define XDBLW   144          // dt_rank + 2*d_state
#define NTOK    (BATCH*LSEQ) // 4096
#define SQRT_INV_8192 0.011048543456039806f
#define LAMBDA_SS 0.01f
#define PI_F 3.14159265358979323846f

// ---------------------------------------------------------------------------
// Scratch (single __device__ array; no allocations anywhere)
// ---------------------------------------------------------------------------
#define O_XN    ((size_t)0)
#define O_XZ    (O_XN   + (size_t)NTOK*DIMC)
#define O_XC    (O_XZ   + (size_t)NTOK*2*DI)
#define O_XDBL  (O_XC   + (size_t)NTOK*DI)
#define O_Y     (O_XDBL + (size_t)NTOK*XDBLW)
#define O_X1    (O_Y    + (size_t)NTOK*DI)
#define O_XN2   (O_X1   + (size_t)NTOK*DIMC)
#define O_FR    (O_XN2  + (size_t)NTOK*DIMC)
#define O_FI    (O_FR   + (size_t)NTOK*DIMC)
#define O_END   (O_FI   + (size_t)NTOK*DIMC)

__device__ float SCRATCH[O_END];

// ---------------------------------------------------------------------------
// cp.async helpers
// ---------------------------------------------------------------------------
__device__ __forceinline__ void cp16(unsigned dst, const void* src, int sz) {
    asm volatile("cp.async.cg.shared.global [%0], [%1], 16, %2;"
                 :: "r"(dst), "l"(src), "r"(sz));
}
__device__ __forceinline__ void cp_commit() {
    asm volatile("cp.async.commit_group;" ::: "memory");
}
template <int N>
__device__ __forceinline__ void cp_wait() {
    asm volatile("cp.async.wait_group %0;" :: "n"(N) : "memory");
}

// ---------------------------------------------------------------------------
// LayerNorm: one warp per token (256 channels), 8 tokens per 256-thread block
// ---------------------------------------------------------------------------
__global__ void ln_kernel(const float* __restrict__ x,
                          const float* __restrict__ w,
                          const float* __restrict__ b,
                          float* __restrict__ out) {
    int t = blockIdx.x * 8 + (threadIdx.x >> 5);
    int lane = threadIdx.x & 31;
    const float4* row = (const float4*)(x + (size_t)t * DIMC);
    float4 v0 = row[lane];
    float4 v1 = row[lane + 32];
    float s = v0.x + v0.y + v0.z + v0.w + v1.x + v1.y + v1.z + v1.w;
    #pragma unroll
    for (int off = 16; off; off >>= 1) s += __shfl_xor_sync(0xffffffffu, s, off);
    float m = s * (1.0f / 256.0f);
    float d0 = v0.x - m, d1 = v0.y - m, d2 = v0.z - m, d3 = v0.w - m;
    float d4 = v1.x - m, d5 = v1.y - m, d6 = v1.z - m, d7 = v1.w - m;
    float q = d0*d0 + d1*d1 + d2*d2 + d3*d3 + d4*d4 + d5*d5 + d6*d6 + d7*d7;
    #pragma unroll
    for (int off = 16; off; off >>= 1) q += __shfl_xor_sync(0xffffffffu, q, off);
    float inv = rsqrtf(q * (1.0f / 256.0f) + 1e-5f);
    const float4* w4 = (const float4*)w;
    const float4* b4 = (const float4*)b;
    float4* o4 = (float4*)(out + (size_t)t * DIMC);
    float4 wa = w4[lane], ba = b4[lane];
    float4 wb = w4[lane + 32], bb = b4[lane + 32];
    float4 r0, r1;
    r0.x = d0*inv*wa.x + ba.x; r0.y = d1*inv*wa.y + ba.y;
    r0.z = d2*inv*wa.z + ba.z; r0.w = d3*inv*wa.w + ba.w;
    r1.x = d4*inv*wb.x + bb.x; r1.y = d5*inv*wb.y + bb.y;
    r1.z = d6*inv*wb.z + bb.z; r1.w = d7*inv*wb.w + bb.w;
    o4[lane] = r0; o4[lane + 32] = r1;
}

// ---------------------------------------------------------------------------
// tf32 tensor-core GEMM: C[M,N] = A[M,K] * W[N,K]^T (+ R[M,N]).
// 128x64 block tile, BK=16, 256 threads = 8 warps (4m x 2n), warp tile 32x32
// via 2x4 mma.sync.m16n8k8.tf32.  4-stage cp.async pipeline; raw fp32 bits
// fed to HMMA (hardware truncates to tf32).  (R6 config - known best.)
// ---------------------------------------------------------------------------
#define GBM 128
#define GBN 64
#define ASTR 20
#define GSTAGES 4
#define GEMM_SMEM (GSTAGES * (GBM + GBN) * ASTR * 4)

__device__ __forceinline__ void mma_tf32(float* c, const unsigned* a, const unsigned* b) {
    asm volatile(
        "mma.sync.aligned.m16n8k8.row.col.f32.tf32.tf32.f32 "
        "{%0,%1,%2,%3}, {%4,%5,%6,%7}, {%8,%9}, {%0,%1,%2,%3};"
        : "+f"(c[0]), "+f"(c[1]), "+f"(c[2]), "+f"(c[3])
        : "r"(a[0]), "r"(a[1]), "r"(a[2]), "r"(a[3]), "r"(b[0]), "r"(b[1]));
}

__global__ void __launch_bounds__(256) gemm_tf32(const float* __restrict__ A,
                                                 const float* __restrict__ W,
                                                 const float* __restrict__ R,
                                                 float* __restrict__ C,
                                                 int M, int N, int K) {
    extern __shared__ float gsm[];
    float* As = gsm;                                // GSTAGES * GBM * ASTR
    float* Bs = gsm + GSTAGES * GBM * ASTR;         // GSTAGES * GBN * ASTR
    unsigned smA = (unsigned)__cvta_generic_to_shared(As);
    unsigned smB = (unsigned)__cvta_generic_to_shared(Bs);

    int m0 = blockIdx.y * GBM;
    int n0 = blockIdx.x * GBN;
    int tid = threadIdx.x;
    int wid = tid >> 5, lane = tid & 31;
    int wm = (wid & 3) * 32;
    int wn = (wid >> 2) * 32;
    int gid = lane >> 2;       // 0..7
    int tig = lane & 3;        // 0..3
    int ar = tid >> 1, ak = (tid & 1) * 8;
    int br = tid >> 2, bk = (tid & 3) * 4;

    const float* Abase = A + (size_t)(m0 + ar) * K + ak;
    bool bok = (n0 + br) < N;
    const float* Bbase = bok ? (W + (size_t)(n0 + br) * K + bk) : W;
    int bsz = bok ? 16 : 0;
    unsigned adst = smA + (unsigned)(ar * ASTR + ak) * 4u;
    unsigned bdst = smB + (unsigned)(br * ASTR + bk) * 4u;
    const unsigned aStage = GBM * ASTR * 4u;
    const unsigned bStage = GBN * ASTR * 4u;

    float acc[2][4][4];
    #pragma unroll
    for (int mi = 0; mi < 2; mi++)
        #pragma unroll
        for (int ni = 0; ni < 4; ni++)
            #pragma unroll
            for (int q = 0; q < 4; q++) acc[mi][ni][q] = 0.0f;

    int nIt = K >> 4;
    // prologue: stages 0..GSTAGES-2
    #pragma unroll
    for (int s = 0; s < GSTAGES - 1; s++) {
        cp16(adst + s * aStage,      Abase + s * 16,     16);
        cp16(adst + s * aStage + 16, Abase + s * 16 + 4, 16);
        cp16(bdst + s * bStage,      Bbase + (bok ? s * 16 : 0), bsz);
        cp_commit();
    }

    for (int it = 0; it < nIt; it++) {
        cp_wait<GSTAGES - 2>();
        __syncthreads();
        int buf = it & (GSTAGES - 1);
        const float* Ab = As + buf * (GBM * ASTR);
        const float* Bb = Bs + buf * (GBN * ASTR);
        #pragma unroll
        for (int ks = 0; ks < 2; ks++) {
            int k8 = ks * 8;
            unsigned afr[2][4], bfr[4][2];
            #pragma unroll
            for (int mi = 0; mi < 2; mi++) {
                int rb = wm + mi * 16 + gid;
                afr[mi][0] = __float_as_uint(Ab[(rb)     * ASTR + k8 + tig]);
                afr[mi][1] = __float_as_uint(Ab[(rb + 8) * ASTR + k8 + tig]);
                afr[mi][2] = __float_as_uint(Ab[(rb)     * ASTR + k8 + tig + 4]);
                afr[mi][3] = __float_as_uint(Ab[(rb + 8) * ASTR + k8 + tig + 4]);
            }
            #pragma unroll
            for (int ni = 0; ni < 4; ni++) {
                int cb = wn + ni * 8 + gid;
                bfr[ni][0] = __float_as_uint(Bb[cb * ASTR + k8 + tig]);
                bfr[ni][1] = __float_as_uint(Bb[cb * ASTR + k8 + tig + 4]);
            }
            #pragma unroll
            for (int mi = 0; mi < 2; mi++)
                #pragma unroll
                for (int ni = 0; ni < 4; ni++)
                    mma_tf32(acc[mi][ni], afr[mi], bfr[ni]);
        }
        int nx = it + GSTAGES - 1;
        if (nx < nIt) {
            int slot = nx & (GSTAGES - 1);
            cp16(adst + slot * aStage,      Abase + nx * 16,     16);
            cp16(adst + slot * aStage + 16, Abase + nx * 16 + 4, 16);
            cp16(bdst + slot * bStage,      Bbase + (bok ? nx * 16 : 0), bsz);
        }
        cp_commit();
    }

    #pragma unroll
    for (int mi = 0; mi < 2; mi++) {
        int row = m0 + wm + mi * 16 + gid;
        #pragma unroll
        for (int ni = 0; ni < 4; ni++) {
            int col = n0 + wn + ni * 8 + tig * 2;
            if (col < N) {
                float v0 = acc[mi][ni][0];
                float v2 = acc[mi][ni][2];
                if (R) { v0 += R[(size_t)row * N + col]; v2 += R[(size_t)(row + 8) * N + col]; }
                C[(size_t)row * N + col] = v0;
                C[(size_t)(row + 8) * N + col] = v2;
            }
            if (col + 1 < N) {
                float v1 = acc[mi][ni][1];
                float v3 = acc[mi][ni][3];
                if (R) { v1 += R[(size_t)row * N + col + 1]; v3 += R[(size_t)(row + 8) * N + col + 1]; }
                C[(size_t)row * N + col + 1] = v1;
                C[(size_t)(row + 8) * N + col + 1] = v3;
            }
        }
    }
}

// ---------------------------------------------------------------------------
// Depthwise causal conv (k=4) + bias + SiLU.  xz[:, 0:512] -> xc
// ---------------------------------------------------------------------------
__global__ void conv_silu_kernel(const float* __restrict__ xz,
                                 const float* __restrict__ cw,
                                 const float* __restrict__ cb,
                                 float* __restrict__ xc) {
    int idx = blockIdx.x * 256 + threadIdx.x;   // NTOK*DI
    int d = idx & (DI - 1);
    int bt = idx >> 9;
    int b = bt >> 11;
    int l = bt & (LSEQ - 1);
    float acc = cb[d];
    #pragma unroll
    for (int k = 0; k < 4; k++) {
        int ls = l + k - 3;
        if (ls >= 0)
            acc += xz[((size_t)((b << 11) | ls)) * (2 * DI) + d] * cw[d * 4 + k];
    }
    float sg = 1.0f / (1.0f + __expf(-acc));
    xc[(size_t)bt * DI + d] = acc * sg;
}

// ---------------------------------------------------------------------------
// Selective scan with fused dt; deferred reduce-scatter for y.
// ---------------------------------------------------------------------------
#define TCHUNK 64
__global__ void __launch_bounds__(256) scan_kernel(
        const float* __restrict__ xdbl,
        const float* __restrict__ xc,
        const float* __restrict__ xz,
        const float* __restrict__ A_log,
        const float* __restrict__ Dvec,
        const float* __restrict__ dtw,
        const float* __restrict__ dtb,
        float* __restrict__ y) {
    __shared__ float sB[TCHUNK][64];
    __shared__ float sC[TCHUNK][64];
    __shared__ float sx16[TCHUNK][16];
    __shared__ float2 sdx[TCHUNK][8];   // (dt, xc)
    __shared__ float sz[TCHUNK][8];
    __shared__ float sy[TCHUNK][8];
    __shared__ float sw[8][16];
    __shared__ float sbias[8];

    int b = blockIdx.x >> 6;
    int dbase = (blockIdx.x & 63) * 8;
    int wid = threadIdx.x >> 5;
    int lane = threadIdx.x & 31;
    int d = dbase + wid;

    if (threadIdx.x < 128) {
        int di = threadIdx.x >> 4, r = threadIdx.x & 15;
        sw[di][r] = dtw[(dbase + di) * DTR + r];
        if (r == 0) sbias[di] = dtb[dbase + di];
    }
    float A0 = -__expf(A_log[d * DS + lane]);
    float A1 = -__expf(A_log[d * DS + lane + 32]);
    float Dd = Dvec[d];
    float h0 = 0.0f, h1 = 0.0f;

    for (int t0 = 0; t0 < LSEQ; t0 += TCHUNK) {
        for (int i = threadIdx.x; i < TCHUNK * 128; i += 256) {
            int tt = i >> 7;
            int c = i & 127;
            float v = xdbl[(size_t)(b * LSEQ + t0 + tt) * XDBLW + DTR + c];
            if (c < 64) sB[tt][c] = v; else sC[tt][c - 64] = v;
        }
        for (int i = threadIdx.x; i < TCHUNK * 16; i += 256) {
            int tt = i >> 4, r = i & 15;
            sx16[tt][r] = xdbl[(size_t)(b * LSEQ + t0 + tt) * XDBLW + r];
        }
        for (int i = threadIdx.x; i < TCHUNK * 8; i += 256) {
            int tt = i >> 3, di = i & 7;
            size_t bt = (size_t)(b * LSEQ + t0 + tt);
            sdx[tt][di].y = xc[bt * DI + dbase + di];
            sz[tt][di]    = xz[bt * (2 * DI) + DI + dbase + di];
        }
        __syncthreads();
        for (int i = threadIdx.x; i < TCHUNK * 8; i += 256) {
            int tt = i >> 3, di = i & 7;
            float acc = sbias[di];
            #pragma unroll
            for (int r = 0; r < 16; r++) acc = fmaf(sx16[tt][r], sw[di][r], acc);
            sdx[tt][di].x = (acc > 20.0f) ? acc : __logf(1.0f + __expf(acc));
        }
        __syncthreads();

        #pragma unroll 1
        for (int g = 0; g < TCHUNK / 32; g++) {
            float part[32];
            #pragma unroll
            for (int j = 0; j < 32; j++) {
                int tt = g * 32 + j;
                float2 dx = sdx[tt][wid];
                float du = dx.x * dx.y;
                float dA0 = __expf(dx.x * A0);
                float dA1 = __expf(dx.x * A1);
                h0 = fmaf(dA0, h0, du * sB[tt][lane]);
                h1 = fmaf(dA1, h1, du * sB[tt][lane + 32]);
                part[j] = fmaf(h0, sC[tt][lane], h1 * sC[tt][lane + 32]);
            }
            #pragma unroll
            for (int s = 16; s >= 1; s >>= 1) {
                bool up = (lane & s) != 0;
                #pragma unroll
                for (int i2 = 0; i2 < 16; i2++) {
                    if (i2 >= s) break;
                    float keep = up ? part[i2 + s] : part[i2];
                    float send = up ? part[i2] : part[i2 + s];
                    part[i2] = keep + __shfl_xor_sync(0xffffffffu, send, s);
                }
            }
            int tt = g * 32 + lane;
            float2 dx = sdx[tt][wid];
            float zv = sz[tt][wid];
            float gate = zv / (1.0f + __expf(-zv));
            sy[tt][wid] = fmaf(dx.y, Dd, part[0]) * gate;
        }
        __syncthreads();
        for (int i = threadIdx.x; i < TCHUNK * 8; i += 256) {
            int tt = i >> 3, di = i & 7;
            y[(size_t)(b * LSEQ + t0 + tt) * DI + dbase + di] = sy[tt][di];
        }
        __syncthreads();
    }
}

// ---------------------------------------------------------------------------
// 2048-pt FFT with shared-memory twiddle table.
// Table layout: tw[half + j] = exp(-i*pi*j/half), half = 1,2,...,1024 (2048
// float2 entries, tw[0] unused).  Lookups are consecutive -> conflict-free.
// Forward DIF (natural -> bit-reversed); inverse DIT uses the conjugate.
// 2 channels per block (256 blocks), float2 global I/O, stride 2049.
// ---------------------------------------------------------------------------
#define FSTR 2049
#define FFT_SMEM ((2 * 2 * FSTR + 2 * 2048) * 4)

__device__ __forceinline__ void build_twiddles(float2* tw, int tid) {
    for (int k = tid; k < 2048; k += 512) {
        if (k == 0) { tw[0] = make_float2(1.0f, 0.0f); continue; }
        int hb = 31 - __clz(k);
        int half = 1 << hb;
        int j = k - half;
        float ang = -PI_F * (float)j / (float)half;
        float s, c;
        sincosf(ang, &s, &c);
        tw[k] = make_float2(c, s);
    }
}

__global__ void __launch_bounds__(512) fft_fwd_kernel(const float* __restrict__ xin,
                                                      float* __restrict__ dR,
                                                      float* __restrict__ dI) {
    extern __shared__ float sm[];
    float* sr = sm;
    float* si = sm + 2 * FSTR;
    float2* tw = (float2*)(sm + 4 * FSTR);
    int b = blockIdx.x >> 7;
    int c0 = (blockIdx.x & 127) * 2;
    size_t base = (size_t)b * LSEQ * DIMC + c0;
    int tid = threadIdx.x;

    build_twiddles(tw, tid);
    for (int n = tid; n < 2048; n += 512) {
        float2 v = *(const float2*)(xin + base + (size_t)n * DIMC);
        sr[0 * FSTR + n] = v.x; sr[1 * FSTR + n] = v.y;
        si[0 * FSTR + n] = 0.0f; si[1 * FSTR + n] = 0.0f;
    }
    __syncthreads();

    #pragma unroll
    for (int hb = 10; hb >= 0; hb--) {
        int half = 1 << hb;
        for (int e = tid; e < 2048; e += 512) {
            int col = e >> 10, idx = e & 1023;
            int j = idx & (half - 1);
            int pos = ((idx >> hb) << (hb + 1)) + j;
            float* cr = sr + col * FSTR;
            float* ci = si + col * FSTR;
            float ar = cr[pos],        ai = ci[pos];
            float br = cr[pos + half], bi = ci[pos + half];
            float2 w = tw[half + j];
            float xr = ar - br, xi = ai - bi;
            cr[pos] = ar + br;  ci[pos] = ai + bi;
            cr[pos + half] = xr * w.x - xi * w.y;
            ci[pos + half] = xr * w.y + xi * w.x;
        }
        __syncthreads();
    }

    for (int n = tid; n < 2048; n += 512) {
        float2 vr, vi;
        vr.x = sr[0 * FSTR + n]; vr.y = sr[1 * FSTR + n];
        vi.x = si[0 * FSTR + n]; vi.y = si[1 * FSTR + n];
        *(float2*)(dR + base + (size_t)n * DIMC) = vr;
        *(float2*)(dI + base + (size_t)n * DIMC) = vi;
    }
}

__global__ void __launch_bounds__(512) fft_inv_kernel(const float* __restrict__ dR,
                                                      const float* __restrict__ dI,
                                                      const float* __restrict__ x1,
                                                      float* __restrict__ out) {
    extern __shared__ float sm[];
    float* sr = sm;
    float* si = sm + 2 * FSTR;
    float2* tw = (float2*)(sm + 4 * FSTR);
    int b = blockIdx.x >> 7;
    int c0 = (blockIdx.x & 127) * 2;
    size_t base = (size_t)b * LSEQ * DIMC + c0;
    int tid = threadIdx.x;

    build_twiddles(tw, tid);
    for (int n = tid; n < 2048; n += 512) {
        float2 vr = *(const float2*)(dR + base + (size_t)n * DIMC);
        float2 vi = *(const float2*)(dI + base + (size_t)n * DIMC);
        sr[0 * FSTR + n] = vr.x; sr[1 * FSTR + n] = vr.y;
        si[0 * FSTR + n] = vi.x; si[1 * FSTR + n] = vi.y;
    }
    __syncthreads();

    #pragma unroll
    for (int hb = 0; hb <= 10; hb++) {
        int half = 1 << hb;
        for (int e = tid; e < 2048; e += 512) {
            int col = e >> 10, idx = e & 1023;
            int j = idx & (half - 1);
            int pos = ((idx >> hb) << (hb + 1)) + j;
            float* cr = sr + col * FSTR;
            float* ci = si + col * FSTR;
            float ar = cr[pos],        ai = ci[pos];
            float br = cr[pos + half], bi = ci[pos + half];
            float2 w = tw[half + j];      // conjugate for inverse
            float tr = br * w.x + bi * w.y;
            float ti = bi * w.x - br * w.y;
            cr[pos] = ar + tr;         ci[pos] = ai + ti;
            cr[pos + half] = ar - tr;  ci[pos + half] = ai - ti;
        }
        __syncthreads();
    }

    for (int n = tid; n < 2048; n += 512) {
        size_t a = base + (size_t)n * DIMC;
        float2 rx = *(const float2*)(x1 + a);
        float2 o;
        o.x = rx.x + sr[0 * FSTR + n];
        o.y = rx.y + sr[1 * FSTR + n];
        *(float2*)(out + a) = o;
    }
}

// ---------------------------------------------------------------------------
// EinFFT MLP with DFT4/IDFT4 over the NB axis folded in.
// ---------------------------------------------------------------------------
__global__ void __launch_bounds__(256) einfft_mlp_kernel(
        float* __restrict__ fR, float* __restrict__ fI,
        const float* __restrict__ cw1, const float* __restrict__ cb1,
        const float* __restrict__ cw2, const float* __restrict__ cb2) {
    __shared__ float sR[2048], sI[2048];
    __shared__ float tR[2048], tI[2048];
    int row0 = blockIdx.x * 8;
    int tid = threadIdx.x;
    for (int i = tid; i < 2048; i += 256) {
        sR[i] = fR[(size_t)row0 * DIMC + i];
        sI[i] = fI[(size_t)row0 * DIMC + i];
    }
    __syncthreads();

    const float sc = SQRT_INV_8192;
    #pragma unroll
    for (int g = tid; g < 512; g += 256) {
        int r = g >> 6, s = g & 63;
        int p = r * 256 + s;
        float r0 = sR[p],       i0 = sI[p];
        float r1 = sR[p + 64],  i1 = sI[p + 64];
        float r2 = sR[p + 128], i2 = sI[p + 128];
        float r3 = sR[p + 192], i3 = sI[p + 192];
        sR[p]       = (r0 + r1 + r2 + r3) * sc;
        sI[p]       = (i0 + i1 + i2 + i3) * sc;
        sR[p + 64]  = (r0 + i1 - r2 - i3) * sc;
        sI[p + 64]  = (i0 - r1 - i2 + r3) * sc;
        sR[p + 128] = (r0 - r1 + r2 - r3) * sc;
        sI[p + 128] = (i0 - i1 + i2 - i3) * sc;
        sR[p + 192] = (r0 - i1 - r2 + i3) * sc;
        sI[p + 192] = (i0 + r1 - i2 - r3) * sc;
    }
    __syncthreads();

    int k = tid >> 6, o = tid & 63;

    {
        const float* w0 = cw1 + k * 4096;
        const float* w1 = cw1 + 16384 + k * 4096;
        float bR = cb1[k * 64 + o];
        float bI = cb1[256 + k * 64 + o];
        float aR[8], aI[8];
        #pragma unroll
        for (int r = 0; r < 8; r++) { aR[r] = bR; aI[r] = bI; }
        for (int dd = 0; dd < 64; dd++) {
            float wa = w0[dd * 64 + o];
            float wb = w1[dd * 64 + o];
            int sb = k * 64 + dd;
            #pragma unroll
            for (int r = 0; r < 8; r++) {
                float xr = sR[r * 256 + sb];
                float xi = sI[r * 256 + sb];
                aR[r] = fmaf(xr, wa, fmaf(-xi, wb, aR[r]));
                aI[r] = fmaf(xr, wb, fmaf( xi, wa, aI[r]));
            }
        }
        #pragma unroll
        for (int r = 0; r < 8; r++) {
            tR[r * 256 + tid] = fmaxf(aR[r], 0.0f);
            tI[r * 256 + tid] = fmaxf(aI[r], 0.0f);
        }
    }
    __syncthreads();

    {
        const float* w0 = cw2 + k * 4096;
        const float* w1 = cw2 + 16384 + k * 4096;
        float bR = cb2[k * 64 + o];
        float bI = cb2[256 + k * 64 + o];
        float aR[8], aI[8];
        #pragma unroll
        for (int r = 0; r < 8; r++) { aR[r] = bR; aI[r] = bI; }
        for (int dd = 0; dd < 64; dd++) {
            float wa = w0[dd * 64 + o];
            float wb = w1[dd * 64 + o];
            int sb = k * 64 + dd;
            #pragma unroll
            for (int r = 0; r < 8; r++) {
                float xr = tR[r * 256 + sb];
                float xi = tI[r * 256 + sb];
                aR[r] = fmaf(xr, wa, fmaf(-xi, wb, aR[r]));
                aI[r] = fmaf(xr, wb, fmaf( xi, wa, aI[r]));
            }
        }
        #pragma unroll
        for (int r = 0; r < 8; r++) {
            float vR = aR[r], vI = aI[r];
            vR = (vR > LAMBDA_SS) ? vR - LAMBDA_SS
                 : ((vR < -LAMBDA_SS) ? vR + LAMBDA_SS : 0.0f);
            vI = (vI > LAMBDA_SS) ? vI - LAMBDA_SS
                 : ((vI < -LAMBDA_SS) ? vI + LAMBDA_SS : 0.0f);
            sR[r * 256 + tid] = vR;
            sI[r * 256 + tid] = vI;
        }
    }
    __syncthreads();

    #pragma unroll
    for (int g = tid; g < 512; g += 256) {
        int r = g >> 6, s = g & 63;
        int p = r * 256 + s;
        float R0 = sR[p],       I0 = sI[p];
        float R1 = sR[p + 64],  I1 = sI[p + 64];
        float R2 = sR[p + 128], I2 = sI[p + 128];
        float R3 = sR[p + 192], I3 = sI[p + 192];
        sR[p]       = (R0 + R1 + R2 + R3) * sc;
        sI[p]       = (I0 + I1 + I2 + I3) * sc;
        sR[p + 64]  = (R0 - I1 - R2 + I3) * sc;
        sI[p + 64]  = (I0 + R1 - I2 - R3) * sc;
        sR[p + 128] = (R0 - R1 + R2 - R3) * sc;
        sI[p + 128] = (I0 - I1 + I2 - I3) * sc;
        sR[p + 192] = (R0 + I1 - R2 - I3) * sc;
        sI[p + 192] = (I0 - R1 - I2 + R3) * sc;
    }
    __syncthreads();

    for (int i = tid; i < 2048; i += 256) {
        fR[(size_t)row0 * DIMC + i] = sR[i];
        fI[(size_t)row0 * DIMC + i] = sI[i];
    }
}

// ---------------------------------------------------------------------------
// Launch
// ---------------------------------------------------------------------------
extern "C" void kernel_launch(void* const* d_in, const int* in_sizes, int n_in,
                              void* d_out, int out_size) {
    const float* x         = (const float*)d_in[0];
    const float* norm1_w   = (const float*)d_in[1];
    const float* norm1_b   = (const float*)d_in[2];
    const float* in_proj_w = (const float*)d_in[3];
    const float* conv_w    = (const float*)d_in[4];
    const float* conv_b    = (const float*)d_in[5];
    const float* x_proj_w  = (const float*)d_in[6];
    const float* dt_proj_w = (const float*)d_in[7];
    const float* dt_proj_b = (const float*)d_in[8];
    const float* A_log     = (const float*)d_in[9];
    const float* Dvec      = (const float*)d_in[10];
    const float* out_proj_w= (const float*)d_in[11];
    const float* norm2_w   = (const float*)d_in[12];
    const float* norm2_b   = (const float*)d_in[13];
    const float* cw1       = (const float*)d_in[14];
    const float* cb1       = (const float*)d_in[15];
    const float* cw2       = (const float*)d_in[16];
    const float* cb2       = (const float*)d_in[17];
    float* out = (float*)d_out;

    void* sp = nullptr;
    cudaGetSymbolAddress(&sp, SCRATCH);
    float* S = (float*)sp;
    float* s_xn   = S + O_XN;
    float* s_xz   = S + O_XZ;
    float* s_xc   = S + O_XC;
    float* s_xdbl = S + O_XDBL;
    float* s_y    = S + O_Y;
    float* s_x1   = S + O_X1;
    float* s_xn2  = S + O_XN2;
    float* s_fr   = S + O_FR;
    float* s_fi   = S + O_FI;

    static int attr_done = 0;
    if (!attr_done) {
        cudaFuncSetAttribute(fft_fwd_kernel,
                             cudaFuncAttributeMaxDynamicSharedMemorySize, FFT_SMEM);
        cudaFuncSetAttribute(fft_inv_kernel,
                             cudaFuncAttributeMaxDynamicSharedMemorySize, FFT_SMEM);
        cudaFuncSetAttribute(gemm_tf32,
                             cudaFuncAttributeMaxDynamicSharedMemorySize, GEMM_SMEM);
        attr_done = 1;
    }

    // 1) LN1
    ln_kernel<<<NTOK / 8, 256>>>(x, norm1_w, norm1_b, s_xn);
    // 2) in_proj
    gemm_tf32<<<dim3((2 * DI) / GBN, NTOK / GBM), 256, GEMM_SMEM>>>(
        s_xn, in_proj_w, nullptr, s_xz, NTOK, 2 * DI, DIMC);
    // 3) conv + silu
    conv_silu_kernel<<<(NTOK * DI) / 256, 256>>>(s_xz, conv_w, conv_b, s_xc);
    // 4) x_proj
    gemm_tf32<<<dim3((XDBLW + GBN - 1) / GBN, NTOK / GBM), 256, GEMM_SMEM>>>(
        s_xc, x_proj_w, nullptr, s_xdbl, NTOK, XDBLW, DI);
    // 5) selective scan (fused dt + D-skip + silu(z) gate)
    scan_kernel<<<BATCH * (DI / 8), 256>>>(s_xdbl, s_xc, s_xz, A_log, Dvec,
                                           dt_proj_w, dt_proj_b, s_y);
    // 6) out_proj + residual
    gemm_tf32<<<dim3(DIMC / GBN, NTOK / GBM), 256, GEMM_SMEM>>>(
        s_y, out_proj_w, x, s_x1, NTOK, DIMC, DI);
    // 7) LN2
    ln_kernel<<<NTOK / 8, 256>>>(s_x1, norm2_w, norm2_b, s_xn2);
    // 8) forward FFT (2 ch/block, 256 blocks, twiddle table)
    fft_fwd_kernel<<<256, 512, FFT_SMEM>>>(s_xn2, s_fr, s_fi);
    // 9) fused EinFFT MLP (DFT4 + relu + softshrink + IDFT4)
    einfft_mlp_kernel<<<NTOK / 8, 256>>>(s_fr, s_fi, cw1, cb1, cw2, cb2);
    // 10) inverse FFT + residual -> out
    fft_inv_kernel<<<256, 512, FFT_SMEM>>>(s_fr, s_fi, s_x1, out);
}

// round 9
// speedup vs baseline: 1.0396x; 1.0396x over previous
#include <cuda_runtime.h>
#include <stdint.h>
#include <math.h>

// ---------------------------------------------------------------------------
// Problem constants
// ---------------------------------------------------------------------------
#define BATCH   2
#define LSEQ    2048
#define DIMC    256
#define DI      512          // d_inner
#define DS      64           // d_state
#define DTR     16           // dt_rank
#define XDBLW   144          // dt_rank + 2*d_state
#define NTOK    (BATCH*LSEQ) // 4096
#define SQRT_INV_8192 0.011048543456039806f
#define LAMBDA_SS 0.01f
#define PI_F 3.14159265358979323846f

// ---------------------------------------------------------------------------
// Scratch (single __device__ array; no allocations anywhere)
// ---------------------------------------------------------------------------
#define O_XN    ((size_t)0)
#define O_XZ    (O_XN   + (size_t)NTOK*DIMC)
#define O_XC    (O_XZ   + (size_t)NTOK*2*DI)
#define O_XDBL  (O_XC   + (size_t)NTOK*DI)
#define O_Y     (O_XDBL + (size_t)NTOK*XDBLW)
#define O_X1    (O_Y    + (size_t)NTOK*DI)
#define O_XN2   (O_X1   + (size_t)NTOK*DIMC)
#define O_FR    (O_XN2  + (size_t)NTOK*DIMC)
#define O_FI    (O_FR   + (size_t)NTOK*DIMC)
#define O_END   (O_FI   + (size_t)NTOK*DIMC)

__device__ float SCRATCH[O_END];

// ---------------------------------------------------------------------------
// cp.async helpers
// ---------------------------------------------------------------------------
__device__ __forceinline__ void cp16(unsigned dst, const void* src, int sz) {
    asm volatile("cp.async.cg.shared.global [%0], [%1], 16, %2;"
                 :: "r"(dst), "l"(src), "r"(sz));
}
__device__ __forceinline__ void cp_commit() {
    asm volatile("cp.async.commit_group;" ::: "memory");
}
template <int N>
__device__ __forceinline__ void cp_wait() {
    asm volatile("cp.async.wait_group %0;" :: "n"(N) : "memory");
}

// ---------------------------------------------------------------------------
// LayerNorm: one warp per token (256 channels), 8 tokens per 256-thread block
// ---------------------------------------------------------------------------
__global__ void ln_kernel(const float* __restrict__ x,
                          const float* __restrict__ w,
                          const float* __restrict__ b,
                          float* __restrict__ out) {
    int t = blockIdx.x * 8 + (threadIdx.x >> 5);
    int lane = threadIdx.x & 31;
    const float4* row = (const float4*)(x + (size_t)t * DIMC);
    float4 v0 = row[lane];
    float4 v1 = row[lane + 32];
    float s = v0.x + v0.y + v0.z + v0.w + v1.x + v1.y + v1.z + v1.w;
    #pragma unroll
    for (int off = 16; off; off >>= 1) s += __shfl_xor_sync(0xffffffffu, s, off);
    float m = s * (1.0f / 256.0f);
    float d0 = v0.x - m, d1 = v0.y - m, d2 = v0.z - m, d3 = v0.w - m;
    float d4 = v1.x - m, d5 = v1.y - m, d6 = v1.z - m, d7 = v1.w - m;
    float q = d0*d0 + d1*d1 + d2*d2 + d3*d3 + d4*d4 + d5*d5 + d6*d6 + d7*d7;
    #pragma unroll
    for (int off = 16; off; off >>= 1) q += __shfl_xor_sync(0xffffffffu, q, off);
    float inv = rsqrtf(q * (1.0f / 256.0f) + 1e-5f);
    const float4* w4 = (const float4*)w;
    const float4* b4 = (const float4*)b;
    float4* o4 = (float4*)(out + (size_t)t * DIMC);
    float4 wa = w4[lane], ba = b4[lane];
    float4 wb = w4[lane + 32], bb = b4[lane + 32];
    float4 r0, r1;
    r0.x = d0*inv*wa.x + ba.x; r0.y = d1*inv*wa.y + ba.y;
    r0.z = d2*inv*wa.z + ba.z; r0.w = d3*inv*wa.w + ba.w;
    r1.x = d4*inv*wb.x + bb.x; r1.y = d5*inv*wb.y + bb.y;
    r1.z = d6*inv*wb.z + bb.z; r1.w = d7*inv*wb.w + bb.w;
    o4[lane] = r0; o4[lane + 32] = r1;
}

// ---------------------------------------------------------------------------
// tf32 tensor-core GEMM: C[M,N] = A[M,K] * W[N,K]^T (+ R[M,N]).
// 64x64 block tile, BK=16, 256 threads = 8 warps (4m x 2n), warp tile 16x32
// via 1x4 mma.sync.m16n8k8.tf32.  4-stage cp.async pipeline (41KB smem ->
// 2-3 blocks/SM), raw fp32 bits to HMMA.  M%64==0, K%16==0 guaranteed.
// ---------------------------------------------------------------------------
#define GBM 64
#define GBN 64
#define ASTR 20
#define GSTAGES 4
#define GEMM_SMEM (GSTAGES * (GBM + GBN) * ASTR * 4)

__device__ __forceinline__ void mma_tf32(float* c, const unsigned* a, const unsigned* b) {
    asm volatile(
        "mma.sync.aligned.m16n8k8.row.col.f32.tf32.tf32.f32 "
        "{%0,%1,%2,%3}, {%4,%5,%6,%7}, {%8,%9}, {%0,%1,%2,%3};"
        : "+f"(c[0]), "+f"(c[1]), "+f"(c[2]), "+f"(c[3])
        : "r"(a[0]), "r"(a[1]), "r"(a[2]), "r"(a[3]), "r"(b[0]), "r"(b[1]));
}

__global__ void __launch_bounds__(256) gemm_tf32(const float* __restrict__ A,
                                                 const float* __restrict__ W,
                                                 const float* __restrict__ R,
                                                 float* __restrict__ C,
                                                 int M, int N, int K) {
    extern __shared__ float gsm[];
    float* As = gsm;                                // GSTAGES * GBM * ASTR
    float* Bs = gsm + GSTAGES * GBM * ASTR;         // GSTAGES * GBN * ASTR
    unsigned smA = (unsigned)__cvta_generic_to_shared(As);
    unsigned smB = (unsigned)__cvta_generic_to_shared(Bs);

    int m0 = blockIdx.y * GBM;
    int n0 = blockIdx.x * GBN;
    int tid = threadIdx.x;
    int wid = tid >> 5, lane = tid & 31;
    int wm = (wid & 3) * 16;       // 4 m-warps x 16 rows
    int wn = (wid >> 2) * 32;      // 2 n-warps x 32 cols
    int gid = lane >> 2;           // 0..7
    int tig = lane & 3;            // 0..3
    int ar = tid >> 2, ak = (tid & 3) * 4;   // one cp16 per thread per tile

    const float* Abase = A + (size_t)(m0 + ar) * K + ak;
    bool bok = (n0 + ar) < N;
    const float* Bbase = bok ? (W + (size_t)(n0 + ar) * K + ak) : W;
    int bsz = bok ? 16 : 0;
    unsigned adst = smA + (unsigned)(ar * ASTR + ak) * 4u;
    unsigned bdst = smB + (unsigned)(ar * ASTR + ak) * 4u;
    const unsigned aStage = GBM * ASTR * 4u;
    const unsigned bStage = GBN * ASTR * 4u;

    float acc[4][4];
    #pragma unroll
    for (int ni = 0; ni < 4; ni++)
        #pragma unroll
        for (int q = 0; q < 4; q++) acc[ni][q] = 0.0f;

    int nIt = K >> 4;
    // prologue: stages 0..GSTAGES-2
    #pragma unroll
    for (int s = 0; s < GSTAGES - 1; s++) {
        cp16(adst + s * aStage, Abase + s * 16, 16);
        cp16(bdst + s * bStage, Bbase + (bok ? s * 16 : 0), bsz);
        cp_commit();
    }

    for (int it = 0; it < nIt; it++) {
        cp_wait<GSTAGES - 2>();
        __syncthreads();
        int buf = it & (GSTAGES - 1);
        const float* Ab = As + buf * (GBM * ASTR);
        const float* Bb = Bs + buf * (GBN * ASTR);
        #pragma unroll
        for (int ks = 0; ks < 2; ks++) {
            int k8 = ks * 8;
            unsigned afr[4], bfr[4][2];
            {
                int rb = wm + gid;
                afr[0] = __float_as_uint(Ab[(rb)     * ASTR + k8 + tig]);
                afr[1] = __float_as_uint(Ab[(rb + 8) * ASTR + k8 + tig]);
                afr[2] = __float_as_uint(Ab[(rb)     * ASTR + k8 + tig + 4]);
                afr[3] = __float_as_uint(Ab[(rb + 8) * ASTR + k8 + tig + 4]);
            }
            #pragma unroll
            for (int ni = 0; ni < 4; ni++) {
                int cb = wn + ni * 8 + gid;
                bfr[ni][0] = __float_as_uint(Bb[cb * ASTR + k8 + tig]);
                bfr[ni][1] = __float_as_uint(Bb[cb * ASTR + k8 + tig + 4]);
            }
            #pragma unroll
            for (int ni = 0; ni < 4; ni++)
                mma_tf32(acc[ni], afr, bfr[ni]);
        }
        int nx = it + GSTAGES - 1;
        if (nx < nIt) {
            int slot = nx & (GSTAGES - 1);
            cp16(adst + slot * aStage, Abase + nx * 16, 16);
            cp16(bdst + slot * bStage, Bbase + (bok ? nx * 16 : 0), bsz);
        }
        cp_commit();
    }

    int row = m0 + wm + gid;
    #pragma unroll
    for (int ni = 0; ni < 4; ni++) {
        int col = n0 + wn + ni * 8 + tig * 2;
        if (col < N) {
            float v0 = acc[ni][0];
            float v2 = acc[ni][2];
            if (R) { v0 += R[(size_t)row * N + col]; v2 += R[(size_t)(row + 8) * N + col]; }
            C[(size_t)row * N + col] = v0;
            C[(size_t)(row + 8) * N + col] = v2;
        }
        if (col + 1 < N) {
            float v1 = acc[ni][1];
            float v3 = acc[ni][3];
            if (R) { v1 += R[(size_t)row * N + col + 1]; v3 += R[(size_t)(row + 8) * N + col + 1]; }
            C[(size_t)row * N + col + 1] = v1;
            C[(size_t)(row + 8) * N + col + 1] = v3;
        }
    }
}

// ---------------------------------------------------------------------------
// Depthwise causal conv (k=4) + bias + SiLU.  xz[:, 0:512] -> xc
// ---------------------------------------------------------------------------
__global__ void conv_silu_kernel(const float* __restrict__ xz,
                                 const float* __restrict__ cw,
                                 const float* __restrict__ cb,
                                 float* __restrict__ xc) {
    int idx = blockIdx.x * 256 + threadIdx.x;   // NTOK*DI
    int d = idx & (DI - 1);
    int bt = idx >> 9;
    int b = bt >> 11;
    int l = bt & (LSEQ - 1);
    float acc = cb[d];
    #pragma unroll
    for (int k = 0; k < 4; k++) {
        int ls = l + k - 3;
        if (ls >= 0)
            acc += xz[((size_t)((b << 11) | ls)) * (2 * DI) + d] * cw[d * 4 + k];
    }
    float sg = 1.0f / (1.0f + __expf(-acc));
    xc[(size_t)bt * DI + d] = acc * sg;
}

// ---------------------------------------------------------------------------
// Selective scan with fused dt; deferred reduce-scatter for y.
// ---------------------------------------------------------------------------
#define TCHUNK 64
__global__ void __launch_bounds__(256) scan_kernel(
        const float* __restrict__ xdbl,
        const float* __restrict__ xc,
        const float* __restrict__ xz,
        const float* __restrict__ A_log,
        const float* __restrict__ Dvec,
        const float* __restrict__ dtw,
        const float* __restrict__ dtb,
        float* __restrict__ y) {
    __shared__ float sB[TCHUNK][64];
    __shared__ float sC[TCHUNK][64];
    __shared__ float sx16[TCHUNK][16];
    __shared__ float2 sdx[TCHUNK][8];   // (dt, xc)
    __shared__ float sz[TCHUNK][8];
    __shared__ float sy[TCHUNK][8];
    __shared__ float sw[8][16];
    __shared__ float sbias[8];

    int b = blockIdx.x >> 6;
    int dbase = (blockIdx.x & 63) * 8;
    int wid = threadIdx.x >> 5;
    int lane = threadIdx.x & 31;
    int d = dbase + wid;

    if (threadIdx.x < 128) {
        int di = threadIdx.x >> 4, r = threadIdx.x & 15;
        sw[di][r] = dtw[(dbase + di) * DTR + r];
        if (r == 0) sbias[di] = dtb[dbase + di];
    }
    float A0 = -__expf(A_log[d * DS + lane]);
    float A1 = -__expf(A_log[d * DS + lane + 32]);
    float Dd = Dvec[d];
    float h0 = 0.0f, h1 = 0.0f;

    for (int t0 = 0; t0 < LSEQ; t0 += TCHUNK) {
        for (int i = threadIdx.x; i < TCHUNK * 128; i += 256) {
            int tt = i >> 7;
            int c = i & 127;
            float v = xdbl[(size_t)(b * LSEQ + t0 + tt) * XDBLW + DTR + c];
            if (c < 64) sB[tt][c] = v; else sC[tt][c - 64] = v;
        }
        for (int i = threadIdx.x; i < TCHUNK * 16; i += 256) {
            int tt = i >> 4, r = i & 15;
            sx16[tt][r] = xdbl[(size_t)(b * LSEQ + t0 + tt) * XDBLW + r];
        }
        for (int i = threadIdx.x; i < TCHUNK * 8; i += 256) {
            int tt = i >> 3, di = i & 7;
            size_t bt = (size_t)(b * LSEQ + t0 + tt);
            sdx[tt][di].y = xc[bt * DI + dbase + di];
            sz[tt][di]    = xz[bt * (2 * DI) + DI + dbase + di];
        }
        __syncthreads();
        for (int i = threadIdx.x; i < TCHUNK * 8; i += 256) {
            int tt = i >> 3, di = i & 7;
            float acc = sbias[di];
            #pragma unroll
            for (int r = 0; r < 16; r++) acc = fmaf(sx16[tt][r], sw[di][r], acc);
            sdx[tt][di].x = (acc > 20.0f) ? acc : __logf(1.0f + __expf(acc));
        }
        __syncthreads();

        #pragma unroll 1
        for (int g = 0; g < TCHUNK / 32; g++) {
            float part[32];
            #pragma unroll
            for (int j = 0; j < 32; j++) {
                int tt = g * 32 + j;
                float2 dx = sdx[tt][wid];
                float du = dx.x * dx.y;
                float dA0 = __expf(dx.x * A0);
                float dA1 = __expf(dx.x * A1);
                h0 = fmaf(dA0, h0, du * sB[tt][lane]);
                h1 = fmaf(dA1, h1, du * sB[tt][lane + 32]);
                part[j] = fmaf(h0, sC[tt][lane], h1 * sC[tt][lane + 32]);
            }
            #pragma unroll
            for (int s = 16; s >= 1; s >>= 1) {
                bool up = (lane & s) != 0;
                #pragma unroll
                for (int i2 = 0; i2 < 16; i2++) {
                    if (i2 >= s) break;
                    float keep = up ? part[i2 + s] : part[i2];
                    float send = up ? part[i2] : part[i2 + s];
                    part[i2] = keep + __shfl_xor_sync(0xffffffffu, send, s);
                }
            }
            int tt = g * 32 + lane;
            float2 dx = sdx[tt][wid];
            float zv = sz[tt][wid];
            float gate = zv / (1.0f + __expf(-zv));
            sy[tt][wid] = fmaf(dx.y, Dd, part[0]) * gate;
        }
        __syncthreads();
        for (int i = threadIdx.x; i < TCHUNK * 8; i += 256) {
            int tt = i >> 3, di = i & 7;
            y[(size_t)(b * LSEQ + t0 + tt) * DI + dbase + di] = sy[tt][di];
        }
        __syncthreads();
    }
}

// ---------------------------------------------------------------------------
// Forward 2048-pt FFT (DIF, natural -> bit-reversed), real input.
// 4 channels per block (128 blocks), float4 global I/O, padded stride 2049.
// ---------------------------------------------------------------------------
#define FSTR 2049
#define FFT_SMEM (2 * 4 * FSTR * 4)

__global__ void __launch_bounds__(512) fft_fwd_kernel(const float* __restrict__ xin,
                                                      float* __restrict__ dR,
                                                      float* __restrict__ dI) {
    extern __shared__ float sm[];
    float* sr = sm;
    float* si = sm + 4 * FSTR;
    int b = blockIdx.x >> 6;
    int c0 = (blockIdx.x & 63) * 4;
    size_t base = (size_t)b * LSEQ * DIMC + c0;
    int tid = threadIdx.x;

    for (int n = tid; n < 2048; n += 512) {
        float4 v = *(const float4*)(xin + base + (size_t)n * DIMC);
        sr[0 * FSTR + n] = v.x; sr[1 * FSTR + n] = v.y;
        sr[2 * FSTR + n] = v.z; sr[3 * FSTR + n] = v.w;
        si[0 * FSTR + n] = 0.0f; si[1 * FSTR + n] = 0.0f;
        si[2 * FSTR + n] = 0.0f; si[3 * FSTR + n] = 0.0f;
    }
    __syncthreads();

    #pragma unroll
    for (int hb = 10; hb >= 0; hb--) {
        int half = 1 << hb;
        float th = -PI_F / (float)half;
        for (int e = tid; e < 4096; e += 512) {
            int col = e >> 10, idx = e & 1023;
            int j = idx & (half - 1);
            int pos = ((idx >> hb) << (hb + 1)) + j;
            float* cr = sr + col * FSTR;
            float* ci = si + col * FSTR;
            float ar = cr[pos],        ai = ci[pos];
            float br = cr[pos + half], bi = ci[pos + half];
            float wi, wr;
            __sincosf(th * (float)j, &wi, &wr);
            float xr = ar - br, xi = ai - bi;
            cr[pos] = ar + br;  ci[pos] = ai + bi;
            cr[pos + half] = xr * wr - xi * wi;
            ci[pos + half] = xr * wi + xi * wr;
        }
        __syncthreads();
    }

    for (int n = tid; n < 2048; n += 512) {
        float4 vr, vi;
        vr.x = sr[0 * FSTR + n]; vr.y = sr[1 * FSTR + n];
        vr.z = sr[2 * FSTR + n]; vr.w = sr[3 * FSTR + n];
        vi.x = si[0 * FSTR + n]; vi.y = si[1 * FSTR + n];
        vi.z = si[2 * FSTR + n]; vi.w = si[3 * FSTR + n];
        *(float4*)(dR + base + (size_t)n * DIMC) = vr;
        *(float4*)(dI + base + (size_t)n * DIMC) = vi;
    }
}

// ---------------------------------------------------------------------------
// Inverse 2048-pt FFT (DIT, bit-reversed -> natural); real part + residual.
// ---------------------------------------------------------------------------
__global__ void __launch_bounds__(512) fft_inv_kernel(const float* __restrict__ dR,
                                                      const float* __restrict__ dI,
                                                      const float* __restrict__ x1,
                                                      float* __restrict__ out) {
    extern __shared__ float sm[];
    float* sr = sm;
    float* si = sm + 4 * FSTR;
    int b = blockIdx.x >> 6;
    int c0 = (blockIdx.x & 63) * 4;
    size_t base = (size_t)b * LSEQ * DIMC + c0;
    int tid = threadIdx.x;

    for (int n = tid; n < 2048; n += 512) {
        float4 vr = *(const float4*)(dR + base + (size_t)n * DIMC);
        float4 vi = *(const float4*)(dI + base + (size_t)n * DIMC);
        sr[0 * FSTR + n] = vr.x; sr[1 * FSTR + n] = vr.y;
        sr[2 * FSTR + n] = vr.z; sr[3 * FSTR + n] = vr.w;
        si[0 * FSTR + n] = vi.x; si[1 * FSTR + n] = vi.y;
        si[2 * FSTR + n] = vi.z; si[3 * FSTR + n] = vi.w;
    }
    __syncthreads();

    #pragma unroll
    for (int hb = 0; hb <= 10; hb++) {
        int half = 1 << hb;
        float th = PI_F / (float)half;
        for (int e = tid; e < 4096; e += 512) {
            int col = e >> 10, idx = e & 1023;
            int j = idx & (half - 1);
            int pos = ((idx >> hb) << (hb + 1)) + j;
            float* cr = sr + col * FSTR;
            float* ci = si + col * FSTR;
            float ar = cr[pos],        ai = ci[pos];
            float br = cr[pos + half], bi = ci[pos + half];
            float wi, wr;
            __sincosf(th * (float)j, &wi, &wr);
            float tr = br * wr - bi * wi;
            float ti = br * wi + bi * wr;
            cr[pos] = ar + tr;         ci[pos] = ai + ti;
            cr[pos + half] = ar - tr;  ci[pos + half] = ai - ti;
        }
        __syncthreads();
    }

    for (int n = tid; n < 2048; n += 512) {
        size_t a = base + (size_t)n * DIMC;
        float4 rx = *(const float4*)(x1 + a);
        float4 o;
        o.x = rx.x + sr[0 * FSTR + n];
        o.y = rx.y + sr[1 * FSTR + n];
        o.z = rx.z + sr[2 * FSTR + n];
        o.w = rx.w + sr[3 * FSTR + n];
        *(float4*)(out + a) = o;
    }
}

// ---------------------------------------------------------------------------
// EinFFT MLP with DFT4/IDFT4 over the NB axis folded in.
// ---------------------------------------------------------------------------
__global__ void __launch_bounds__(256) einfft_mlp_kernel(
        float* __restrict__ fR, float* __restrict__ fI,
        const float* __restrict__ cw1, const float* __restrict__ cb1,
        const float* __restrict__ cw2, const float* __restrict__ cb2) {
    __shared__ float sR[2048], sI[2048];
    __shared__ float tR[2048], tI[2048];
    int row0 = blockIdx.x * 8;
    int tid = threadIdx.x;
    for (int i = tid; i < 2048; i += 256) {
        sR[i] = fR[(size_t)row0 * DIMC + i];
        sI[i] = fI[(size_t)row0 * DIMC + i];
    }
    __syncthreads();

    const float sc = SQRT_INV_8192;
    #pragma unroll
    for (int g = tid; g < 512; g += 256) {
        int r = g >> 6, s = g & 63;
        int p = r * 256 + s;
        float r0 = sR[p],       i0 = sI[p];
        float r1 = sR[p + 64],  i1 = sI[p + 64];
        float r2 = sR[p + 128], i2 = sI[p + 128];
        float r3 = sR[p + 192], i3 = sI[p + 192];
        sR[p]       = (r0 + r1 + r2 + r3) * sc;
        sI[p]       = (i0 + i1 + i2 + i3) * sc;
        sR[p + 64]  = (r0 + i1 - r2 - i3) * sc;
        sI[p + 64]  = (i0 - r1 - i2 + r3) * sc;
        sR[p + 128] = (r0 - r1 + r2 - r3) * sc;
        sI[p + 128] = (i0 - i1 + i2 - i3) * sc;
        sR[p + 192] = (r0 - i1 - r2 + i3) * sc;
        sI[p + 192] = (i0 + r1 - i2 - r3) * sc;
    }
    __syncthreads();

    int k = tid >> 6, o = tid & 63;

    {
        const float* w0 = cw1 + k * 4096;
        const float* w1 = cw1 + 16384 + k * 4096;
        float bR = cb1[k * 64 + o];
        float bI = cb1[256 + k * 64 + o];
        float aR[8], aI[8];
        #pragma unroll
        for (int r = 0; r < 8; r++) { aR[r] = bR; aI[r] = bI; }
        for (int dd = 0; dd < 64; dd++) {
            float wa = w0[dd * 64 + o];
            float wb = w1[dd * 64 + o];
            int sb = k * 64 + dd;
            #pragma unroll
            for (int r = 0; r < 8; r++) {
                float xr = sR[r * 256 + sb];
                float xi = sI[r * 256 + sb];
                aR[r] = fmaf(xr, wa, fmaf(-xi, wb, aR[r]));
                aI[r] = fmaf(xr, wb, fmaf( xi, wa, aI[r]));
            }
        }
        #pragma unroll
        for (int r = 0; r < 8; r++) {
            tR[r * 256 + tid] = fmaxf(aR[r], 0.0f);
            tI[r * 256 + tid] = fmaxf(aI[r], 0.0f);
        }
    }
    __syncthreads();

    {
        const float* w0 = cw2 + k * 4096;
        const float* w1 = cw2 + 16384 + k * 4096;
        float bR = cb2[k * 64 + o];
        float bI = cb2[256 + k * 64 + o];
        float aR[8], aI[8];
        #pragma unroll
        for (int r = 0; r < 8; r++) { aR[r] = bR; aI[r] = bI; }
        for (int dd = 0; dd < 64; dd++) {
            float wa = w0[dd * 64 + o];
            float wb = w1[dd * 64 + o];
            int sb = k * 64 + dd;
            #pragma unroll
            for (int r = 0; r < 8; r++) {
                float xr = tR[r * 256 + sb];
                float xi = tI[r * 256 + sb];
                aR[r] = fmaf(xr, wa, fmaf(-xi, wb, aR[r]));
                aI[r] = fmaf(xr, wb, fmaf( xi, wa, aI[r]));
            }
        }
        #pragma unroll
        for (int r = 0; r < 8; r++) {
            float vR = aR[r], vI = aI[r];
            vR = (vR > LAMBDA_SS) ? vR - LAMBDA_SS
                 : ((vR < -LAMBDA_SS) ? vR + LAMBDA_SS : 0.0f);
            vI = (vI > LAMBDA_SS) ? vI - LAMBDA_SS
                 : ((vI < -LAMBDA_SS) ? vI + LAMBDA_SS : 0.0f);
            sR[r * 256 + tid] = vR;
            sI[r * 256 + tid] = vI;
        }
    }
    __syncthreads();

    #pragma unroll
    for (int g = tid; g < 512; g += 256) {
        int r = g >> 6, s = g & 63;
        int p = r * 256 + s;
        float R0 = sR[p],       I0 = sI[p];
        float R1 = sR[p + 64],  I1 = sI[p + 64];
        float R2 = sR[p + 128], I2 = sI[p + 128];
        float R3 = sR[p + 192], I3 = sI[p + 192];
        sR[p]       = (R0 + R1 + R2 + R3) * sc;
        sI[p]       = (I0 + I1 + I2 + I3) * sc;
        sR[p + 64]  = (R0 - I1 - R2 + I3) * sc;
        sI[p + 64]  = (I0 + R1 - I2 - R3) * sc;
        sR[p + 128] = (R0 - R1 + R2 - R3) * sc;
        sI[p + 128] = (I0 - I1 + I2 - I3) * sc;
        sR[p + 192] = (R0 + I1 - R2 - I3) * sc;
        sI[p + 192] = (I0 - R1 - I2 + R3) * sc;
    }
    __syncthreads();

    for (int i = tid; i < 2048; i += 256) {
        fR[(size_t)row0 * DIMC + i] = sR[i];
        fI[(size_t)row0 * DIMC + i] = sI[i];
    }
}

// ---------------------------------------------------------------------------
// Launch
// ---------------------------------------------------------------------------
extern "C" void kernel_launch(void* const* d_in, const int* in_sizes, int n_in,
                              void* d_out, int out_size) {
    const float* x         = (const float*)d_in[0];
    const float* norm1_w   = (const float*)d_in[1];
    const float* norm1_b   = (const float*)d_in[2];
    const float* in_proj_w = (const float*)d_in[3];
    const float* conv_w    = (const float*)d_in[4];
    const float* conv_b    = (const float*)d_in[5];
    const float* x_proj_w  = (const float*)d_in[6];
    const float* dt_proj_w = (const float*)d_in[7];
    const float* dt_proj_b = (const float*)d_in[8];
    const float* A_log     = (const float*)d_in[9];
    const float* Dvec      = (const float*)d_in[10];
    const float* out_proj_w= (const float*)d_in[11];
    const float* norm2_w   = (const float*)d_in[12];
    const float* norm2_b   = (const float*)d_in[13];
    const float* cw1       = (const float*)d_in[14];
    const float* cb1       = (const float*)d_in[15];
    const float* cw2       = (const float*)d_in[16];
    const float* cb2       = (const float*)d_in[17];
    float* out = (float*)d_out;

    void* sp = nullptr;
    cudaGetSymbolAddress(&sp, SCRATCH);
    float* S = (float*)sp;
    float* s_xn   = S + O_XN;
    float* s_xz   = S + O_XZ;
    float* s_xc   = S + O_XC;
    float* s_xdbl = S + O_XDBL;
    float* s_y    = S + O_Y;
    float* s_x1   = S + O_X1;
    float* s_xn2  = S + O_XN2;
    float* s_fr   = S + O_FR;
    float* s_fi   = S + O_FI;

    static int attr_done = 0;
    if (!attr_done) {
        cudaFuncSetAttribute(fft_fwd_kernel,
                             cudaFuncAttributeMaxDynamicSharedMemorySize, FFT_SMEM);
        cudaFuncSetAttribute(fft_inv_kernel,
                             cudaFuncAttributeMaxDynamicSharedMemorySize, FFT_SMEM);
        cudaFuncSetAttribute(gemm_tf32,
                             cudaFuncAttributeMaxDynamicSharedMemorySize, GEMM_SMEM);
        attr_done = 1;
    }

    // 1) LN1
    ln_kernel<<<NTOK / 8, 256>>>(x, norm1_w, norm1_b, s_xn);
    // 2) in_proj
    gemm_tf32<<<dim3((2 * DI) / GBN, NTOK / GBM), 256, GEMM_SMEM>>>(
        s_xn, in_proj_w, nullptr, s_xz, NTOK, 2 * DI, DIMC);
    // 3) conv + silu
    conv_silu_kernel<<<(NTOK * DI) / 256, 256>>>(s_xz, conv_w, conv_b, s_xc);
    // 4) x_proj
    gemm_tf32<<<dim3((XDBLW + GBN - 1) / GBN, NTOK / GBM), 256, GEMM_SMEM>>>(
        s_xc, x_proj_w, nullptr, s_xdbl, NTOK, XDBLW, DI);
    // 5) selective scan (fused dt + D-skip + silu(z) gate)
    scan_kernel<<<BATCH * (DI / 8), 256>>>(s_xdbl, s_xc, s_xz, A_log, Dvec,
                                           dt_proj_w, dt_proj_b, s_y);
    // 6) out_proj + residual
    gemm_tf32<<<dim3(DIMC / GBN, NTOK / GBM), 256, GEMM_SMEM>>>(
        s_y, out_proj_w, x, s_x1, NTOK, DIMC, DI);
    // 7) LN2
    ln_kernel<<<NTOK / 8, 256>>>(s_x1, norm2_w, norm2_b, s_xn2);
    // 8) forward FFT (4 ch/block, 128 blocks)
    fft_fwd_kernel<<<128, 512, FFT_SMEM>>>(s_xn2, s_fr, s_fi);
    // 9) fused EinFFT MLP (DFT4 + relu + softshrink + IDFT4)
    einfft_mlp_kernel<<<NTOK / 8, 256>>>(s_fr, s_fi, cw1, cb1, cw2, cb2);
    // 10) inverse FFT + residual -> out
    fft_inv_kernel<<<128, 512, FFT_SMEM>>>(s_fr, s_fi, s_x1, out);
}

// round 10
// speedup vs baseline: 1.0498x; 1.0099x over previous
#include <cuda_runtime.h>
#include <stdint.h>
#include <math.h>

// ---------------------------------------------------------------------------
// Problem constants
// ---------------------------------------------------------------------------
#define BATCH   2
#define LSEQ    2048
#define DIMC    256
#define DI      512          // d_inner
#define DS      64           // d_state
#define DTR     16           // dt_rank
#define XDBLW   144          // dt_rank + 2*d_state
#define NTOK    (BATCH*LSEQ) // 4096
#define SQRT_INV_8192 0.011048543456039806f
#define LAMBDA_SS 0.01f
#define PI_F 3.14159265358979323846f

// ---------------------------------------------------------------------------
// Scratch (single __device__ array; no allocations anywhere)
// ---------------------------------------------------------------------------
#define O_XN    ((size_t)0)
#define O_XZ    (O_XN   + (size_t)NTOK*DIMC)
#define O_XC    (O_XZ   + (size_t)NTOK*2*DI)
#define O_XDBL  (O_XC   + (size_t)NTOK*DI)
#define O_Y     (O_XDBL + (size_t)NTOK*XDBLW)
#define O_X1    (O_Y    + (size_t)NTOK*DI)
#define O_XN2   (O_X1   + (size_t)NTOK*DIMC)
#define O_FR    (O_XN2  + (size_t)NTOK*DIMC)
#define O_FI    (O_FR   + (size_t)NTOK*DIMC)
#define O_END   (O_FI   + (size_t)NTOK*DIMC)

__device__ float SCRATCH[O_END];

// ---------------------------------------------------------------------------
// cp.async helpers
// ---------------------------------------------------------------------------
__device__ __forceinline__ void cp16(unsigned dst, const void* src, int sz) {
    asm volatile("cp.async.cg.shared.global [%0], [%1], 16, %2;"
                 :: "r"(dst), "l"(src), "r"(sz));
}
__device__ __forceinline__ void cp_commit() {
    asm volatile("cp.async.commit_group;" ::: "memory");
}
template <int N>
__device__ __forceinline__ void cp_wait() {
    asm volatile("cp.async.wait_group %0;" :: "n"(N) : "memory");
}

// ---------------------------------------------------------------------------
// LayerNorm: one warp per token (256 channels), 8 tokens per 256-thread block
// ---------------------------------------------------------------------------
__global__ void ln_kernel(const float* __restrict__ x,
                          const float* __restrict__ w,
                          const float* __restrict__ b,
                          float* __restrict__ out) {
    int t = blockIdx.x * 8 + (threadIdx.x >> 5);
    int lane = threadIdx.x & 31;
    const float4* row = (const float4*)(x + (size_t)t * DIMC);
    float4 v0 = row[lane];
    float4 v1 = row[lane + 32];
    float s = v0.x + v0.y + v0.z + v0.w + v1.x + v1.y + v1.z + v1.w;
    #pragma unroll
    for (int off = 16; off; off >>= 1) s += __shfl_xor_sync(0xffffffffu, s, off);
    float m = s * (1.0f / 256.0f);
    float d0 = v0.x - m, d1 = v0.y - m, d2 = v0.z - m, d3 = v0.w - m;
    float d4 = v1.x - m, d5 = v1.y - m, d6 = v1.z - m, d7 = v1.w - m;
    float q = d0*d0 + d1*d1 + d2*d2 + d3*d3 + d4*d4 + d5*d5 + d6*d6 + d7*d7;
    #pragma unroll
    for (int off = 16; off; off >>= 1) q += __shfl_xor_sync(0xffffffffu, q, off);
    float inv = rsqrtf(q * (1.0f / 256.0f) + 1e-5f);
    const float4* w4 = (const float4*)w;
    const float4* b4 = (const float4*)b;
    float4* o4 = (float4*)(out + (size_t)t * DIMC);
    float4 wa = w4[lane], ba = b4[lane];
    float4 wb = w4[lane + 32], bb = b4[lane + 32];
    float4 r0, r1;
    r0.x = d0*inv*wa.x + ba.x; r0.y = d1*inv*wa.y + ba.y;
    r0.z = d2*inv*wa.z + ba.z; r0.w = d3*inv*wa.w + ba.w;
    r1.x = d4*inv*wb.x + bb.x; r1.y = d5*inv*wb.y + bb.y;
    r1.z = d6*inv*wb.z + bb.z; r1.w = d7*inv*wb.w + bb.w;
    o4[lane] = r0; o4[lane + 32] = r1;
}

// ---------------------------------------------------------------------------
// tf32 tensor-core GEMM: C[M,N] = A[M,K] * W[N,K]^T (+ R[M,N]).
// 128x64 block tile, BK=16, 256 threads = 8 warps (4m x 2n), warp tile 32x32
// via 2x4 mma.sync.m16n8k8.tf32.  4-stage cp.async pipeline; raw fp32 bits
// fed to HMMA.  (R6 config - best measured.)
// ---------------------------------------------------------------------------
#define GBM 128
#define GBN 64
#define ASTR 20
#define GSTAGES 4
#define GEMM_SMEM (GSTAGES * (GBM + GBN) * ASTR * 4)

__device__ __forceinline__ void mma_tf32(float* c, const unsigned* a, const unsigned* b) {
    asm volatile(
        "mma.sync.aligned.m16n8k8.row.col.f32.tf32.tf32.f32 "
        "{%0,%1,%2,%3}, {%4,%5,%6,%7}, {%8,%9}, {%0,%1,%2,%3};"
        : "+f"(c[0]), "+f"(c[1]), "+f"(c[2]), "+f"(c[3])
        : "r"(a[0]), "r"(a[1]), "r"(a[2]), "r"(a[3]), "r"(b[0]), "r"(b[1]));
}

__global__ void __launch_bounds__(256) gemm_tf32(const float* __restrict__ A,
                                                 const float* __restrict__ W,
                                                 const float* __restrict__ R,
                                                 float* __restrict__ C,
                                                 int M, int N, int K) {
    extern __shared__ float gsm[];
    float* As = gsm;
    float* Bs = gsm + GSTAGES * GBM * ASTR;
    unsigned smA = (unsigned)__cvta_generic_to_shared(As);
    unsigned smB = (unsigned)__cvta_generic_to_shared(Bs);

    int m0 = blockIdx.y * GBM;
    int n0 = blockIdx.x * GBN;
    int tid = threadIdx.x;
    int wid = tid >> 5, lane = tid & 31;
    int wm = (wid & 3) * 32;
    int wn = (wid >> 2) * 32;
    int gid = lane >> 2;
    int tig = lane & 3;
    int ar = tid >> 1, ak = (tid & 1) * 8;
    int br = tid >> 2, bk = (tid & 3) * 4;

    const float* Abase = A + (size_t)(m0 + ar) * K + ak;
    bool bok = (n0 + br) < N;
    const float* Bbase = bok ? (W + (size_t)(n0 + br) * K + bk) : W;
    int bsz = bok ? 16 : 0;
    unsigned adst = smA + (unsigned)(ar * ASTR + ak) * 4u;
    unsigned bdst = smB + (unsigned)(br * ASTR + bk) * 4u;
    const unsigned aStage = GBM * ASTR * 4u;
    const unsigned bStage = GBN * ASTR * 4u;

    float acc[2][4][4];
    #pragma unroll
    for (int mi = 0; mi < 2; mi++)
        #pragma unroll
        for (int ni = 0; ni < 4; ni++)
            #pragma unroll
            for (int q = 0; q < 4; q++) acc[mi][ni][q] = 0.0f;

    int nIt = K >> 4;
    #pragma unroll
    for (int s = 0; s < GSTAGES - 1; s++) {
        cp16(adst + s * aStage,      Abase + s * 16,     16);
        cp16(adst + s * aStage + 16, Abase + s * 16 + 4, 16);
        cp16(bdst + s * bStage,      Bbase + (bok ? s * 16 : 0), bsz);
        cp_commit();
    }

    for (int it = 0; it < nIt; it++) {
        cp_wait<GSTAGES - 2>();
        __syncthreads();
        int buf = it & (GSTAGES - 1);
        const float* Ab = As + buf * (GBM * ASTR);
        const float* Bb = Bs + buf * (GBN * ASTR);
        #pragma unroll
        for (int ks = 0; ks < 2; ks++) {
            int k8 = ks * 8;
            unsigned afr[2][4], bfr[4][2];
            #pragma unroll
            for (int mi = 0; mi < 2; mi++) {
                int rb = wm + mi * 16 + gid;
                afr[mi][0] = __float_as_uint(Ab[(rb)     * ASTR + k8 + tig]);
                afr[mi][1] = __float_as_uint(Ab[(rb + 8) * ASTR + k8 + tig]);
                afr[mi][2] = __float_as_uint(Ab[(rb)     * ASTR + k8 + tig + 4]);
                afr[mi][3] = __float_as_uint(Ab[(rb + 8) * ASTR + k8 + tig + 4]);
            }
            #pragma unroll
            for (int ni = 0; ni < 4; ni++) {
                int cb = wn + ni * 8 + gid;
                bfr[ni][0] = __float_as_uint(Bb[cb * ASTR + k8 + tig]);
                bfr[ni][1] = __float_as_uint(Bb[cb * ASTR + k8 + tig + 4]);
            }
            #pragma unroll
            for (int mi = 0; mi < 2; mi++)
                #pragma unroll
                for (int ni = 0; ni < 4; ni++)
                    mma_tf32(acc[mi][ni], afr[mi], bfr[ni]);
        }
        int nx = it + GSTAGES - 1;
        if (nx < nIt) {
            int slot = nx & (GSTAGES - 1);
            cp16(adst + slot * aStage,      Abase + nx * 16,     16);
            cp16(adst + slot * aStage + 16, Abase + nx * 16 + 4, 16);
            cp16(bdst + slot * bStage,      Bbase + (bok ? nx * 16 : 0), bsz);
        }
        cp_commit();
    }

    #pragma unroll
    for (int mi = 0; mi < 2; mi++) {
        int row = m0 + wm + mi * 16 + gid;
        #pragma unroll
        for (int ni = 0; ni < 4; ni++) {
            int col = n0 + wn + ni * 8 + tig * 2;
            if (col < N) {
                float v0 = acc[mi][ni][0];
                float v2 = acc[mi][ni][2];
                if (R) { v0 += R[(size_t)row * N + col]; v2 += R[(size_t)(row + 8) * N + col]; }
                C[(size_t)row * N + col] = v0;
                C[(size_t)(row + 8) * N + col] = v2;
            }
            if (col + 1 < N) {
                float v1 = acc[mi][ni][1];
                float v3 = acc[mi][ni][3];
                if (R) { v1 += R[(size_t)row * N + col + 1]; v3 += R[(size_t)(row + 8) * N + col + 1]; }
                C[(size_t)row * N + col + 1] = v1;
                C[(size_t)(row + 8) * N + col + 1] = v3;
            }
        }
    }
}

// ---------------------------------------------------------------------------
// Depthwise causal conv (k=4) + bias + SiLU.  xz[:, 0:512] -> xc
// ---------------------------------------------------------------------------
__global__ void conv_silu_kernel(const float* __restrict__ xz,
                                 const float* __restrict__ cw,
                                 const float* __restrict__ cb,
                                 float* __restrict__ xc) {
    int idx = blockIdx.x * 256 + threadIdx.x;
    int d = idx & (DI - 1);
    int bt = idx >> 9;
    int b = bt >> 11;
    int l = bt & (LSEQ - 1);
    float acc = cb[d];
    #pragma unroll
    for (int k = 0; k < 4; k++) {
        int ls = l + k - 3;
        if (ls >= 0)
            acc += xz[((size_t)((b << 11) | ls)) * (2 * DI) + d] * cw[d * 4 + k];
    }
    float sg = 1.0f / (1.0f + __expf(-acc));
    xc[(size_t)bt * DI + d] = acc * sg;
}

// ---------------------------------------------------------------------------
// Selective scan with fused dt; deferred reduce-scatter for y.
// B,C interleaved as float2 in smem -> 2x LDS.64 per step instead of 4x LDS.32.
// ---------------------------------------------------------------------------
#define TCHUNK 64
__global__ void __launch_bounds__(256) scan_kernel(
        const float* __restrict__ xdbl,
        const float* __restrict__ xc,
        const float* __restrict__ xz,
        const float* __restrict__ A_log,
        const float* __restrict__ Dvec,
        const float* __restrict__ dtw,
        const float* __restrict__ dtb,
        float* __restrict__ y) {
    __shared__ float2 sBC[TCHUNK][64];   // (.x = B, .y = C)
    __shared__ float sx16[TCHUNK][16];
    __shared__ float2 sdx[TCHUNK][8];    // (dt, xc)
    __shared__ float sz[TCHUNK][8];
    __shared__ float sy[TCHUNK][8];
    __shared__ float sw[8][16];
    __shared__ float sbias[8];

    int b = blockIdx.x >> 6;
    int dbase = (blockIdx.x & 63) * 8;
    int wid = threadIdx.x >> 5;
    int lane = threadIdx.x & 31;
    int d = dbase + wid;

    if (threadIdx.x < 128) {
        int di = threadIdx.x >> 4, r = threadIdx.x & 15;
        sw[di][r] = dtw[(dbase + di) * DTR + r];
        if (r == 0) sbias[di] = dtb[dbase + di];
    }
    float A0 = -__expf(A_log[d * DS + lane]);
    float A1 = -__expf(A_log[d * DS + lane + 32]);
    float Dd = Dvec[d];
    float h0 = 0.0f, h1 = 0.0f;

    for (int t0 = 0; t0 < LSEQ; t0 += TCHUNK) {
        for (int i = threadIdx.x; i < TCHUNK * 128; i += 256) {
            int tt = i >> 7;
            int c = i & 127;
            float v = xdbl[(size_t)(b * LSEQ + t0 + tt) * XDBLW + DTR + c];
            if (c < 64) sBC[tt][c].x = v; else sBC[tt][c - 64].y = v;
        }
        for (int i = threadIdx.x; i < TCHUNK * 16; i += 256) {
            int tt = i >> 4, r = i & 15;
            sx16[tt][r] = xdbl[(size_t)(b * LSEQ + t0 + tt) * XDBLW + r];
        }
        for (int i = threadIdx.x; i < TCHUNK * 8; i += 256) {
            int tt = i >> 3, di = i & 7;
            size_t bt = (size_t)(b * LSEQ + t0 + tt);
            sdx[tt][di].y = xc[bt * DI + dbase + di];
            sz[tt][di]    = xz[bt * (2 * DI) + DI + dbase + di];
        }
        __syncthreads();
        for (int i = threadIdx.x; i < TCHUNK * 8; i += 256) {
            int tt = i >> 3, di = i & 7;
            float acc = sbias[di];
            #pragma unroll
            for (int r = 0; r < 16; r++) acc = fmaf(sx16[tt][r], sw[di][r], acc);
            sdx[tt][di].x = (acc > 20.0f) ? acc : __logf(1.0f + __expf(acc));
        }
        __syncthreads();

        #pragma unroll 1
        for (int g = 0; g < TCHUNK / 32; g++) {
            float part[32];
            #pragma unroll
            for (int j = 0; j < 32; j++) {
                int tt = g * 32 + j;
                float2 dx = sdx[tt][wid];
                float du = dx.x * dx.y;
                float dA0 = __expf(dx.x * A0);
                float dA1 = __expf(dx.x * A1);
                float2 bc0 = sBC[tt][lane];
                float2 bc1 = sBC[tt][lane + 32];
                h0 = fmaf(dA0, h0, du * bc0.x);
                h1 = fmaf(dA1, h1, du * bc1.x);
                part[j] = fmaf(h0, bc0.y, h1 * bc1.y);
            }
            #pragma unroll
            for (int s = 16; s >= 1; s >>= 1) {
                bool up = (lane & s) != 0;
                #pragma unroll
                for (int i2 = 0; i2 < 16; i2++) {
                    if (i2 >= s) break;
                    float keep = up ? part[i2 + s] : part[i2];
                    float send = up ? part[i2] : part[i2 + s];
                    part[i2] = keep + __shfl_xor_sync(0xffffffffu, send, s);
                }
            }
            int tt = g * 32 + lane;
            float2 dx = sdx[tt][wid];
            float zv = sz[tt][wid];
            float gate = zv / (1.0f + __expf(-zv));
            sy[tt][wid] = fmaf(dx.y, Dd, part[0]) * gate;
        }
        __syncthreads();
        for (int i = threadIdx.x; i < TCHUNK * 8; i += 256) {
            int tt = i >> 3, di = i & 7;
            y[(size_t)(b * LSEQ + t0 + tt) * DI + dbase + di] = sy[tt][di];
        }
        __syncthreads();
    }
}

// ---------------------------------------------------------------------------
// Forward 2048-pt FFT (DIF, natural -> bit-reversed), real input.
// 4 channels per block (128 blocks), float4 global I/O, padded stride 2049.
// ---------------------------------------------------------------------------
#define FSTR 2049
#define FFT_SMEM (2 * 4 * FSTR * 4)

__global__ void __launch_bounds__(512) fft_fwd_kernel(const float* __restrict__ xin,
                                                      float* __restrict__ dR,
                                                      float* __restrict__ dI) {
    extern __shared__ float sm[];
    float* sr = sm;
    float* si = sm + 4 * FSTR;
    int b = blockIdx.x >> 6;
    int c0 = (blockIdx.x & 63) * 4;
    size_t base = (size_t)b * LSEQ * DIMC + c0;
    int tid = threadIdx.x;

    for (int n = tid; n < 2048; n += 512) {
        float4 v = *(const float4*)(xin + base + (size_t)n * DIMC);
        sr[0 * FSTR + n] = v.x; sr[1 * FSTR + n] = v.y;
        sr[2 * FSTR + n] = v.z; sr[3 * FSTR + n] = v.w;
        si[0 * FSTR + n] = 0.0f; si[1 * FSTR + n] = 0.0f;
        si[2 * FSTR + n] = 0.0f; si[3 * FSTR + n] = 0.0f;
    }
    __syncthreads();

    #pragma unroll
    for (int hb = 10; hb >= 0; hb--) {
        int half = 1 << hb;
        float th = -PI_F / (float)half;
        for (int e = tid; e < 4096; e += 512) {
            int col = e >> 10, idx = e & 1023;
            int j = idx & (half - 1);
            int pos = ((idx >> hb) << (hb + 1)) + j;
            float* cr = sr + col * FSTR;
            float* ci = si + col * FSTR;
            float ar = cr[pos],        ai = ci[pos];
            float br = cr[pos + half], bi = ci[pos + half];
            float wi, wr;
            __sincosf(th * (float)j, &wi, &wr);
            float xr = ar - br, xi = ai - bi;
            cr[pos] = ar + br;  ci[pos] = ai + bi;
            cr[pos + half] = xr * wr - xi * wi;
            ci[pos + half] = xr * wi + xi * wr;
        }
        __syncthreads();
    }

    for (int n = tid; n < 2048; n += 512) {
        float4 vr, vi;
        vr.x = sr[0 * FSTR + n]; vr.y = sr[1 * FSTR + n];
        vr.z = sr[2 * FSTR + n]; vr.w = sr[3 * FSTR + n];
        vi.x = si[0 * FSTR + n]; vi.y = si[1 * FSTR + n];
        vi.z = si[2 * FSTR + n]; vi.w = si[3 * FSTR + n];
        *(float4*)(dR + base + (size_t)n * DIMC) = vr;
        *(float4*)(dI + base + (size_t)n * DIMC) = vi;
    }
}

// ---------------------------------------------------------------------------
// Inverse 2048-pt FFT (DIT, bit-reversed -> natural); real part + residual.
// ---------------------------------------------------------------------------
__global__ void __launch_bounds__(512) fft_inv_kernel(const float* __restrict__ dR,
                                                      const float* __restrict__ dI,
                                                      const float* __restrict__ x1,
                                                      float* __restrict__ out) {
    extern __shared__ float sm[];
    float* sr = sm;
    float* si = sm + 4 * FSTR;
    int b = blockIdx.x >> 6;
    int c0 = (blockIdx.x & 63) * 4;
    size_t base = (size_t)b * LSEQ * DIMC + c0;
    int tid = threadIdx.x;

    for (int n = tid; n < 2048; n += 512) {
        float4 vr = *(const float4*)(dR + base + (size_t)n * DIMC);
        float4 vi = *(const float4*)(dI + base + (size_t)n * DIMC);
        sr[0 * FSTR + n] = vr.x; sr[1 * FSTR + n] = vr.y;
        sr[2 * FSTR + n] = vr.z; sr[3 * FSTR + n] = vr.w;
        si[0 * FSTR + n] = vi.x; si[1 * FSTR + n] = vi.y;
        si[2 * FSTR + n] = vi.z; si[3 * FSTR + n] = vi.w;
    }
    __syncthreads();

    #pragma unroll
    for (int hb = 0; hb <= 10; hb++) {
        int half = 1 << hb;
        float th = PI_F / (float)half;
        for (int e = tid; e < 4096; e += 512) {
            int col = e >> 10, idx = e & 1023;
            int j = idx & (half - 1);
            int pos = ((idx >> hb) << (hb + 1)) + j;
            float* cr = sr + col * FSTR;
            float* ci = si + col * FSTR;
            float ar = cr[pos],        ai = ci[pos];
            float br = cr[pos + half], bi = ci[pos + half];
            float wi, wr;
            __sincosf(th * (float)j, &wi, &wr);
            float tr = br * wr - bi * wi;
            float ti = br * wi + bi * wr;
            cr[pos] = ar + tr;         ci[pos] = ai + ti;
            cr[pos + half] = ar - tr;  ci[pos + half] = ai - ti;
        }
        __syncthreads();
    }

    for (int n = tid; n < 2048; n += 512) {
        size_t a = base + (size_t)n * DIMC;
        float4 rx = *(const float4*)(x1 + a);
        float4 o;
        o.x = rx.x + sr[0 * FSTR + n];
        o.y = rx.y + sr[1 * FSTR + n];
        o.z = rx.z + sr[2 * FSTR + n];
        o.w = rx.w + sr[3 * FSTR + n];
        *(float4*)(out + a) = o;
    }
}

// ---------------------------------------------------------------------------
// EinFFT MLP with DFT4/IDFT4 over the NB axis folded in.
// dd-loops unrolled x4 to batch the weight loads (hide L2 latency).
// ---------------------------------------------------------------------------
__global__ void __launch_bounds__(256) einfft_mlp_kernel(
        float* __restrict__ fR, float* __restrict__ fI,
        const float* __restrict__ cw1, const float* __restrict__ cb1,
        const float* __restrict__ cw2, const float* __restrict__ cb2) {
    __shared__ float sR[2048], sI[2048];
    __shared__ float tR[2048], tI[2048];
    int row0 = blockIdx.x * 8;
    int tid = threadIdx.x;
    for (int i = tid; i < 2048; i += 256) {
        sR[i] = fR[(size_t)row0 * DIMC + i];
        sI[i] = fI[(size_t)row0 * DIMC + i];
    }
    __syncthreads();

    const float sc = SQRT_INV_8192;
    #pragma unroll
    for (int g = tid; g < 512; g += 256) {
        int r = g >> 6, s = g & 63;
        int p = r * 256 + s;
        float r0 = sR[p],       i0 = sI[p];
        float r1 = sR[p + 64],  i1 = sI[p + 64];
        float r2 = sR[p + 128], i2 = sI[p + 128];
        float r3 = sR[p + 192], i3 = sI[p + 192];
        sR[p]       = (r0 + r1 + r2 + r3) * sc;
        sI[p]       = (i0 + i1 + i2 + i3) * sc;
        sR[p + 64]  = (r0 + i1 - r2 - i3) * sc;
        sI[p + 64]  = (i0 - r1 - i2 + r3) * sc;
        sR[p + 128] = (r0 - r1 + r2 - r3) * sc;
        sI[p + 128] = (i0 - i1 + i2 - i3) * sc;
        sR[p + 192] = (r0 - i1 - r2 + i3) * sc;
        sI[p + 192] = (i0 + r1 - i2 - r3) * sc;
    }
    __syncthreads();

    int k = tid >> 6, o = tid & 63;

    {
        const float* w0 = cw1 + k * 4096;
        const float* w1 = cw1 + 16384 + k * 4096;
        float bR = cb1[k * 64 + o];
        float bI = cb1[256 + k * 64 + o];
        float aR[8], aI[8];
        #pragma unroll
        for (int r = 0; r < 8; r++) { aR[r] = bR; aI[r] = bI; }
        #pragma unroll 4
        for (int dd = 0; dd < 64; dd++) {
            float wa = w0[dd * 64 + o];
            float wb = w1[dd * 64 + o];
            int sb = k * 64 + dd;
            #pragma unroll
            for (int r = 0; r < 8; r++) {
                float xr = sR[r * 256 + sb];
                float xi = sI[r * 256 + sb];
                aR[r] = fmaf(xr, wa, fmaf(-xi, wb, aR[r]));
                aI[r] = fmaf(xr, wb, fmaf( xi, wa, aI[r]));
            }
        }
        #pragma unroll
        for (int r = 0; r < 8; r++) {
            tR[r * 256 + tid] = fmaxf(aR[r], 0.0f);
            tI[r * 256 + tid] = fmaxf(aI[r], 0.0f);
        }
    }
    __syncthreads();

    {
        const float* w0 = cw2 + k * 4096;
        const float* w1 = cw2 + 16384 + k * 4096;
        float bR = cb2[k * 64 + o];
        float bI = cb2[256 + k * 64 + o];
        float aR[8], aI[8];
        #pragma unroll
        for (int r = 0; r < 8; r++) { aR[r] = bR; aI[r] = bI; }
        #pragma unroll 4
        for (int dd = 0; dd < 64; dd++) {
            float wa = w0[dd * 64 + o];
            float wb = w1[dd * 64 + o];
            int sb = k * 64 + dd;
            #pragma unroll
            for (int r = 0; r < 8; r++) {
                float xr = tR[r * 256 + sb];
                float xi = tI[r * 256 + sb];
                aR[r] = fmaf(xr, wa, fmaf(-xi, wb, aR[r]));
                aI[r] = fmaf(xr, wb, fmaf( xi, wa, aI[r]));
            }
        }
        #pragma unroll
        for (int r = 0; r < 8; r++) {
            float vR = aR[r], vI = aI[r];
            vR = (vR > LAMBDA_SS) ? vR - LAMBDA_SS
                 : ((vR < -LAMBDA_SS) ? vR + LAMBDA_SS : 0.0f);
            vI = (vI > LAMBDA_SS) ? vI - LAMBDA_SS
                 : ((vI < -LAMBDA_SS) ? vI + LAMBDA_SS : 0.0f);
            sR[r * 256 + tid] = vR;
            sI[r * 256 + tid] = vI;
        }
    }
    __syncthreads();

    #pragma unroll
    for (int g = tid; g < 512; g += 256) {
        int r = g >> 6, s = g & 63;
        int p = r * 256 + s;
        float R0 = sR[p],       I0 = sI[p];
        float R1 = sR[p + 64],  I1 = sI[p + 64];
        float R2 = sR[p + 128], I2 = sI[p + 128];
        float R3 = sR[p + 192], I3 = sI[p + 192];
        sR[p]       = (R0 + R1 + R2 + R3) * sc;
        sI[p]       = (I0 + I1 + I2 + I3) * sc;
        sR[p + 64]  = (R0 - I1 - R2 + I3) * sc;
        sI[p + 64]  = (I0 + R1 - I2 - R3) * sc;
        sR[p + 128] = (R0 - R1 + R2 - R3) * sc;
        sI[p + 128] = (I0 - I1 + I2 - I3) * sc;
        sR[p + 192] = (R0 + I1 - R2 - I3) * sc;
        sI[p + 192] = (I0 - R1 - I2 + R3) * sc;
    }
    __syncthreads();

    for (int i = tid; i < 2048; i += 256) {
        fR[(size_t)row0 * DIMC + i] = sR[i];
        fI[(size_t)row0 * DIMC + i] = sI[i];
    }
}

// ---------------------------------------------------------------------------
// Launch
// ---------------------------------------------------------------------------
extern "C" void kernel_launch(void* const* d_in, const int* in_sizes, int n_in,
                              void* d_out, int out_size) {
    const float* x         = (const float*)d_in[0];
    const float* norm1_w   = (const float*)d_in[1];
    const float* norm1_b   = (const float*)d_in[2];
    const float* in_proj_w = (const float*)d_in[3];
    const float* conv_w    = (const float*)d_in[4];
    const float* conv_b    = (const float*)d_in[5];
    const float* x_proj_w  = (const float*)d_in[6];
    const float* dt_proj_w = (const float*)d_in[7];
    const float* dt_proj_b = (const float*)d_in[8];
    const float* A_log     = (const float*)d_in[9];
    const float* Dvec      = (const float*)d_in[10];
    const float* out_proj_w= (const float*)d_in[11];
    const float* norm2_w   = (const float*)d_in[12];
    const float* norm2_b   = (const float*)d_in[13];
    const float* cw1       = (const float*)d_in[14];
    const float* cb1       = (const float*)d_in[15];
    const float* cw2       = (const float*)d_in[16];
    const float* cb2       = (const float*)d_in[17];
    float* out = (float*)d_out;

    void* sp = nullptr;
    cudaGetSymbolAddress(&sp, SCRATCH);
    float* S = (float*)sp;
    float* s_xn   = S + O_XN;
    float* s_xz   = S + O_XZ;
    float* s_xc   = S + O_XC;
    float* s_xdbl = S + O_XDBL;
    float* s_y    = S + O_Y;
    float* s_x1   = S + O_X1;
    float* s_xn2  = S + O_XN2;
    float* s_fr   = S + O_FR;
    float* s_fi   = S + O_FI;

    static int attr_done = 0;
    if (!attr_done) {
        cudaFuncSetAttribute(fft_fwd_kernel,
                             cudaFuncAttributeMaxDynamicSharedMemorySize, FFT_SMEM);
        cudaFuncSetAttribute(fft_inv_kernel,
                             cudaFuncAttributeMaxDynamicSharedMemorySize, FFT_SMEM);
        cudaFuncSetAttribute(gemm_tf32,
                             cudaFuncAttributeMaxDynamicSharedMemorySize, GEMM_SMEM);
        attr_done = 1;
    }

    // 1) LN1
    ln_kernel<<<NTOK / 8, 256>>>(x, norm1_w, norm1_b, s_xn);
    // 2) in_proj
    gemm_tf32<<<dim3((2 * DI) / GBN, NTOK / GBM), 256, GEMM_SMEM>>>(
        s_xn, in_proj_w, nullptr, s_xz, NTOK, 2 * DI, DIMC);
    // 3) conv + silu
    conv_silu_kernel<<<(NTOK * DI) / 256, 256>>>(s_xz, conv_w, conv_b, s_xc);
    // 4) x_proj
    gemm_tf32<<<dim3((XDBLW + GBN - 1) / GBN, NTOK / GBM), 256, GEMM_SMEM>>>(
        s_xc, x_proj_w, nullptr, s_xdbl, NTOK, XDBLW, DI);
    // 5) selective scan (fused dt + D-skip + silu(z) gate)
    scan_kernel<<<BATCH * (DI / 8), 256>>>(s_xdbl, s_xc, s_xz, A_log, Dvec,
                                           dt_proj_w, dt_proj_b, s_y);
    // 6) out_proj + residual
    gemm_tf32<<<dim3(DIMC / GBN, NTOK / GBM), 256, GEMM_SMEM>>>(
        s_y, out_proj_w, x, s_x1, NTOK, DIMC, DI);
    // 7) LN2
    ln_kernel<<<NTOK / 8, 256>>>(s_x1, norm2_w, norm2_b, s_xn2);
    // 8) forward FFT (4 ch/block, 128 blocks)
    fft_fwd_kernel<<<128, 512, FFT_SMEM>>>(s_xn2, s_fr, s_fi);
    // 9) fused EinFFT MLP (DFT4 + relu + softshrink + IDFT4)
    einfft_mlp_kernel<<<NTOK / 8, 256>>>(s_fr, s_fi, cw1, cb1, cw2, cb2);
    // 10) inverse FFT + residual -> out
    fft_inv_kernel<<<128, 512, FFT_SMEM>>>(s_fr, s_fi, s_x1, out);
}

// round 11
// speedup vs baseline: 1.1049x; 1.0524x over previous
#include <cuda_runtime.h>
#include <cuda_bf16.h>
#include <stdint.h>
#include <math.h>

// ---------------------------------------------------------------------------
// Problem constants
// ---------------------------------------------------------------------------
#define BATCH   2
#define LSEQ    2048
#define DIMC    256
#define DI      512          // d_inner
#define DS      64           // d_state
#define DTR     16           // dt_rank
#define XDBLW   144          // dt_rank + 2*d_state
#define NTOK    (BATCH*LSEQ) // 4096
#define SQRT_INV_8192 0.011048543456039806f
#define LAMBDA_SS 0.01f
#define PI_F 3.14159265358979323846f

// weight sizes (elems)
#define W_IN_N  (2*DI)
#define W_IN_K  DIMC
#define W_X_N   XDBLW
#define W_X_K   DI
#define W_O_N   DIMC
#define W_O_K   DI
#define W_IN_SZ (W_IN_N*W_IN_K)   // 262144
#define W_X_SZ  (W_X_N*W_X_K)     // 73728
#define W_O_SZ  (W_O_N*W_O_K)     // 131072

// ---------------------------------------------------------------------------
// Scratch (single __device__ array; no allocations anywhere)
// Offsets in float units; bf16 regions use 2 elems per float slot.
// ---------------------------------------------------------------------------
#define O_XZ    ((size_t)0)
#define O_XC    (O_XZ   + (size_t)NTOK*2*DI)
#define O_XDBL  (O_XC   + (size_t)NTOK*DI)
#define O_X1    (O_XDBL + (size_t)NTOK*XDBLW)
#define O_XN2   (O_X1   + (size_t)NTOK*DIMC)
#define O_FR    (O_XN2  + (size_t)NTOK*DIMC)
#define O_FI    (O_FR   + (size_t)NTOK*DIMC)
#define O_XNBF  (O_FI   + (size_t)NTOK*DIMC)               // bf16 NTOK*DIMC
#define O_XCBF  (O_XNBF + (size_t)NTOK*DIMC/2)             // bf16 NTOK*DI
#define O_YBF   (O_XCBF + (size_t)NTOK*DI/2)               // bf16 NTOK*DI
#define O_WBF   (O_YBF  + (size_t)NTOK*DI/2)               // bf16 weights
#define O_END   (O_WBF  + (size_t)(W_IN_SZ+W_X_SZ+W_O_SZ)/2 + 64)

__device__ float SCRATCH[O_END];

// ---------------------------------------------------------------------------
// cp.async helpers
// ---------------------------------------------------------------------------
__device__ __forceinline__ void cp16(unsigned dst, const void* src, int sz) {
    asm volatile("cp.async.cg.shared.global [%0], [%1], 16, %2;"
                 :: "r"(dst), "l"(src), "r"(sz));
}
__device__ __forceinline__ void cp_commit() {
    asm volatile("cp.async.commit_group;" ::: "memory");
}
template <int N>
__device__ __forceinline__ void cp_wait() {
    asm volatile("cp.async.wait_group %0;" :: "n"(N) : "memory");
}

// ---------------------------------------------------------------------------
// Weight fp32 -> bf16 convert (all three matrices, contiguous dest)
// ---------------------------------------------------------------------------
__global__ void wcvt_kernel(const float* __restrict__ w_in,
                            const float* __restrict__ w_x,
                            const float* __restrict__ w_o,
                            __nv_bfloat16* __restrict__ dst) {
    int total = W_IN_SZ + W_X_SZ + W_O_SZ;
    for (int i = blockIdx.x * 256 + threadIdx.x; i < total; i += gridDim.x * 256) {
        float v;
        if (i < W_IN_SZ) v = w_in[i];
        else if (i < W_IN_SZ + W_X_SZ) v = w_x[i - W_IN_SZ];
        else v = w_o[i - W_IN_SZ - W_X_SZ];
        dst[i] = __float2bfloat16_rn(v);
    }
}

// ---------------------------------------------------------------------------
// LayerNorm: one warp per token.  Writes fp32 (if out) and/or bf16 (if obf).
// ---------------------------------------------------------------------------
__global__ void ln_kernel(const float* __restrict__ x,
                          const float* __restrict__ w,
                          const float* __restrict__ b,
                          float* __restrict__ out,
                          __nv_bfloat16* __restrict__ obf) {
    int t = blockIdx.x * 8 + (threadIdx.x >> 5);
    int lane = threadIdx.x & 31;
    const float4* row = (const float4*)(x + (size_t)t * DIMC);
    float4 v0 = row[lane];
    float4 v1 = row[lane + 32];
    float s = v0.x + v0.y + v0.z + v0.w + v1.x + v1.y + v1.z + v1.w;
    #pragma unroll
    for (int off = 16; off; off >>= 1) s += __shfl_xor_sync(0xffffffffu, s, off);
    float m = s * (1.0f / 256.0f);
    float d0 = v0.x - m, d1 = v0.y - m, d2 = v0.z - m, d3 = v0.w - m;
    float d4 = v1.x - m, d5 = v1.y - m, d6 = v1.z - m, d7 = v1.w - m;
    float q = d0*d0 + d1*d1 + d2*d2 + d3*d3 + d4*d4 + d5*d5 + d6*d6 + d7*d7;
    #pragma unroll
    for (int off = 16; off; off >>= 1) q += __shfl_xor_sync(0xffffffffu, q, off);
    float inv = rsqrtf(q * (1.0f / 256.0f) + 1e-5f);
    const float4* w4 = (const float4*)w;
    const float4* b4 = (const float4*)b;
    float4 wa = w4[lane], ba = b4[lane];
    float4 wb = w4[lane + 32], bb = b4[lane + 32];
    float4 r0, r1;
    r0.x = d0*inv*wa.x + ba.x; r0.y = d1*inv*wa.y + ba.y;
    r0.z = d2*inv*wa.z + ba.z; r0.w = d3*inv*wa.w + ba.w;
    r1.x = d4*inv*wb.x + bb.x; r1.y = d5*inv*wb.y + bb.y;
    r1.z = d6*inv*wb.z + bb.z; r1.w = d7*inv*wb.w + bb.w;
    if (out) {
        float4* o4 = (float4*)(out + (size_t)t * DIMC);
        o4[lane] = r0; o4[lane + 32] = r1;
    }
    if (obf) {
        __nv_bfloat162* o2 = (__nv_bfloat162*)(obf + (size_t)t * DIMC);
        o2[lane*2]      = __nv_bfloat162(__float2bfloat16_rn(r0.x), __float2bfloat16_rn(r0.y));
        o2[lane*2 + 1]  = __nv_bfloat162(__float2bfloat16_rn(r0.z), __float2bfloat16_rn(r0.w));
        o2[64 + lane*2]     = __nv_bfloat162(__float2bfloat16_rn(r1.x), __float2bfloat16_rn(r1.y));
        o2[64 + lane*2 + 1] = __nv_bfloat162(__float2bfloat16_rn(r1.z), __float2bfloat16_rn(r1.w));
    }
}

// ---------------------------------------------------------------------------
// bf16 tensor-core GEMM: C[M,N] = A[M,K] * W[N,K]^T (+ R[M,N]).
// 128x64 block tile, BK=32, 256 threads = 8 warps (4m x 2n), warp tile 32x32
// via 2x4 mma.sync.m16n8k16.bf16, 2 k-steps per tile.  4-stage cp.async.
// M%128==0, K%32==0 guaranteed.
// ---------------------------------------------------------------------------
#define GBM 128
#define GBN 64
#define BK  32
#define HSTR 40          // bf16 row stride in smem (pad 8)
#define GSTAGES 4
#define GEMM_SMEM (GSTAGES * (GBM + GBN) * HSTR * 2)

__device__ __forceinline__ void mma_bf16(float* c, const unsigned* a, const unsigned* b) {
    asm volatile(
        "mma.sync.aligned.m16n8k16.row.col.f32.bf16.bf16.f32 "
        "{%0,%1,%2,%3}, {%4,%5,%6,%7}, {%8,%9}, {%0,%1,%2,%3};"
        : "+f"(c[0]), "+f"(c[1]), "+f"(c[2]), "+f"(c[3])
        : "r"(a[0]), "r"(a[1]), "r"(a[2]), "r"(a[3]), "r"(b[0]), "r"(b[1]));
}

__global__ void __launch_bounds__(256) gemm_bf16(const __nv_bfloat16* __restrict__ A,
                                                 const __nv_bfloat16* __restrict__ W,
                                                 const float* __restrict__ R,
                                                 float* __restrict__ C,
                                                 int M, int N, int K) {
    extern __shared__ __nv_bfloat16 hsm[];
    __nv_bfloat16* As = hsm;                               // GSTAGES*GBM*HSTR
    __nv_bfloat16* Bs = hsm + GSTAGES * GBM * HSTR;        // GSTAGES*GBN*HSTR
    unsigned smA = (unsigned)__cvta_generic_to_shared(As);
    unsigned smB = (unsigned)__cvta_generic_to_shared(Bs);

    int m0 = blockIdx.y * GBM;
    int n0 = blockIdx.x * GBN;
    int tid = threadIdx.x;
    int wid = tid >> 5, lane = tid & 31;
    int wm = (wid & 3) * 32;
    int wn = (wid >> 2) * 32;
    int gid = lane >> 2;       // 0..7
    int tig = lane & 3;        // 0..3
    int ar = tid >> 1, akq = (tid & 1) * 16;   // A: 2 cp16 per thread
    int br = tid >> 2, bkq = (tid & 3) * 8;    // B: 1 cp16 per thread

    const __nv_bfloat16* Abase = A + (size_t)(m0 + ar) * K + akq;
    bool bok = (n0 + br) < N;
    const __nv_bfloat16* Bbase = bok ? (W + (size_t)(n0 + br) * K + bkq) : W;
    int bsz = bok ? 16 : 0;
    unsigned adst = smA + (unsigned)(ar * HSTR + akq) * 2u;
    unsigned bdst = smB + (unsigned)(br * HSTR + bkq) * 2u;
    const unsigned aStage = GBM * HSTR * 2u;
    const unsigned bStage = GBN * HSTR * 2u;

    float acc[2][4][4];
    #pragma unroll
    for (int mi = 0; mi < 2; mi++)
        #pragma unroll
        for (int ni = 0; ni < 4; ni++)
            #pragma unroll
            for (int q = 0; q < 4; q++) acc[mi][ni][q] = 0.0f;

    int nIt = K / BK;
    // prologue
    #pragma unroll
    for (int s = 0; s < GSTAGES - 1; s++) {
        cp16(adst + s * aStage,      Abase + s * BK,     16);
        cp16(adst + s * aStage + 16, Abase + s * BK + 8, 16);
        cp16(bdst + s * bStage,      Bbase + (bok ? s * BK : 0), bsz);
        cp_commit();
    }

    for (int it = 0; it < nIt; it++) {
        cp_wait<GSTAGES - 2>();
        __syncthreads();
        int buf = it & (GSTAGES - 1);
        const __nv_bfloat16* Ab = As + buf * (GBM * HSTR);
        const __nv_bfloat16* Bb = Bs + buf * (GBN * HSTR);
        #pragma unroll
        for (int ks = 0; ks < 2; ks++) {
            int k16 = ks * 16;
            unsigned afr[2][4], bfr[4][2];
            #pragma unroll
            for (int mi = 0; mi < 2; mi++) {
                int rb = wm + mi * 16 + gid;
                afr[mi][0] = *(const unsigned*)(Ab + (rb)     * HSTR + k16 + tig * 2);
                afr[mi][1] = *(const unsigned*)(Ab + (rb + 8) * HSTR + k16 + tig * 2);
                afr[mi][2] = *(const unsigned*)(Ab + (rb)     * HSTR + k16 + tig * 2 + 8);
                afr[mi][3] = *(const unsigned*)(Ab + (rb + 8) * HSTR + k16 + tig * 2 + 8);
            }
            #pragma unroll
            for (int ni = 0; ni < 4; ni++) {
                int cb = wn + ni * 8 + gid;
                bfr[ni][0] = *(const unsigned*)(Bb + cb * HSTR + k16 + tig * 2);
                bfr[ni][1] = *(const unsigned*)(Bb + cb * HSTR + k16 + tig * 2 + 8);
            }
            #pragma unroll
            for (int mi = 0; mi < 2; mi++)
                #pragma unroll
                for (int ni = 0; ni < 4; ni++)
                    mma_bf16(acc[mi][ni], afr[mi], bfr[ni]);
        }
        int nx = it + GSTAGES - 1;
        if (nx < nIt) {
            int slot = nx & (GSTAGES - 1);
            cp16(adst + slot * aStage,      Abase + nx * BK,     16);
            cp16(adst + slot * aStage + 16, Abase + nx * BK + 8, 16);
            cp16(bdst + slot * bStage,      Bbase + (bok ? nx * BK : 0), bsz);
        }
        cp_commit();
    }

    #pragma unroll
    for (int mi = 0; mi < 2; mi++) {
        int row = m0 + wm + mi * 16 + gid;
        #pragma unroll
        for (int ni = 0; ni < 4; ni++) {
            int col = n0 + wn + ni * 8 + tig * 2;
            if (col < N) {
                float v0 = acc[mi][ni][0];
                float v2 = acc[mi][ni][2];
                if (R) { v0 += R[(size_t)row * N + col]; v2 += R[(size_t)(row + 8) * N + col]; }
                C[(size_t)row * N + col] = v0;
                C[(size_t)(row + 8) * N + col] = v2;
            }
            if (col + 1 < N) {
                float v1 = acc[mi][ni][1];
                float v3 = acc[mi][ni][3];
                if (R) { v1 += R[(size_t)row * N + col + 1]; v3 += R[(size_t)(row + 8) * N + col + 1]; }
                C[(size_t)row * N + col + 1] = v1;
                C[(size_t)(row + 8) * N + col + 1] = v3;
            }
        }
    }
}

// ---------------------------------------------------------------------------
// Depthwise causal conv (k=4) + bias + SiLU.  Writes fp32 xc and bf16 xc_bf.
// ---------------------------------------------------------------------------
__global__ void conv_silu_kernel(const float* __restrict__ xz,
                                 const float* __restrict__ cw,
                                 const float* __restrict__ cb,
                                 float* __restrict__ xc,
                                 __nv_bfloat16* __restrict__ xc_bf) {
    int idx = blockIdx.x * 256 + threadIdx.x;
    int d = idx & (DI - 1);
    int bt = idx >> 9;
    int b = bt >> 11;
    int l = bt & (LSEQ - 1);
    float acc = cb[d];
    #pragma unroll
    for (int k = 0; k < 4; k++) {
        int ls = l + k - 3;
        if (ls >= 0)
            acc += xz[((size_t)((b << 11) | ls)) * (2 * DI) + d] * cw[d * 4 + k];
    }
    float sg = 1.0f / (1.0f + __expf(-acc));
    float v = acc * sg;
    xc[(size_t)bt * DI + d] = v;
    xc_bf[(size_t)bt * DI + d] = __float2bfloat16_rn(v);
}

// ---------------------------------------------------------------------------
// Selective scan with fused dt; deferred reduce-scatter for y.  y out in bf16.
// ---------------------------------------------------------------------------
#define TCHUNK 64
__global__ void __launch_bounds__(256) scan_kernel(
        const float* __restrict__ xdbl,
        const float* __restrict__ xc,
        const float* __restrict__ xz,
        const float* __restrict__ A_log,
        const float* __restrict__ Dvec,
        const float* __restrict__ dtw,
        const float* __restrict__ dtb,
        __nv_bfloat16* __restrict__ y_bf) {
    __shared__ float2 sBC[TCHUNK][64];   // (.x = B, .y = C)
    __shared__ float sx16[TCHUNK][16];
    __shared__ float2 sdx[TCHUNK][8];    // (dt, xc)
    __shared__ float sz[TCHUNK][8];
    __shared__ float sy[TCHUNK][8];
    __shared__ float sw[8][16];
    __shared__ float sbias[8];

    int b = blockIdx.x >> 6;
    int dbase = (blockIdx.x & 63) * 8;
    int wid = threadIdx.x >> 5;
    int lane = threadIdx.x & 31;
    int d = dbase + wid;

    if (threadIdx.x < 128) {
        int di = threadIdx.x >> 4, r = threadIdx.x & 15;
        sw[di][r] = dtw[(dbase + di) * DTR + r];
        if (r == 0) sbias[di] = dtb[dbase + di];
    }
    float A0 = -__expf(A_log[d * DS + lane]);
    float A1 = -__expf(A_log[d * DS + lane + 32]);
    float Dd = Dvec[d];
    float h0 = 0.0f, h1 = 0.0f;

    for (int t0 = 0; t0 < LSEQ; t0 += TCHUNK) {
        for (int i = threadIdx.x; i < TCHUNK * 128; i += 256) {
            int tt = i >> 7;
            int c = i & 127;
            float v = xdbl[(size_t)(b * LSEQ + t0 + tt) * XDBLW + DTR + c];
            if (c < 64) sBC[tt][c].x = v; else sBC[tt][c - 64].y = v;
        }
        for (int i = threadIdx.x; i < TCHUNK * 16; i += 256) {
            int tt = i >> 4, r = i & 15;
            sx16[tt][r] = xdbl[(size_t)(b * LSEQ + t0 + tt) * XDBLW + r];
        }
        for (int i = threadIdx.x; i < TCHUNK * 8; i += 256) {
            int tt = i >> 3, di = i & 7;
            size_t bt = (size_t)(b * LSEQ + t0 + tt);
            sdx[tt][di].y = xc[bt * DI + dbase + di];
            sz[tt][di]    = xz[bt * (2 * DI) + DI + dbase + di];
        }
        __syncthreads();
        for (int i = threadIdx.x; i < TCHUNK * 8; i += 256) {
            int tt = i >> 3, di = i & 7;
            float acc = sbias[di];
            #pragma unroll
            for (int r = 0; r < 16; r++) acc = fmaf(sx16[tt][r], sw[di][r], acc);
            sdx[tt][di].x = (acc > 20.0f) ? acc : __logf(1.0f + __expf(acc));
        }
        __syncthreads();

        #pragma unroll 1
        for (int g = 0; g < TCHUNK / 32; g++) {
            float part[32];
            #pragma unroll
            for (int j = 0; j < 32; j++) {
                int tt = g * 32 + j;
                float2 dx = sdx[tt][wid];
                float du = dx.x * dx.y;
                float dA0 = __expf(dx.x * A0);
                float dA1 = __expf(dx.x * A1);
                float2 bc0 = sBC[tt][lane];
                float2 bc1 = sBC[tt][lane + 32];
                h0 = fmaf(dA0, h0, du * bc0.x);
                h1 = fmaf(dA1, h1, du * bc1.x);
                part[j] = fmaf(h0, bc0.y, h1 * bc1.y);
            }
            #pragma unroll
            for (int s = 16; s >= 1; s >>= 1) {
                bool up = (lane & s) != 0;
                #pragma unroll
                for (int i2 = 0; i2 < 16; i2++) {
                    if (i2 >= s) break;
                    float keep = up ? part[i2 + s] : part[i2];
                    float send = up ? part[i2] : part[i2 + s];
                    part[i2] = keep + __shfl_xor_sync(0xffffffffu, send, s);
                }
            }
            int tt = g * 32 + lane;
            float2 dx = sdx[tt][wid];
            float zv = sz[tt][wid];
            float gate = zv / (1.0f + __expf(-zv));
            sy[tt][wid] = fmaf(dx.y, Dd, part[0]) * gate;
        }
        __syncthreads();
        for (int i = threadIdx.x; i < TCHUNK * 8; i += 256) {
            int tt = i >> 3, di = i & 7;
            y_bf[(size_t)(b * LSEQ + t0 + tt) * DI + dbase + di] =
                __float2bfloat16_rn(sy[tt][di]);
        }
        __syncthreads();
    }
}

// ---------------------------------------------------------------------------
// Forward 2048-pt FFT (DIF, natural -> bit-reversed), real input.
// 4 channels per block (128 blocks), float4 global I/O, padded stride 2049.
// ---------------------------------------------------------------------------
#define FSTR 2049
#define FFT_SMEM (2 * 4 * FSTR * 4)

__global__ void __launch_bounds__(512) fft_fwd_kernel(const float* __restrict__ xin,
                                                      float* __restrict__ dR,
                                                      float* __restrict__ dI) {
    extern __shared__ float sm[];
    float* sr = sm;
    float* si = sm + 4 * FSTR;
    int b = blockIdx.x >> 6;
    int c0 = (blockIdx.x & 63) * 4;
    size_t base = (size_t)b * LSEQ * DIMC + c0;
    int tid = threadIdx.x;

    for (int n = tid; n < 2048; n += 512) {
        float4 v = *(const float4*)(xin + base + (size_t)n * DIMC);
        sr[0 * FSTR + n] = v.x; sr[1 * FSTR + n] = v.y;
        sr[2 * FSTR + n] = v.z; sr[3 * FSTR + n] = v.w;
        si[0 * FSTR + n] = 0.0f; si[1 * FSTR + n] = 0.0f;
        si[2 * FSTR + n] = 0.0f; si[3 * FSTR + n] = 0.0f;
    }
    __syncthreads();

    #pragma unroll
    for (int hb = 10; hb >= 0; hb--) {
        int half = 1 << hb;
        float th = -PI_F / (float)half;
        for (int e = tid; e < 4096; e += 512) {
            int col = e >> 10, idx = e & 1023;
            int j = idx & (half - 1);
            int pos = ((idx >> hb) << (hb + 1)) + j;
            float* cr = sr + col * FSTR;
            float* ci = si + col * FSTR;
            float ar = cr[pos],        ai = ci[pos];
            float br = cr[pos + half], bi = ci[pos + half];
            float wi, wr;
            __sincosf(th * (float)j, &wi, &wr);
            float xr = ar - br, xi = ai - bi;
            cr[pos] = ar + br;  ci[pos] = ai + bi;
            cr[pos + half] = xr * wr - xi * wi;
            ci[pos + half] = xr * wi + xi * wr;
        }
        __syncthreads();
    }

    for (int n = tid; n < 2048; n += 512) {
        float4 vr, vi;
        vr.x = sr[0 * FSTR + n]; vr.y = sr[1 * FSTR + n];
        vr.z = sr[2 * FSTR + n]; vr.w = sr[3 * FSTR + n];
        vi.x = si[0 * FSTR + n]; vi.y = si[1 * FSTR + n];
        vi.z = si[2 * FSTR + n]; vi.w = si[3 * FSTR + n];
        *(float4*)(dR + base + (size_t)n * DIMC) = vr;
        *(float4*)(dI + base + (size_t)n * DIMC) = vi;
    }
}

// ---------------------------------------------------------------------------
// Inverse 2048-pt FFT (DIT, bit-reversed -> natural); real part + residual.
// ---------------------------------------------------------------------------
__global__ void __launch_bounds__(512) fft_inv_kernel(const float* __restrict__ dR,
                                                      const float* __restrict__ dI,
                                                      const float* __restrict__ x1,
                                                      float* __restrict__ out) {
    extern __shared__ float sm[];
    float* sr = sm;
    float* si = sm + 4 * FSTR;
    int b = blockIdx.x >> 6;
    int c0 = (blockIdx.x & 63) * 4;
    size_t base = (size_t)b * LSEQ * DIMC + c0;
    int tid = threadIdx.x;

    for (int n = tid; n < 2048; n += 512) {
        float4 vr = *(const float4*)(dR + base + (size_t)n * DIMC);
        float4 vi = *(const float4*)(dI + base + (size_t)n * DIMC);
        sr[0 * FSTR + n] = vr.x; sr[1 * FSTR + n] = vr.y;
        sr[2 * FSTR + n] = vr.z; sr[3 * FSTR + n] = vr.w;
        si[0 * FSTR + n] = vi.x; si[1 * FSTR + n] = vi.y;
        si[2 * FSTR + n] = vi.z; si[3 * FSTR + n] = vi.w;
    }
    __syncthreads();

    #pragma unroll
    for (int hb = 0; hb <= 10; hb++) {
        int half = 1 << hb;
        float th = PI_F / (float)half;
        for (int e = tid; e < 4096; e += 512) {
            int col = e >> 10, idx = e & 1023;
            int j = idx & (half - 1);
            int pos = ((idx >> hb) << (hb + 1)) + j;
            float* cr = sr + col * FSTR;
            float* ci = si + col * FSTR;
            float ar = cr[pos],        ai = ci[pos];
            float br = cr[pos + half], bi = ci[pos + half];
            float wi, wr;
            __sincosf(th * (float)j, &wi, &wr);
            float tr = br * wr - bi * wi;
            float ti = br * wi + bi * wr;
            cr[pos] = ar + tr;         ci[pos] = ai + ti;
            cr[pos + half] = ar - tr;  ci[pos + half] = ai - ti;
        }
        __syncthreads();
    }

    for (int n = tid; n < 2048; n += 512) {
        size_t a = base + (size_t)n * DIMC;
        float4 rx = *(const float4*)(x1 + a);
        float4 o;
        o.x = rx.x + sr[0 * FSTR + n];
        o.y = rx.y + sr[1 * FSTR + n];
        o.z = rx.z + sr[2 * FSTR + n];
        o.w = rx.w + sr[3 * FSTR + n];
        *(float4*)(out + a) = o;
    }
}

// ---------------------------------------------------------------------------
// EinFFT MLP with DFT4/IDFT4 over the NB axis folded in.
// ---------------------------------------------------------------------------
__global__ void __launch_bounds__(256) einfft_mlp_kernel(
        float* __restrict__ fR, float* __restrict__ fI,
        const float* __restrict__ cw1, const float* __restrict__ cb1,
        const float* __restrict__ cw2, const float* __restrict__ cb2) {
    __shared__ float sR[2048], sI[2048];
    __shared__ float tR[2048], tI[2048];
    int row0 = blockIdx.x * 8;
    int tid = threadIdx.x;
    for (int i = tid; i < 2048; i += 256) {
        sR[i] = fR[(size_t)row0 * DIMC + i];
        sI[i] = fI[(size_t)row0 * DIMC + i];
    }
    __syncthreads();

    const float sc = SQRT_INV_8192;
    #pragma unroll
    for (int g = tid; g < 512; g += 256) {
        int r = g >> 6, s = g & 63;
        int p = r * 256 + s;
        float r0 = sR[p],       i0 = sI[p];
        float r1 = sR[p + 64],  i1 = sI[p + 64];
        float r2 = sR[p + 128], i2 = sI[p + 128];
        float r3 = sR[p + 192], i3 = sI[p + 192];
        sR[p]       = (r0 + r1 + r2 + r3) * sc;
        sI[p]       = (i0 + i1 + i2 + i3) * sc;
        sR[p + 64]  = (r0 + i1 - r2 - i3) * sc;
        sI[p + 64]  = (i0 - r1 - i2 + r3) * sc;
        sR[p + 128] = (r0 - r1 + r2 - r3) * sc;
        sI[p + 128] = (i0 - i1 + i2 - i3) * sc;
        sR[p + 192] = (r0 - i1 - r2 + i3) * sc;
        sI[p + 192] = (i0 + r1 - i2 - r3) * sc;
    }
    __syncthreads();

    int k = tid >> 6, o = tid & 63;

    {
        const float* w0 = cw1 + k * 4096;
        const float* w1 = cw1 + 16384 + k * 4096;
        float bR = cb1[k * 64 + o];
        float bI = cb1[256 + k * 64 + o];
        float aR[8], aI[8];
        #pragma unroll
        for (int r = 0; r < 8; r++) { aR[r] = bR; aI[r] = bI; }
        #pragma unroll 4
        for (int dd = 0; dd < 64; dd++) {
            float wa = w0[dd * 64 + o];
            float wb = w1[dd * 64 + o];
            int sb = k * 64 + dd;
            #pragma unroll
            for (int r = 0; r < 8; r++) {
                float xr = sR[r * 256 + sb];
                float xi = sI[r * 256 + sb];
                aR[r] = fmaf(xr, wa, fmaf(-xi, wb, aR[r]));
                aI[r] = fmaf(xr, wb, fmaf( xi, wa, aI[r]));
            }
        }
        #pragma unroll
        for (int r = 0; r < 8; r++) {
            tR[r * 256 + tid] = fmaxf(aR[r], 0.0f);
            tI[r * 256 + tid] = fmaxf(aI[r], 0.0f);
        }
    }
    __syncthreads();

    {
        const float* w0 = cw2 + k * 4096;
        const float* w1 = cw2 + 16384 + k * 4096;
        float bR = cb2[k * 64 + o];
        float bI = cb2[256 + k * 64 + o];
        float aR[8], aI[8];
        #pragma unroll
        for (int r = 0; r < 8; r++) { aR[r] = bR; aI[r] = bI; }
        #pragma unroll 4
        for (int dd = 0; dd < 64; dd++) {
            float wa = w0[dd * 64 + o];
            float wb = w1[dd * 64 + o];
            int sb = k * 64 + dd;
            #pragma unroll
            for (int r = 0; r < 8; r++) {
                float xr = tR[r * 256 + sb];
                float xi = tI[r * 256 + sb];
                aR[r] = fmaf(xr, wa, fmaf(-xi, wb, aR[r]));
                aI[r] = fmaf(xr, wb, fmaf( xi, wa, aI[r]));
            }
        }
        #pragma unroll
        for (int r = 0; r < 8; r++) {
            float vR = aR[r], vI = aI[r];
            vR = (vR > LAMBDA_SS) ? vR - LAMBDA_SS
                 : ((vR < -LAMBDA_SS) ? vR + LAMBDA_SS : 0.0f);
            vI = (vI > LAMBDA_SS) ? vI - LAMBDA_SS
                 : ((vI < -LAMBDA_SS) ? vI + LAMBDA_SS : 0.0f);
            sR[r * 256 + tid] = vR;
            sI[r * 256 + tid] = vI;
        }
    }
    __syncthreads();

    #pragma unroll
    for (int g = tid; g < 512; g += 256) {
        int r = g >> 6, s = g & 63;
        int p = r * 256 + s;
        float R0 = sR[p],       I0 = sI[p];
        float R1 = sR[p + 64],  I1 = sI[p + 64];
        float R2 = sR[p + 128], I2 = sI[p + 128];
        float R3 = sR[p + 192], I3 = sI[p + 192];
        sR[p]       = (R0 + R1 + R2 + R3) * sc;
        sI[p]       = (I0 + I1 + I2 + I3) * sc;
        sR[p + 64]  = (R0 - I1 - R2 + I3) * sc;
        sI[p + 64]  = (I0 + R1 - I2 - R3) * sc;
        sR[p + 128] = (R0 - R1 + R2 - R3) * sc;
        sI[p + 128] = (I0 - I1 + I2 - I3) * sc;
        sR[p + 192] = (R0 + I1 - R2 - I3) * sc;
        sI[p + 192] = (I0 - R1 - I2 + R3) * sc;
    }
    __syncthreads();

    for (int i = tid; i < 2048; i += 256) {
        fR[(size_t)row0 * DIMC + i] = sR[i];
        fI[(size_t)row0 * DIMC + i] = sI[i];
    }
}

// ---------------------------------------------------------------------------
// Launch
// ---------------------------------------------------------------------------
extern "C" void kernel_launch(void* const* d_in, const int* in_sizes, int n_in,
                              void* d_out, int out_size) {
    const float* x         = (const float*)d_in[0];
    const float* norm1_w   = (const float*)d_in[1];
    const float* norm1_b   = (const float*)d_in[2];
    const float* in_proj_w = (const float*)d_in[3];
    const float* conv_w    = (const float*)d_in[4];
    const float* conv_b    = (const float*)d_in[5];
    const float* x_proj_w  = (const float*)d_in[6];
    const float* dt_proj_w = (const float*)d_in[7];
    const float* dt_proj_b = (const float*)d_in[8];
    const float* A_log     = (const float*)d_in[9];
    const float* Dvec      = (const float*)d_in[10];
    const float* out_proj_w= (const float*)d_in[11];
    const float* norm2_w   = (const float*)d_in[12];
    const float* norm2_b   = (const float*)d_in[13];
    const float* cw1       = (const float*)d_in[14];
    const float* cb1       = (const float*)d_in[15];
    const float* cw2       = (const float*)d_in[16];
    const float* cb2       = (const float*)d_in[17];
    float* out = (float*)d_out;

    void* sp = nullptr;
    cudaGetSymbolAddress(&sp, SCRATCH);
    float* S = (float*)sp;
    float* s_xz   = S + O_XZ;
    float* s_xc   = S + O_XC;
    float* s_xdbl = S + O_XDBL;
    float* s_x1   = S + O_X1;
    float* s_xn2  = S + O_XN2;
    float* s_fr   = S + O_FR;
    float* s_fi   = S + O_FI;
    __nv_bfloat16* s_xnbf = (__nv_bfloat16*)(S + O_XNBF);
    __nv_bfloat16* s_xcbf = (__nv_bfloat16*)(S + O_XCBF);
    __nv_bfloat16* s_ybf  = (__nv_bfloat16*)(S + O_YBF);
    __nv_bfloat16* s_wbf  = (__nv_bfloat16*)(S + O_WBF);
    __nv_bfloat16* win_bf = s_wbf;
    __nv_bfloat16* wx_bf  = s_wbf + W_IN_SZ;
    __nv_bfloat16* wo_bf  = s_wbf + W_IN_SZ + W_X_SZ;

    static int attr_done = 0;
    if (!attr_done) {
        cudaFuncSetAttribute(fft_fwd_kernel,
                             cudaFuncAttributeMaxDynamicSharedMemorySize, FFT_SMEM);
        cudaFuncSetAttribute(fft_inv_kernel,
                             cudaFuncAttributeMaxDynamicSharedMemorySize, FFT_SMEM);
        cudaFuncSetAttribute(gemm_bf16,
                             cudaFuncAttributeMaxDynamicSharedMemorySize, GEMM_SMEM);
        attr_done = 1;
    }

    // 0) convert weights fp32 -> bf16
    wcvt_kernel<<<296, 256>>>(in_proj_w, x_proj_w, out_proj_w, s_wbf);
    // 1) LN1 -> bf16 only
    ln_kernel<<<NTOK / 8, 256>>>(x, norm1_w, norm1_b, nullptr, s_xnbf);
    // 2) in_proj (bf16 -> fp32)
    gemm_bf16<<<dim3((2 * DI) / GBN, NTOK / GBM), 256, GEMM_SMEM>>>(
        s_xnbf, win_bf, nullptr, s_xz, NTOK, 2 * DI, DIMC);
    // 3) conv + silu -> fp32 + bf16
    conv_silu_kernel<<<(NTOK * DI) / 256, 256>>>(s_xz, conv_w, conv_b, s_xc, s_xcbf);
    // 4) x_proj (bf16 -> fp32)
    gemm_bf16<<<dim3((XDBLW + GBN - 1) / GBN, NTOK / GBM), 256, GEMM_SMEM>>>(
        s_xcbf, wx_bf, nullptr, s_xdbl, NTOK, XDBLW, DI);
    // 5) selective scan -> bf16 y
    scan_kernel<<<BATCH * (DI / 8), 256>>>(s_xdbl, s_xc, s_xz, A_log, Dvec,
                                           dt_proj_w, dt_proj_b, s_ybf);
    // 6) out_proj + residual (bf16 -> fp32)
    gemm_bf16<<<dim3(DIMC / GBN, NTOK / GBM), 256, GEMM_SMEM>>>(
        s_ybf, wo_bf, x, s_x1, NTOK, DIMC, DI);
    // 7) LN2 -> fp32 only
    ln_kernel<<<NTOK / 8, 256>>>(s_x1, norm2_w, norm2_b, s_xn2, nullptr);
    // 8) forward FFT
    fft_fwd_kernel<<<128, 512, FFT_SMEM>>>(s_xn2, s_fr, s_fi);
    // 9) fused EinFFT MLP
    einfft_mlp_kernel<<<NTOK / 8, 256>>>(s_fr, s_fi, cw1, cb1, cw2, cb2);
    // 10) inverse FFT + residual -> out
    fft_inv_kernel<<<128, 512, FFT_SMEM>>>(s_fr, s_fi, s_x1, out);
}

// round 12
// speedup vs baseline: 1.5843x; 1.4339x over previous
#include <cuda_runtime.h>
#include <cuda_bf16.h>
#include <stdint.h>
#include <math.h>

// ---------------------------------------------------------------------------
// Problem constants
// ---------------------------------------------------------------------------
#define BATCH   2
#define LSEQ    2048
#define DIMC    256
#define DI      512          // d_inner
#define DS      64           // d_state
#define DTR     16           // dt_rank
#define XDBLW   144          // dt_rank + 2*d_state
#define NTOK    (BATCH*LSEQ) // 4096
#define SQRT_INV_8192 0.011048543456039806f
#define LAMBDA_SS 0.01f
#define PI_F 3.14159265358979323846f

// weight sizes (elems)
#define W_IN_SZ (2*DI*DIMC)   // 262144
#define W_X_SZ  (XDBLW*DI)    // 73728
#define W_O_SZ  (DIMC*DI)     // 131072

// ---------------------------------------------------------------------------
// Scratch (single __device__ array; no allocations anywhere)
// Offsets in float units; bf16 regions use 2 elems per float slot.
// ---------------------------------------------------------------------------
#define O_XC    ((size_t)0)                                // fp32 NTOK*DI
#define O_XDBL  (O_XC   + (size_t)NTOK*DI)                 // fp32 NTOK*XDBLW
#define O_X1    (O_XDBL + (size_t)NTOK*XDBLW)              // fp32 NTOK*DIMC
#define O_XN2   (O_X1   + (size_t)NTOK*DIMC)
#define O_FR    (O_XN2  + (size_t)NTOK*DIMC)
#define O_FI    (O_FR   + (size_t)NTOK*DIMC)
#define O_XZB   (O_FI   + (size_t)NTOK*DIMC)               // bf16 NTOK*2*DI
#define O_XNBF  (O_XZB  + (size_t)NTOK*DI)                 // bf16 NTOK*DIMC
#define O_XCBF  (O_XNBF + (size_t)NTOK*DIMC/2)             // bf16 NTOK*DI
#define O_YBF   (O_XCBF + (size_t)NTOK*DI/2)               // bf16 NTOK*DI
#define O_WBF   (O_YBF  + (size_t)NTOK*DI/2)               // bf16 weights
#define O_END   (O_WBF  + (size_t)(W_IN_SZ+W_X_SZ+W_O_SZ)/2 + 64)

__device__ float SCRATCH[O_END];

// ---------------------------------------------------------------------------
// cp.async helpers
// ---------------------------------------------------------------------------
__device__ __forceinline__ void cp16(unsigned dst, const void* src, int sz) {
    asm volatile("cp.async.cg.shared.global [%0], [%1], 16, %2;"
                 :: "r"(dst), "l"(src), "r"(sz));
}
__device__ __forceinline__ void cp_commit() {
    asm volatile("cp.async.commit_group;" ::: "memory");
}
template <int N>
__device__ __forceinline__ void cp_wait() {
    asm volatile("cp.async.wait_group %0;" :: "n"(N) : "memory");
}

// ---------------------------------------------------------------------------
// Weight fp32 -> bf16 convert (all three matrices, contiguous dest)
// ---------------------------------------------------------------------------
__global__ void wcvt_kernel(const float* __restrict__ w_in,
                            const float* __restrict__ w_x,
                            const float* __restrict__ w_o,
                            __nv_bfloat16* __restrict__ dst) {
    int total = W_IN_SZ + W_X_SZ + W_O_SZ;
    for (int i = blockIdx.x * 256 + threadIdx.x; i < total; i += gridDim.x * 256) {
        float v;
        if (i < W_IN_SZ) v = w_in[i];
        else if (i < W_IN_SZ + W_X_SZ) v = w_x[i - W_IN_SZ];
        else v = w_o[i - W_IN_SZ - W_X_SZ];
        dst[i] = __float2bfloat16_rn(v);
    }
}

// ---------------------------------------------------------------------------
// LayerNorm: one warp per token.  Writes fp32 (if out) and/or bf16 (if obf).
// ---------------------------------------------------------------------------
__global__ void ln_kernel(const float* __restrict__ x,
                          const float* __restrict__ w,
                          const float* __restrict__ b,
                          float* __restrict__ out,
                          __nv_bfloat16* __restrict__ obf) {
    int t = blockIdx.x * 8 + (threadIdx.x >> 5);
    int lane = threadIdx.x & 31;
    const float4* row = (const float4*)(x + (size_t)t * DIMC);
    float4 v0 = row[lane];
    float4 v1 = row[lane + 32];
    float s = v0.x + v0.y + v0.z + v0.w + v1.x + v1.y + v1.z + v1.w;
    #pragma unroll
    for (int off = 16; off; off >>= 1) s += __shfl_xor_sync(0xffffffffu, s, off);
    float m = s * (1.0f / 256.0f);
    float d0 = v0.x - m, d1 = v0.y - m, d2 = v0.z - m, d3 = v0.w - m;
    float d4 = v1.x - m, d5 = v1.y - m, d6 = v1.z - m, d7 = v1.w - m;
    float q = d0*d0 + d1*d1 + d2*d2 + d3*d3 + d4*d4 + d5*d5 + d6*d6 + d7*d7;
    #pragma unroll
    for (int off = 16; off; off >>= 1) q += __shfl_xor_sync(0xffffffffu, q, off);
    float inv = rsqrtf(q * (1.0f / 256.0f) + 1e-5f);
    const float4* w4 = (const float4*)w;
    const float4* b4 = (const float4*)b;
    float4 wa = w4[lane], ba = b4[lane];
    float4 wb = w4[lane + 32], bb = b4[lane + 32];
    float4 r0, r1;
    r0.x = d0*inv*wa.x + ba.x; r0.y = d1*inv*wa.y + ba.y;
    r0.z = d2*inv*wa.z + ba.z; r0.w = d3*inv*wa.w + ba.w;
    r1.x = d4*inv*wb.x + bb.x; r1.y = d5*inv*wb.y + bb.y;
    r1.z = d6*inv*wb.z + bb.z; r1.w = d7*inv*wb.w + bb.w;
    if (out) {
        float4* o4 = (float4*)(out + (size_t)t * DIMC);
        o4[lane] = r0; o4[lane + 32] = r1;
    }
    if (obf) {
        __nv_bfloat162* o2 = (__nv_bfloat162*)(obf + (size_t)t * DIMC);
        o2[lane*2]      = __nv_bfloat162(__float2bfloat16_rn(r0.x), __float2bfloat16_rn(r0.y));
        o2[lane*2 + 1]  = __nv_bfloat162(__float2bfloat16_rn(r0.z), __float2bfloat16_rn(r0.w));
        o2[64 + lane*2]     = __nv_bfloat162(__float2bfloat16_rn(r1.x), __float2bfloat16_rn(r1.y));
        o2[64 + lane*2 + 1] = __nv_bfloat162(__float2bfloat16_rn(r1.z), __float2bfloat16_rn(r1.w));
    }
}

// ---------------------------------------------------------------------------
// bf16 tensor-core GEMM: out = A[M,K] * W[N,K]^T (+ R).  Output fp32 (C) or
// bf16 (Cbf) -- exactly one of C/Cbf non-null.
// 128x64 tile, BK=32, 8 warps, warp tile 32x32 via 2x4 m16n8k16.
// ---------------------------------------------------------------------------
#define GBM 128
#define GBN 64
#define BK  32
#define HSTR 40
#define GSTAGES 4
#define GEMM_SMEM (GSTAGES * (GBM + GBN) * HSTR * 2)

__device__ __forceinline__ void mma_bf16(float* c, const unsigned* a, const unsigned* b) {
    asm volatile(
        "mma.sync.aligned.m16n8k16.row.col.f32.bf16.bf16.f32 "
        "{%0,%1,%2,%3}, {%4,%5,%6,%7}, {%8,%9}, {%0,%1,%2,%3};"
        : "+f"(c[0]), "+f"(c[1]), "+f"(c[2]), "+f"(c[3])
        : "r"(a[0]), "r"(a[1]), "r"(a[2]), "r"(a[3]), "r"(b[0]), "r"(b[1]));
}

__global__ void __launch_bounds__(256) gemm_bf16(const __nv_bfloat16* __restrict__ A,
                                                 const __nv_bfloat16* __restrict__ W,
                                                 const float* __restrict__ R,
                                                 float* __restrict__ C,
                                                 __nv_bfloat16* __restrict__ Cbf,
                                                 int M, int N, int K) {
    extern __shared__ __nv_bfloat16 hsm[];
    __nv_bfloat16* As = hsm;
    __nv_bfloat16* Bs = hsm + GSTAGES * GBM * HSTR;
    unsigned smA = (unsigned)__cvta_generic_to_shared(As);
    unsigned smB = (unsigned)__cvta_generic_to_shared(Bs);

    int m0 = blockIdx.y * GBM;
    int n0 = blockIdx.x * GBN;
    int tid = threadIdx.x;
    int wid = tid >> 5, lane = tid & 31;
    int wm = (wid & 3) * 32;
    int wn = (wid >> 2) * 32;
    int gid = lane >> 2;
    int tig = lane & 3;
    int ar = tid >> 1, akq = (tid & 1) * 16;
    int br = tid >> 2, bkq = (tid & 3) * 8;

    const __nv_bfloat16* Abase = A + (size_t)(m0 + ar) * K + akq;
    bool bok = (n0 + br) < N;
    const __nv_bfloat16* Bbase = bok ? (W + (size_t)(n0 + br) * K + bkq) : W;
    int bsz = bok ? 16 : 0;
    unsigned adst = smA + (unsigned)(ar * HSTR + akq) * 2u;
    unsigned bdst = smB + (unsigned)(br * HSTR + bkq) * 2u;
    const unsigned aStage = GBM * HSTR * 2u;
    const unsigned bStage = GBN * HSTR * 2u;

    float acc[2][4][4];
    #pragma unroll
    for (int mi = 0; mi < 2; mi++)
        #pragma unroll
        for (int ni = 0; ni < 4; ni++)
            #pragma unroll
            for (int q = 0; q < 4; q++) acc[mi][ni][q] = 0.0f;

    int nIt = K / BK;
    #pragma unroll
    for (int s = 0; s < GSTAGES - 1; s++) {
        cp16(adst + s * aStage,      Abase + s * BK,     16);
        cp16(adst + s * aStage + 16, Abase + s * BK + 8, 16);
        cp16(bdst + s * bStage,      Bbase + (bok ? s * BK : 0), bsz);
        cp_commit();
    }

    for (int it = 0; it < nIt; it++) {
        cp_wait<GSTAGES - 2>();
        __syncthreads();
        int buf = it & (GSTAGES - 1);
        const __nv_bfloat16* Ab = As + buf * (GBM * HSTR);
        const __nv_bfloat16* Bb = Bs + buf * (GBN * HSTR);
        #pragma unroll
        for (int ks = 0; ks < 2; ks++) {
            int k16 = ks * 16;
            unsigned afr[2][4], bfr[4][2];
            #pragma unroll
            for (int mi = 0; mi < 2; mi++) {
                int rb = wm + mi * 16 + gid;
                afr[mi][0] = *(const unsigned*)(Ab + (rb)     * HSTR + k16 + tig * 2);
                afr[mi][1] = *(const unsigned*)(Ab + (rb + 8) * HSTR + k16 + tig * 2);
                afr[mi][2] = *(const unsigned*)(Ab + (rb)     * HSTR + k16 + tig * 2 + 8);
                afr[mi][3] = *(const unsigned*)(Ab + (rb + 8) * HSTR + k16 + tig * 2 + 8);
            }
            #pragma unroll
            for (int ni = 0; ni < 4; ni++) {
                int cb = wn + ni * 8 + gid;
                bfr[ni][0] = *(const unsigned*)(Bb + cb * HSTR + k16 + tig * 2);
                bfr[ni][1] = *(const unsigned*)(Bb + cb * HSTR + k16 + tig * 2 + 8);
            }
            #pragma unroll
            for (int mi = 0; mi < 2; mi++)
                #pragma unroll
                for (int ni = 0; ni < 4; ni++)
                    mma_bf16(acc[mi][ni], afr[mi], bfr[ni]);
        }
        int nx = it + GSTAGES - 1;
        if (nx < nIt) {
            int slot = nx & (GSTAGES - 1);
            cp16(adst + slot * aStage,      Abase + nx * BK,     16);
            cp16(adst + slot * aStage + 16, Abase + nx * BK + 8, 16);
            cp16(bdst + slot * bStage,      Bbase + (bok ? nx * BK : 0), bsz);
        }
        cp_commit();
    }

    #pragma unroll
    for (int mi = 0; mi < 2; mi++) {
        int row = m0 + wm + mi * 16 + gid;
        #pragma unroll
        for (int ni = 0; ni < 4; ni++) {
            int col = n0 + wn + ni * 8 + tig * 2;
            #pragma unroll
            for (int half = 0; half < 2; half++) {
                int rr = row + half * 8;
                float v0 = acc[mi][ni][half * 2];
                float v1 = acc[mi][ni][half * 2 + 1];
                if (col < N) {
                    if (Cbf) Cbf[(size_t)rr * N + col] = __float2bfloat16_rn(v0);
                    else {
                        if (R) v0 += R[(size_t)rr * N + col];
                        C[(size_t)rr * N + col] = v0;
                    }
                }
                if (col + 1 < N) {
                    if (Cbf) Cbf[(size_t)rr * N + col + 1] = __float2bfloat16_rn(v1);
                    else {
                        if (R) v1 += R[(size_t)rr * N + col + 1];
                        C[(size_t)rr * N + col + 1] = v1;
                    }
                }
            }
        }
    }
}

// ---------------------------------------------------------------------------
// Depthwise causal conv (k=4) + bias + SiLU, bf16 input xz.
// Writes fp32 xc and bf16 xc_bf.
// ---------------------------------------------------------------------------
__global__ void conv_silu_kernel(const __nv_bfloat16* __restrict__ xzb,
                                 const float* __restrict__ cw,
                                 const float* __restrict__ cb,
                                 float* __restrict__ xc,
                                 __nv_bfloat16* __restrict__ xc_bf) {
    int idx = blockIdx.x * 256 + threadIdx.x;
    int d = idx & (DI - 1);
    int bt = idx >> 9;
    int b = bt >> 11;
    int l = bt & (LSEQ - 1);
    float acc = cb[d];
    #pragma unroll
    for (int k = 0; k < 4; k++) {
        int ls = l + k - 3;
        if (ls >= 0)
            acc += __bfloat162float(xzb[((size_t)((b << 11) | ls)) * (2 * DI) + d])
                   * cw[d * 4 + k];
    }
    float sg = 1.0f / (1.0f + __expf(-acc));
    float v = acc * sg;
    xc[(size_t)bt * DI + d] = v;
    xc_bf[(size_t)bt * DI + d] = __float2bfloat16_rn(v);
}

// ---------------------------------------------------------------------------
// Selective scan with fused dt; deferred reduce-scatter; cp.async
// double-buffered staging (full 144-float xdbl row staged contiguously).
// ---------------------------------------------------------------------------
#define TCHUNK 64
#define SXW 148
// dynamic smem layout (floats): sX[2][64][SXW], sxc[2][64][8], sdt[64][8],
// sy[64][8], sw[8][16], sbias[8], then bf16 szb[2][64][8]
#define SCAN_F (2*64*SXW + 2*64*8 + 512 + 512 + 128 + 8)
#define SCAN_SMEM (SCAN_F * 4 + 2*64*8*2)

__global__ void __launch_bounds__(256) scan_kernel(
        const float* __restrict__ xdbl,
        const float* __restrict__ xc,
        const __nv_bfloat16* __restrict__ xzb,
        const float* __restrict__ A_log,
        const float* __restrict__ Dvec,
        const float* __restrict__ dtw,
        const float* __restrict__ dtb,
        __nv_bfloat16* __restrict__ y_bf) {
    extern __shared__ float ssm[];
    float* sX   = ssm;                      // [2][64][SXW]
    float* sxcc = sX + 2 * 64 * SXW;        // [2][64][8]
    float* sdt  = sxcc + 2 * 64 * 8;        // [64][8]
    float* sy   = sdt + 512;                // [64][8]
    float* sw   = sy + 512;                 // [8][16]
    float* sbias= sw + 128;                 // [8]
    __nv_bfloat16* szb = (__nv_bfloat16*)(sbias + 8);  // [2][64][8]
    unsigned aX  = (unsigned)__cvta_generic_to_shared(sX);
    unsigned aXC = (unsigned)__cvta_generic_to_shared(sxcc);
    unsigned aZ  = (unsigned)__cvta_generic_to_shared(szb);

    int b = blockIdx.x >> 6;
    int dbase = (blockIdx.x & 63) * 8;
    int wid = threadIdx.x >> 5;
    int lane = threadIdx.x & 31;
    int d = dbase + wid;
    int tid = threadIdx.x;

    if (tid < 128) {
        int di = tid >> 4, r = tid & 15;
        sw[di * 16 + r] = dtw[(dbase + di) * DTR + r];
        if (r == 0) sbias[di] = dtb[dbase + di];
    }
    float A0 = -__expf(A_log[d * DS + lane]);
    float A1 = -__expf(A_log[d * DS + lane + 32]);
    float Dd = Dvec[d];
    float h0 = 0.0f, h1 = 0.0f;

    // stage chunk macro-equivalent lambda
    auto stage = [&](int buf, int t0) {
        size_t rowbase = (size_t)(b * LSEQ + t0);
        for (int i = tid; i < 64 * 36; i += 256) {
            int tt = i / 36, q = i - tt * 36;
            cp16(aX + (unsigned)(((buf * 64 + tt) * SXW) + q * 4) * 4u,
                 xdbl + (rowbase + tt) * XDBLW + q * 4, 16);
        }
        for (int i = tid; i < 128; i += 256) {
            int tt = i >> 1, hf = i & 1;
            cp16(aXC + (unsigned)(((buf * 64 + tt) * 8) + hf * 4) * 4u,
                 xc + (rowbase + tt) * DI + dbase + hf * 4, 16);
        }
        if (tid < 64) {
            cp16(aZ + (unsigned)((buf * 64 + tid) * 8) * 2u,
                 xzb + (rowbase + tid) * (2 * DI) + DI + dbase, 16);
        }
    };

    stage(0, 0);
    cp_commit();

    for (int c = 0; c < LSEQ / TCHUNK; c++) {
        int buf = c & 1;
        cp_wait<0>();
        __syncthreads();
        if (c + 1 < LSEQ / TCHUNK) stage(buf ^ 1, (c + 1) * TCHUNK);
        cp_commit();

        // dt = softplus(x16 . w + b)
        for (int i = tid; i < 512; i += 256) {
            int tt = i >> 3, di = i & 7;
            const float* xr = sX + (buf * 64 + tt) * SXW;
            float acc = sbias[di];
            #pragma unroll
            for (int r = 0; r < 16; r++) acc = fmaf(xr[r], sw[di * 16 + r], acc);
            sdt[tt * 8 + di] = (acc > 20.0f) ? acc : __logf(1.0f + __expf(acc));
        }
        __syncthreads();

        #pragma unroll 1
        for (int g = 0; g < TCHUNK / 32; g++) {
            float part[32];
            #pragma unroll
            for (int j = 0; j < 32; j++) {
                int tt = g * 32 + j;
                const float* xr = sX + (buf * 64 + tt) * SXW;
                float dtv = sdt[tt * 8 + wid];
                float xcv = sxcc[(buf * 64 + tt) * 8 + wid];
                float du = dtv * xcv;
                float dA0 = __expf(dtv * A0);
                float dA1 = __expf(dtv * A1);
                h0 = fmaf(dA0, h0, du * xr[16 + lane]);
                h1 = fmaf(dA1, h1, du * xr[48 + lane]);
                part[j] = fmaf(h0, xr[80 + lane], h1 * xr[112 + lane]);
            }
            #pragma unroll
            for (int s = 16; s >= 1; s >>= 1) {
                bool up = (lane & s) != 0;
                #pragma unroll
                for (int i2 = 0; i2 < 16; i2++) {
                    if (i2 >= s) break;
                    float keep = up ? part[i2 + s] : part[i2];
                    float send = up ? part[i2] : part[i2 + s];
                    part[i2] = keep + __shfl_xor_sync(0xffffffffu, send, s);
                }
            }
            int tt = g * 32 + lane;
            float dtv = sdt[tt * 8 + wid];
            float xcv = sxcc[(buf * 64 + tt) * 8 + wid];
            float zv = __bfloat162float(szb[(buf * 64 + tt) * 8 + wid]);
            float gate = zv / (1.0f + __expf(-zv));
            sy[tt * 8 + wid] = fmaf(xcv, Dd, part[0]) * gate;
            (void)dtv;
        }
        __syncthreads();
        for (int i = tid; i < TCHUNK * 8; i += 256) {
            int tt = i >> 3, di = i & 7;
            y_bf[(size_t)(b * LSEQ + c * TCHUNK + tt) * DI + dbase + di] =
                __float2bfloat16_rn(sy[tt * 8 + di]);
        }
        __syncthreads();
    }
}

// ---------------------------------------------------------------------------
// Forward 2048-pt FFT (DIF), real input.  4 ch/block, float4 I/O.
// ---------------------------------------------------------------------------
#define FSTR 2049
#define FFT_SMEM (2 * 4 * FSTR * 4)

__global__ void __launch_bounds__(512) fft_fwd_kernel(const float* __restrict__ xin,
                                                      float* __restrict__ dR,
                                                      float* __restrict__ dI) {
    extern __shared__ float sm[];
    float* sr = sm;
    float* si = sm + 4 * FSTR;
    int b = blockIdx.x >> 6;
    int c0 = (blockIdx.x & 63) * 4;
    size_t base = (size_t)b * LSEQ * DIMC + c0;
    int tid = threadIdx.x;

    for (int n = tid; n < 2048; n += 512) {
        float4 v = *(const float4*)(xin + base + (size_t)n * DIMC);
        sr[0 * FSTR + n] = v.x; sr[1 * FSTR + n] = v.y;
        sr[2 * FSTR + n] = v.z; sr[3 * FSTR + n] = v.w;
        si[0 * FSTR + n] = 0.0f; si[1 * FSTR + n] = 0.0f;
        si[2 * FSTR + n] = 0.0f; si[3 * FSTR + n] = 0.0f;
    }
    __syncthreads();

    #pragma unroll
    for (int hb = 10; hb >= 0; hb--) {
        int half = 1 << hb;
        float th = -PI_F / (float)half;
        for (int e = tid; e < 4096; e += 512) {
            int col = e >> 10, idx = e & 1023;
            int j = idx & (half - 1);
            int pos = ((idx >> hb) << (hb + 1)) + j;
            float* cr = sr + col * FSTR;
            float* ci = si + col * FSTR;
            float ar = cr[pos],        ai = ci[pos];
            float br = cr[pos + half], bi = ci[pos + half];
            float wi, wr;
            __sincosf(th * (float)j, &wi, &wr);
            float xr = ar - br, xi = ai - bi;
            cr[pos] = ar + br;  ci[pos] = ai + bi;
            cr[pos + half] = xr * wr - xi * wi;
            ci[pos + half] = xr * wi + xi * wr;
        }
        __syncthreads();
    }

    for (int n = tid; n < 2048; n += 512) {
        float4 vr, vi;
        vr.x = sr[0 * FSTR + n]; vr.y = sr[1 * FSTR + n];
        vr.z = sr[2 * FSTR + n]; vr.w = sr[3 * FSTR + n];
        vi.x = si[0 * FSTR + n]; vi.y = si[1 * FSTR + n];
        vi.z = si[2 * FSTR + n]; vi.w = si[3 * FSTR + n];
        *(float4*)(dR + base + (size_t)n * DIMC) = vr;
        *(float4*)(dI + base + (size_t)n * DIMC) = vi;
    }
}

// ---------------------------------------------------------------------------
// Inverse 2048-pt FFT (DIT); real part + residual.
// ---------------------------------------------------------------------------
__global__ void __launch_bounds__(512) fft_inv_kernel(const float* __restrict__ dR,
                                                      const float* __restrict__ dI,
                                                      const float* __restrict__ x1,
                                                      float* __restrict__ out) {
    extern __shared__ float sm[];
    float* sr = sm;
    float* si = sm + 4 * FSTR;
    int b = blockIdx.x >> 6;
    int c0 = (blockIdx.x & 63) * 4;
    size_t base = (size_t)b * LSEQ * DIMC + c0;
    int tid = threadIdx.x;

    for (int n = tid; n < 2048; n += 512) {
        float4 vr = *(const float4*)(dR + base + (size_t)n * DIMC);
        float4 vi = *(const float4*)(dI + base + (size_t)n * DIMC);
        sr[0 * FSTR + n] = vr.x; sr[1 * FSTR + n] = vr.y;
        sr[2 * FSTR + n] = vr.z; sr[3 * FSTR + n] = vr.w;
        si[0 * FSTR + n] = vi.x; si[1 * FSTR + n] = vi.y;
        si[2 * FSTR + n] = vi.z; si[3 * FSTR + n] = vi.w;
    }
    __syncthreads();

    #pragma unroll
    for (int hb = 0; hb <= 10; hb++) {
        int half = 1 << hb;
        float th = PI_F / (float)half;
        for (int e = tid; e < 4096; e += 512) {
            int col = e >> 10, idx = e & 1023;
            int j = idx & (half - 1);
            int pos = ((idx >> hb) << (hb + 1)) + j;
            float* cr = sr + col * FSTR;
            float* ci = si + col * FSTR;
            float ar = cr[pos],        ai = ci[pos];
            float br = cr[pos + half], bi = ci[pos + half];
            float wi, wr;
            __sincosf(th * (float)j, &wi, &wr);
            float tr = br * wr - bi * wi;
            float ti = br * wi + bi * wr;
            cr[pos] = ar + tr;         ci[pos] = ai + ti;
            cr[pos + half] = ar - tr;  ci[pos + half] = ai - ti;
        }
        __syncthreads();
    }

    for (int n = tid; n < 2048; n += 512) {
        size_t a = base + (size_t)n * DIMC;
        float4 rx = *(const float4*)(x1 + a);
        float4 o;
        o.x = rx.x + sr[0 * FSTR + n];
        o.y = rx.y + sr[1 * FSTR + n];
        o.z = rx.z + sr[2 * FSTR + n];
        o.w = rx.w + sr[3 * FSTR + n];
        *(float4*)(out + a) = o;
    }
}

// ---------------------------------------------------------------------------
// EinFFT MLP with DFT4/IDFT4 folded in.
// ---------------------------------------------------------------------------
__global__ void __launch_bounds__(256) einfft_mlp_kernel(
        float* __restrict__ fR, float* __restrict__ fI,
        const float* __restrict__ cw1, const float* __restrict__ cb1,
        const float* __restrict__ cw2, const float* __restrict__ cb2) {
    __shared__ float sR[2048], sI[2048];
    __shared__ float tR[2048], tI[2048];
    int row0 = blockIdx.x * 8;
    int tid = threadIdx.x;
    for (int i = tid; i < 2048; i += 256) {
        sR[i] = fR[(size_t)row0 * DIMC + i];
        sI[i] = fI[(size_t)row0 * DIMC + i];
    }
    __syncthreads();

    const float sc = SQRT_INV_8192;
    #pragma unroll
    for (int g = tid; g < 512; g += 256) {
        int r = g >> 6, s = g & 63;
        int p = r * 256 + s;
        float r0 = sR[p],       i0 = sI[p];
        float r1 = sR[p + 64],  i1 = sI[p + 64];
        float r2 = sR[p + 128], i2 = sI[p + 128];
        float r3 = sR[p + 192], i3 = sI[p + 192];
        sR[p]       = (r0 + r1 + r2 + r3) * sc;
        sI[p]       = (i0 + i1 + i2 + i3) * sc;
        sR[p + 64]  = (r0 + i1 - r2 - i3) * sc;
        sI[p + 64]  = (i0 - r1 - i2 + r3) * sc;
        sR[p + 128] = (r0 - r1 + r2 - r3) * sc;
        sI[p + 128] = (i0 - i1 + i2 - i3) * sc;
        sR[p + 192] = (r0 - i1 - r2 + i3) * sc;
        sI[p + 192] = (i0 + r1 - i2 - r3) * sc;
    }
    __syncthreads();

    int k = tid >> 6, o = tid & 63;

    {
        const float* w0 = cw1 + k * 4096;
        const float* w1 = cw1 + 16384 + k * 4096;
        float bR = cb1[k * 64 + o];
        float bI = cb1[256 + k * 64 + o];
        float aR[8], aI[8];
        #pragma unroll
        for (int r = 0; r < 8; r++) { aR[r] = bR; aI[r] = bI; }
        #pragma unroll 4
        for (int dd = 0; dd < 64; dd++) {
            float wa = w0[dd * 64 + o];
            float wb = w1[dd * 64 + o];
            int sb = k * 64 + dd;
            #pragma unroll
            for (int r = 0; r < 8; r++) {
                float xr = sR[r * 256 + sb];
                float xi = sI[r * 256 + sb];
                aR[r] = fmaf(xr, wa, fmaf(-xi, wb, aR[r]));
                aI[r] = fmaf(xr, wb, fmaf( xi, wa, aI[r]));
            }
        }
        #pragma unroll
        for (int r = 0; r < 8; r++) {
            tR[r * 256 + tid] = fmaxf(aR[r], 0.0f);
            tI[r * 256 + tid] = fmaxf(aI[r], 0.0f);
        }
    }
    __syncthreads();

    {
        const float* w0 = cw2 + k * 4096;
        const float* w1 = cw2 + 16384 + k * 4096;
        float bR = cb2[k * 64 + o];
        float bI = cb2[256 + k * 64 + o];
        float aR[8], aI[8];
        #pragma unroll
        for (int r = 0; r < 8; r++) { aR[r] = bR; aI[r] = bI; }
        #pragma unroll 4
        for (int dd = 0; dd < 64; dd++) {
            float wa = w0[dd * 64 + o];
            float wb = w1[dd * 64 + o];
            int sb = k * 64 + dd;
            #pragma unroll
            for (int r = 0; r < 8; r++) {
                float xr = tR[r * 256 + sb];
                float xi = tI[r * 256 + sb];
                aR[r] = fmaf(xr, wa, fmaf(-xi, wb, aR[r]));
                aI[r] = fmaf(xr, wb, fmaf( xi, wa, aI[r]));
            }
        }
        #pragma unroll
        for (int r = 0; r < 8; r++) {
            float vR = aR[r], vI = aI[r];
            vR = (vR > LAMBDA_SS) ? vR - LAMBDA_SS
                 : ((vR < -LAMBDA_SS) ? vR + LAMBDA_SS : 0.0f);
            vI = (vI > LAMBDA_SS) ? vI - LAMBDA_SS
                 : ((vI < -LAMBDA_SS) ? vI + LAMBDA_SS : 0.0f);
            sR[r * 256 + tid] = vR;
            sI[r * 256 + tid] = vI;
        }
    }
    __syncthreads();

    #pragma unroll
    for (int g = tid; g < 512; g += 256) {
        int r = g >> 6, s = g & 63;
        int p = r * 256 + s;
        float R0 = sR[p],       I0 = sI[p];
        float R1 = sR[p + 64],  I1 = sI[p + 64];
        float R2 = sR[p + 128], I2 = sI[p + 128];
        float R3 = sR[p + 192], I3 = sI[p + 192];
        sR[p]       = (R0 + R1 + R2 + R3) * sc;
        sI[p]       = (I0 + I1 + I2 + I3) * sc;
        sR[p + 64]  = (R0 - I1 - R2 + I3) * sc;
        sI[p + 64]  = (I0 + R1 - I2 - R3) * sc;
        sR[p + 128] = (R0 - R1 + R2 - R3) * sc;
        sI[p + 128] = (I0 - I1 + I2 - I3) * sc;
        sR[p + 192] = (R0 + I1 - R2 - I3) * sc;
        sI[p + 192] = (I0 - R1 - I2 + R3) * sc;
    }
    __syncthreads();

    for (int i = tid; i < 2048; i += 256) {
        fR[(size_t)row0 * DIMC + i] = sR[i];
        fI[(size_t)row0 * DIMC + i] = sI[i];
    }
}

// ---------------------------------------------------------------------------
// Launch
// ---------------------------------------------------------------------------
extern "C" void kernel_launch(void* const* d_in, const int* in_sizes, int n_in,
                              void* d_out, int out_size) {
    const float* x         = (const float*)d_in[0];
    const float* norm1_w   = (const float*)d_in[1];
    const float* norm1_b   = (const float*)d_in[2];
    const float* in_proj_w = (const float*)d_in[3];
    const float* conv_w    = (const float*)d_in[4];
    const float* conv_b    = (const float*)d_in[5];
    const float* x_proj_w  = (const float*)d_in[6];
    const float* dt_proj_w = (const float*)d_in[7];
    const float* dt_proj_b = (const float*)d_in[8];
    const float* A_log     = (const float*)d_in[9];
    const float* Dvec      = (const float*)d_in[10];
    const float* out_proj_w= (const float*)d_in[11];
    const float* norm2_w   = (const float*)d_in[12];
    const float* norm2_b   = (const float*)d_in[13];
    const float* cw1       = (const float*)d_in[14];
    const float* cb1       = (const float*)d_in[15];
    const float* cw2       = (const float*)d_in[16];
    const float* cb2       = (const float*)d_in[17];
    float* out = (float*)d_out;

    void* sp = nullptr;
    cudaGetSymbolAddress(&sp, SCRATCH);
    float* S = (float*)sp;
    float* s_xc   = S + O_XC;
    float* s_xdbl = S + O_XDBL;
    float* s_x1   = S + O_X1;
    float* s_xn2  = S + O_XN2;
    float* s_fr   = S + O_FR;
    float* s_fi   = S + O_FI;
    __nv_bfloat16* s_xzb  = (__nv_bfloat16*)(S + O_XZB);
    __nv_bfloat16* s_xnbf = (__nv_bfloat16*)(S + O_XNBF);
    __nv_bfloat16* s_xcbf = (__nv_bfloat16*)(S + O_XCBF);
    __nv_bfloat16* s_ybf  = (__nv_bfloat16*)(S + O_YBF);
    __nv_bfloat16* s_wbf  = (__nv_bfloat16*)(S + O_WBF);
    __nv_bfloat16* win_bf = s_wbf;
    __nv_bfloat16* wx_bf  = s_wbf + W_IN_SZ;
    __nv_bfloat16* wo_bf  = s_wbf + W_IN_SZ + W_X_SZ;

    static int attr_done = 0;
    if (!attr_done) {
        cudaFuncSetAttribute(fft_fwd_kernel,
                             cudaFuncAttributeMaxDynamicSharedMemorySize, FFT_SMEM);
        cudaFuncSetAttribute(fft_inv_kernel,
                             cudaFuncAttributeMaxDynamicSharedMemorySize, FFT_SMEM);
        cudaFuncSetAttribute(gemm_bf16,
                             cudaFuncAttributeMaxDynamicSharedMemorySize, GEMM_SMEM);
        cudaFuncSetAttribute(scan_kernel,
                             cudaFuncAttributeMaxDynamicSharedMemorySize, SCAN_SMEM);
        attr_done = 1;
    }

    // 0) convert weights fp32 -> bf16
    wcvt_kernel<<<296, 256>>>(in_proj_w, x_proj_w, out_proj_w, s_wbf);
    // 1) LN1 -> bf16 only
    ln_kernel<<<NTOK / 8, 256>>>(x, norm1_w, norm1_b, nullptr, s_xnbf);
    // 2) in_proj -> bf16 xz
    gemm_bf16<<<dim3((2 * DI) / GBN, NTOK / GBM), 256, GEMM_SMEM>>>(
        s_xnbf, win_bf, nullptr, nullptr, s_xzb, NTOK, 2 * DI, DIMC);
    // 3) conv + silu (bf16 in) -> fp32 xc + bf16 xcbf
    conv_silu_kernel<<<(NTOK * DI) / 256, 256>>>(s_xzb, conv_w, conv_b, s_xc, s_xcbf);
    // 4) x_proj -> fp32 xdbl
    gemm_bf16<<<dim3((XDBLW + GBN - 1) / GBN, NTOK / GBM), 256, GEMM_SMEM>>>(
        s_xcbf, wx_bf, nullptr, s_xdbl, nullptr, NTOK, XDBLW, DI);
    // 5) selective scan (cp.async double-buffered) -> bf16 y
    scan_kernel<<<BATCH * (DI / 8), 256, SCAN_SMEM>>>(
        s_xdbl, s_xc, s_xzb, A_log, Dvec, dt_proj_w, dt_proj_b, s_ybf);
    // 6) out_proj + residual -> fp32 x1
    gemm_bf16<<<dim3(DIMC / GBN, NTOK / GBM), 256, GEMM_SMEM>>>(
        s_ybf, wo_bf, x, s_x1, nullptr, NTOK, DIMC, DI);
    // 7) LN2 -> fp32
    ln_kernel<<<NTOK / 8, 256>>>(s_x1, norm2_w, norm2_b, s_xn2, nullptr);
    // 8) forward FFT
    fft_fwd_kernel<<<128, 512, FFT_SMEM>>>(s_xn2, s_fr, s_fi);
    // 9) fused EinFFT MLP
    einfft_mlp_kernel<<<NTOK / 8, 256>>>(s_fr, s_fi, cw1, cb1, cw2, cb2);
    // 10) inverse FFT + residual -> out
    fft_inv_kernel<<<128, 512, FFT_SMEM>>>(s_fr, s_fi, s_x1, out);
}

// round 13
// speedup vs baseline: 1.5957x; 1.0072x over previous
#include <cuda_runtime.h>
#include <cuda_bf16.h>
#include <stdint.h>
#include <math.h>

// ---------------------------------------------------------------------------
// Problem constants
// ---------------------------------------------------------------------------
#define BATCH   2
#define LSEQ    2048
#define DIMC    256
#define DI      512          // d_inner
#define DS      64           // d_state
#define DTR     16           // dt_rank
#define XDBLW   144          // dt_rank + 2*d_state
#define NTOK    (BATCH*LSEQ) // 4096
#define SQRT_INV_8192 0.011048543456039806f
#define LAMBDA_SS 0.01f
#define PI_F 3.14159265358979323846f

// weight sizes (elems)
#define W_IN_SZ (2*DI*DIMC)   // 262144
#define W_X_SZ  (XDBLW*DI)    // 73728
#define W_O_SZ  (DIMC*DI)     // 131072

// ---------------------------------------------------------------------------
// Scratch (single __device__ array; no allocations anywhere)
// ---------------------------------------------------------------------------
#define O_XC    ((size_t)0)                                // fp32 NTOK*DI
#define O_XDBL  (O_XC   + (size_t)NTOK*DI)                 // fp32 NTOK*XDBLW
#define O_X1    (O_XDBL + (size_t)NTOK*XDBLW)              // fp32 NTOK*DIMC
#define O_XN2   (O_X1   + (size_t)NTOK*DIMC)
#define O_FR    (O_XN2  + (size_t)NTOK*DIMC)
#define O_FI    (O_FR   + (size_t)NTOK*DIMC)
#define O_XZB   (O_FI   + (size_t)NTOK*DIMC)               // bf16 NTOK*2*DI
#define O_XNBF  (O_XZB  + (size_t)NTOK*DI)                 // bf16 NTOK*DIMC
#define O_XCBF  (O_XNBF + (size_t)NTOK*DIMC/2)             // bf16 NTOK*DI
#define O_YBF   (O_XCBF + (size_t)NTOK*DI/2)               // bf16 NTOK*DI
#define O_WBF   (O_YBF  + (size_t)NTOK*DI/2)               // bf16 weights
#define O_END   (O_WBF  + (size_t)(W_IN_SZ+W_X_SZ+W_O_SZ)/2 + 64)

__device__ float SCRATCH[O_END];

// ---------------------------------------------------------------------------
// cp.async helpers
// ---------------------------------------------------------------------------
__device__ __forceinline__ void cp16(unsigned dst, const void* src, int sz) {
    asm volatile("cp.async.cg.shared.global [%0], [%1], 16, %2;"
                 :: "r"(dst), "l"(src), "r"(sz));
}
__device__ __forceinline__ void cp_commit() {
    asm volatile("cp.async.commit_group;" ::: "memory");
}
template <int N>
__device__ __forceinline__ void cp_wait() {
    asm volatile("cp.async.wait_group %0;" :: "n"(N) : "memory");
}

// ---------------------------------------------------------------------------
// Weight fp32 -> bf16 convert
// ---------------------------------------------------------------------------
__global__ void wcvt_kernel(const float* __restrict__ w_in,
                            const float* __restrict__ w_x,
                            const float* __restrict__ w_o,
                            __nv_bfloat16* __restrict__ dst) {
    int total = W_IN_SZ + W_X_SZ + W_O_SZ;
    for (int i = blockIdx.x * 256 + threadIdx.x; i < total; i += gridDim.x * 256) {
        float v;
        if (i < W_IN_SZ) v = w_in[i];
        else if (i < W_IN_SZ + W_X_SZ) v = w_x[i - W_IN_SZ];
        else v = w_o[i - W_IN_SZ - W_X_SZ];
        dst[i] = __float2bfloat16_rn(v);
    }
}

// ---------------------------------------------------------------------------
// LayerNorm: one warp per token.  Writes fp32 (if out) and/or bf16 (if obf).
// ---------------------------------------------------------------------------
__global__ void ln_kernel(const float* __restrict__ x,
                          const float* __restrict__ w,
                          const float* __restrict__ b,
                          float* __restrict__ out,
                          __nv_bfloat16* __restrict__ obf) {
    int t = blockIdx.x * 8 + (threadIdx.x >> 5);
    int lane = threadIdx.x & 31;
    const float4* row = (const float4*)(x + (size_t)t * DIMC);
    float4 v0 = row[lane];
    float4 v1 = row[lane + 32];
    float s = v0.x + v0.y + v0.z + v0.w + v1.x + v1.y + v1.z + v1.w;
    #pragma unroll
    for (int off = 16; off; off >>= 1) s += __shfl_xor_sync(0xffffffffu, s, off);
    float m = s * (1.0f / 256.0f);
    float d0 = v0.x - m, d1 = v0.y - m, d2 = v0.z - m, d3 = v0.w - m;
    float d4 = v1.x - m, d5 = v1.y - m, d6 = v1.z - m, d7 = v1.w - m;
    float q = d0*d0 + d1*d1 + d2*d2 + d3*d3 + d4*d4 + d5*d5 + d6*d6 + d7*d7;
    #pragma unroll
    for (int off = 16; off; off >>= 1) q += __shfl_xor_sync(0xffffffffu, q, off);
    float inv = rsqrtf(q * (1.0f / 256.0f) + 1e-5f);
    const float4* w4 = (const float4*)w;
    const float4* b4 = (const float4*)b;
    float4 wa = w4[lane], ba = b4[lane];
    float4 wb = w4[lane + 32], bb = b4[lane + 32];
    float4 r0, r1;
    r0.x = d0*inv*wa.x + ba.x; r0.y = d1*inv*wa.y + ba.y;
    r0.z = d2*inv*wa.z + ba.z; r0.w = d3*inv*wa.w + ba.w;
    r1.x = d4*inv*wb.x + bb.x; r1.y = d5*inv*wb.y + bb.y;
    r1.z = d6*inv*wb.z + bb.z; r1.w = d7*inv*wb.w + bb.w;
    if (out) {
        float4* o4 = (float4*)(out + (size_t)t * DIMC);
        o4[lane] = r0; o4[lane + 32] = r1;
    }
    if (obf) {
        __nv_bfloat162* o2 = (__nv_bfloat162*)(obf + (size_t)t * DIMC);
        o2[lane*2]      = __nv_bfloat162(__float2bfloat16_rn(r0.x), __float2bfloat16_rn(r0.y));
        o2[lane*2 + 1]  = __nv_bfloat162(__float2bfloat16_rn(r0.z), __float2bfloat16_rn(r0.w));
        o2[64 + lane*2]     = __nv_bfloat162(__float2bfloat16_rn(r1.x), __float2bfloat16_rn(r1.y));
        o2[64 + lane*2 + 1] = __nv_bfloat162(__float2bfloat16_rn(r1.z), __float2bfloat16_rn(r1.w));
    }
}

// ---------------------------------------------------------------------------
// bf16 tensor-core GEMM: out = A[M,K] * W[N,K]^T (+ R).  Output fp32 or bf16.
// 128x64 tile, BK=32, 8 warps, warp tile 32x32 via 2x4 m16n8k16.
// ---------------------------------------------------------------------------
#define GBM 128
#define GBN 64
#define BK  32
#define HSTR 40
#define GSTAGES 4
#define GEMM_SMEM (GSTAGES * (GBM + GBN) * HSTR * 2)

__device__ __forceinline__ void mma_bf16(float* c, const unsigned* a, const unsigned* b) {
    asm volatile(
        "mma.sync.aligned.m16n8k16.row.col.f32.bf16.bf16.f32 "
        "{%0,%1,%2,%3}, {%4,%5,%6,%7}, {%8,%9}, {%0,%1,%2,%3};"
        : "+f"(c[0]), "+f"(c[1]), "+f"(c[2]), "+f"(c[3])
        : "r"(a[0]), "r"(a[1]), "r"(a[2]), "r"(a[3]), "r"(b[0]), "r"(b[1]));
}

__global__ void __launch_bounds__(256) gemm_bf16(const __nv_bfloat16* __restrict__ A,
                                                 const __nv_bfloat16* __restrict__ W,
                                                 const float* __restrict__ R,
                                                 float* __restrict__ C,
                                                 __nv_bfloat16* __restrict__ Cbf,
                                                 int M, int N, int K) {
    extern __shared__ __nv_bfloat16 hsm[];
    __nv_bfloat16* As = hsm;
    __nv_bfloat16* Bs = hsm + GSTAGES * GBM * HSTR;
    unsigned smA = (unsigned)__cvta_generic_to_shared(As);
    unsigned smB = (unsigned)__cvta_generic_to_shared(Bs);

    int m0 = blockIdx.y * GBM;
    int n0 = blockIdx.x * GBN;
    int tid = threadIdx.x;
    int wid = tid >> 5, lane = tid & 31;
    int wm = (wid & 3) * 32;
    int wn = (wid >> 2) * 32;
    int gid = lane >> 2;
    int tig = lane & 3;
    int ar = tid >> 1, akq = (tid & 1) * 16;
    int br = tid >> 2, bkq = (tid & 3) * 8;

    const __nv_bfloat16* Abase = A + (size_t)(m0 + ar) * K + akq;
    bool bok = (n0 + br) < N;
    const __nv_bfloat16* Bbase = bok ? (W + (size_t)(n0 + br) * K + bkq) : W;
    int bsz = bok ? 16 : 0;
    unsigned adst = smA + (unsigned)(ar * HSTR + akq) * 2u;
    unsigned bdst = smB + (unsigned)(br * HSTR + bkq) * 2u;
    const unsigned aStage = GBM * HSTR * 2u;
    const unsigned bStage = GBN * HSTR * 2u;

    float acc[2][4][4];
    #pragma unroll
    for (int mi = 0; mi < 2; mi++)
        #pragma unroll
        for (int ni = 0; ni < 4; ni++)
            #pragma unroll
            for (int q = 0; q < 4; q++) acc[mi][ni][q] = 0.0f;

    int nIt = K / BK;
    #pragma unroll
    for (int s = 0; s < GSTAGES - 1; s++) {
        cp16(adst + s * aStage,      Abase + s * BK,     16);
        cp16(adst + s * aStage + 16, Abase + s * BK + 8, 16);
        cp16(bdst + s * bStage,      Bbase + (bok ? s * BK : 0), bsz);
        cp_commit();
    }

    for (int it = 0; it < nIt; it++) {
        cp_wait<GSTAGES - 2>();
        __syncthreads();
        int buf = it & (GSTAGES - 1);
        const __nv_bfloat16* Ab = As + buf * (GBM * HSTR);
        const __nv_bfloat16* Bb = Bs + buf * (GBN * HSTR);
        #pragma unroll
        for (int ks = 0; ks < 2; ks++) {
            int k16 = ks * 16;
            unsigned afr[2][4], bfr[4][2];
            #pragma unroll
            for (int mi = 0; mi < 2; mi++) {
                int rb = wm + mi * 16 + gid;
                afr[mi][0] = *(const unsigned*)(Ab + (rb)     * HSTR + k16 + tig * 2);
                afr[mi][1] = *(const unsigned*)(Ab + (rb + 8) * HSTR + k16 + tig * 2);
                afr[mi][2] = *(const unsigned*)(Ab + (rb)     * HSTR + k16 + tig * 2 + 8);
                afr[mi][3] = *(const unsigned*)(Ab + (rb + 8) * HSTR + k16 + tig * 2 + 8);
            }
            #pragma unroll
            for (int ni = 0; ni < 4; ni++) {
                int cb = wn + ni * 8 + gid;
                bfr[ni][0] = *(const unsigned*)(Bb + cb * HSTR + k16 + tig * 2);
                bfr[ni][1] = *(const unsigned*)(Bb + cb * HSTR + k16 + tig * 2 + 8);
            }
            #pragma unroll
            for (int mi = 0; mi < 2; mi++)
                #pragma unroll
                for (int ni = 0; ni < 4; ni++)
                    mma_bf16(acc[mi][ni], afr[mi], bfr[ni]);
        }
        int nx = it + GSTAGES - 1;
        if (nx < nIt) {
            int slot = nx & (GSTAGES - 1);
            cp16(adst + slot * aStage,      Abase + nx * BK,     16);
            cp16(adst + slot * aStage + 16, Abase + nx * BK + 8, 16);
            cp16(bdst + slot * bStage,      Bbase + (bok ? nx * BK : 0), bsz);
        }
        cp_commit();
    }

    #pragma unroll
    for (int mi = 0; mi < 2; mi++) {
        int row = m0 + wm + mi * 16 + gid;
        #pragma unroll
        for (int ni = 0; ni < 4; ni++) {
            int col = n0 + wn + ni * 8 + tig * 2;
            #pragma unroll
            for (int half = 0; half < 2; half++) {
                int rr = row + half * 8;
                float v0 = acc[mi][ni][half * 2];
                float v1 = acc[mi][ni][half * 2 + 1];
                if (col < N) {
                    if (Cbf) Cbf[(size_t)rr * N + col] = __float2bfloat16_rn(v0);
                    else {
                        if (R) v0 += R[(size_t)rr * N + col];
                        C[(size_t)rr * N + col] = v0;
                    }
                }
                if (col + 1 < N) {
                    if (Cbf) Cbf[(size_t)rr * N + col + 1] = __float2bfloat16_rn(v1);
                    else {
                        if (R) v1 += R[(size_t)rr * N + col + 1];
                        C[(size_t)rr * N + col + 1] = v1;
                    }
                }
            }
        }
    }
}

// ---------------------------------------------------------------------------
// Depthwise causal conv (k=4) + bias + SiLU, bf16 input, x2 vectorized.
// ---------------------------------------------------------------------------
__global__ void conv_silu_kernel(const __nv_bfloat16* __restrict__ xzb,
                                 const float* __restrict__ cw,
                                 const float* __restrict__ cb,
                                 float* __restrict__ xc,
                                 __nv_bfloat16* __restrict__ xc_bf) {
    int idx = blockIdx.x * 256 + threadIdx.x;   // NTOK*DI/2
    int dp = idx & (DI / 2 - 1);
    int bt = idx >> 8;
    int b = bt >> 11;
    int l = bt & (LSEQ - 1);
    int d0 = dp * 2;
    float acc0 = cb[d0], acc1 = cb[d0 + 1];
    #pragma unroll
    for (int k = 0; k < 4; k++) {
        int ls = l + k - 3;
        if (ls >= 0) {
            __nv_bfloat162 v = *(const __nv_bfloat162*)(
                xzb + ((size_t)((b << 11) | ls)) * (2 * DI) + d0);
            acc0 = fmaf(__bfloat162float(v.x), cw[d0 * 4 + k], acc0);
            acc1 = fmaf(__bfloat162float(v.y), cw[(d0 + 1) * 4 + k], acc1);
        }
    }
    float v0 = acc0 / (1.0f + __expf(-acc0));
    float v1 = acc1 / (1.0f + __expf(-acc1));
    *(float2*)(xc + (size_t)bt * DI + d0) = make_float2(v0, v1);
    *(__nv_bfloat162*)(xc_bf + (size_t)bt * DI + d0) =
        __nv_bfloat162(__float2bfloat16_rn(v0), __float2bfloat16_rn(v1));
}

// ---------------------------------------------------------------------------
// Selective scan with fused dt; deferred reduce-scatter; cp.async
// double-buffered staging.
// ---------------------------------------------------------------------------
#define TCHUNK 64
#define SXW 148
#define SCAN_F (2*64*SXW + 2*64*8 + 512 + 512 + 128 + 8)
#define SCAN_SMEM (SCAN_F * 4 + 2*64*8*2)

__global__ void __launch_bounds__(256) scan_kernel(
        const float* __restrict__ xdbl,
        const float* __restrict__ xc,
        const __nv_bfloat16* __restrict__ xzb,
        const float* __restrict__ A_log,
        const float* __restrict__ Dvec,
        const float* __restrict__ dtw,
        const float* __restrict__ dtb,
        __nv_bfloat16* __restrict__ y_bf) {
    extern __shared__ float ssm[];
    float* sX   = ssm;                      // [2][64][SXW]
    float* sxcc = sX + 2 * 64 * SXW;        // [2][64][8]
    float* sdt  = sxcc + 2 * 64 * 8;        // [64][8]
    float* sy   = sdt + 512;                // [64][8]
    float* sw   = sy + 512;                 // [8][16]
    float* sbias= sw + 128;                 // [8]
    __nv_bfloat16* szb = (__nv_bfloat16*)(sbias + 8);  // [2][64][8]
    unsigned aX  = (unsigned)__cvta_generic_to_shared(sX);
    unsigned aXC = (unsigned)__cvta_generic_to_shared(sxcc);
    unsigned aZ  = (unsigned)__cvta_generic_to_shared(szb);

    int b = blockIdx.x >> 6;
    int dbase = (blockIdx.x & 63) * 8;
    int wid = threadIdx.x >> 5;
    int lane = threadIdx.x & 31;
    int d = dbase + wid;
    int tid = threadIdx.x;

    if (tid < 128) {
        int di = tid >> 4, r = tid & 15;
        sw[di * 16 + r] = dtw[(dbase + di) * DTR + r];
        if (r == 0) sbias[di] = dtb[dbase + di];
    }
    float A0 = -__expf(A_log[d * DS + lane]);
    float A1 = -__expf(A_log[d * DS + lane + 32]);
    float Dd = Dvec[d];
    float h0 = 0.0f, h1 = 0.0f;

    auto stage = [&](int buf, int t0) {
        size_t rowbase = (size_t)(b * LSEQ + t0);
        for (int i = tid; i < 64 * 36; i += 256) {
            int tt = i / 36, q = i - tt * 36;
            cp16(aX + (unsigned)(((buf * 64 + tt) * SXW) + q * 4) * 4u,
                 xdbl + (rowbase + tt) * XDBLW + q * 4, 16);
        }
        for (int i = tid; i < 128; i += 256) {
            int tt = i >> 1, hf = i & 1;
            cp16(aXC + (unsigned)(((buf * 64 + tt) * 8) + hf * 4) * 4u,
                 xc + (rowbase + tt) * DI + dbase + hf * 4, 16);
        }
        if (tid < 64) {
            cp16(aZ + (unsigned)((buf * 64 + tid) * 8) * 2u,
                 xzb + (rowbase + tid) * (2 * DI) + DI + dbase, 16);
        }
    };

    stage(0, 0);
    cp_commit();

    for (int c = 0; c < LSEQ / TCHUNK; c++) {
        int buf = c & 1;
        cp_wait<0>();
        __syncthreads();
        if (c + 1 < LSEQ / TCHUNK) stage(buf ^ 1, (c + 1) * TCHUNK);
        cp_commit();

        for (int i = tid; i < 512; i += 256) {
            int tt = i >> 3, di = i & 7;
            const float* xr = sX + (buf * 64 + tt) * SXW;
            float acc = sbias[di];
            #pragma unroll
            for (int r = 0; r < 16; r++) acc = fmaf(xr[r], sw[di * 16 + r], acc);
            sdt[tt * 8 + di] = (acc > 20.0f) ? acc : __logf(1.0f + __expf(acc));
        }
        __syncthreads();

        #pragma unroll 1
        for (int g = 0; g < TCHUNK / 32; g++) {
            float part[32];
            #pragma unroll
            for (int j = 0; j < 32; j++) {
                int tt = g * 32 + j;
                const float* xr = sX + (buf * 64 + tt) * SXW;
                float dtv = sdt[tt * 8 + wid];
                float xcv = sxcc[(buf * 64 + tt) * 8 + wid];
                float du = dtv * xcv;
                float dA0 = __expf(dtv * A0);
                float dA1 = __expf(dtv * A1);
                h0 = fmaf(dA0, h0, du * xr[16 + lane]);
                h1 = fmaf(dA1, h1, du * xr[48 + lane]);
                part[j] = fmaf(h0, xr[80 + lane], h1 * xr[112 + lane]);
            }
            #pragma unroll
            for (int s = 16; s >= 1; s >>= 1) {
                bool up = (lane & s) != 0;
                #pragma unroll
                for (int i2 = 0; i2 < 16; i2++) {
                    if (i2 >= s) break;
                    float keep = up ? part[i2 + s] : part[i2];
                    float send = up ? part[i2] : part[i2 + s];
                    part[i2] = keep + __shfl_xor_sync(0xffffffffu, send, s);
                }
            }
            int tt = g * 32 + lane;
            float xcv = sxcc[(buf * 64 + tt) * 8 + wid];
            float zv = __bfloat162float(szb[(buf * 64 + tt) * 8 + wid]);
            float gate = zv / (1.0f + __expf(-zv));
            sy[tt * 8 + wid] = fmaf(xcv, Dd, part[0]) * gate;
        }
        __syncthreads();
        for (int i = tid; i < TCHUNK * 8; i += 256) {
            int tt = i >> 3, di = i & 7;
            y_bf[(size_t)(b * LSEQ + c * TCHUNK + tt) * DI + dbase + di] =
                __float2bfloat16_rn(sy[tt * 8 + di]);
        }
        __syncthreads();
    }
}

// ---------------------------------------------------------------------------
// Forward 2048-pt FFT (DIF), real input.  4 ch/block, float4 I/O.
// ---------------------------------------------------------------------------
#define FSTR 2049
#define FFT_SMEM (2 * 4 * FSTR * 4)

__global__ void __launch_bounds__(512) fft_fwd_kernel(const float* __restrict__ xin,
                                                      float* __restrict__ dR,
                                                      float* __restrict__ dI) {
    extern __shared__ float sm[];
    float* sr = sm;
    float* si = sm + 4 * FSTR;
    int b = blockIdx.x >> 6;
    int c0 = (blockIdx.x & 63) * 4;
    size_t base = (size_t)b * LSEQ * DIMC + c0;
    int tid = threadIdx.x;

    for (int n = tid; n < 2048; n += 512) {
        float4 v = *(const float4*)(xin + base + (size_t)n * DIMC);
        sr[0 * FSTR + n] = v.x; sr[1 * FSTR + n] = v.y;
        sr[2 * FSTR + n] = v.z; sr[3 * FSTR + n] = v.w;
        si[0 * FSTR + n] = 0.0f; si[1 * FSTR + n] = 0.0f;
        si[2 * FSTR + n] = 0.0f; si[3 * FSTR + n] = 0.0f;
    }
    __syncthreads();

    #pragma unroll
    for (int hb = 10; hb >= 0; hb--) {
        int half = 1 << hb;
        float th = -PI_F / (float)half;
        for (int e = tid; e < 4096; e += 512) {
            int col = e >> 10, idx = e & 1023;
            int j = idx & (half - 1);
            int pos = ((idx >> hb) << (hb + 1)) + j;
            float* cr = sr + col * FSTR;
            float* ci = si + col * FSTR;
            float ar = cr[pos],        ai = ci[pos];
            float br = cr[pos + half], bi = ci[pos + half];
            float wi, wr;
            __sincosf(th * (float)j, &wi, &wr);
            float xr = ar - br, xi = ai - bi;
            cr[pos] = ar + br;  ci[pos] = ai + bi;
            cr[pos + half] = xr * wr - xi * wi;
            ci[pos + half] = xr * wi + xi * wr;
        }
        __syncthreads();
    }

    for (int n = tid; n < 2048; n += 512) {
        float4 vr, vi;
        vr.x = sr[0 * FSTR + n]; vr.y = sr[1 * FSTR + n];
        vr.z = sr[2 * FSTR + n]; vr.w = sr[3 * FSTR + n];
        vi.x = si[0 * FSTR + n]; vi.y = si[1 * FSTR + n];
        vi.z = si[2 * FSTR + n]; vi.w = si[3 * FSTR + n];
        *(float4*)(dR + base + (size_t)n * DIMC) = vr;
        *(float4*)(dI + base + (size_t)n * DIMC) = vi;
    }
}

// ---------------------------------------------------------------------------
// Inverse 2048-pt FFT (DIT); real part + residual.
// ---------------------------------------------------------------------------
__global__ void __launch_bounds__(512) fft_inv_kernel(const float* __restrict__ dR,
                                                      const float* __restrict__ dI,
                                                      const float* __restrict__ x1,
                                                      float* __restrict__ out) {
    extern __shared__ float sm[];
    float* sr = sm;
    float* si = sm + 4 * FSTR;
    int b = blockIdx.x >> 6;
    int c0 = (blockIdx.x & 63) * 4;
    size_t base = (size_t)b * LSEQ * DIMC + c0;
    int tid = threadIdx.x;

    for (int n = tid; n < 2048; n += 512) {
        float4 vr = *(const float4*)(dR + base + (size_t)n * DIMC);
        float4 vi = *(const float4*)(dI + base + (size_t)n * DIMC);
        sr[0 * FSTR + n] = vr.x; sr[1 * FSTR + n] = vr.y;
        sr[2 * FSTR + n] = vr.z; sr[3 * FSTR + n] = vr.w;
        si[0 * FSTR + n] = vi.x; si[1 * FSTR + n] = vi.y;
        si[2 * FSTR + n] = vi.z; si[3 * FSTR + n] = vi.w;
    }
    __syncthreads();

    #pragma unroll
    for (int hb = 0; hb <= 10; hb++) {
        int half = 1 << hb;
        float th = PI_F / (float)half;
        for (int e = tid; e < 4096; e += 512) {
            int col = e >> 10, idx = e & 1023;
            int j = idx & (half - 1);
            int pos = ((idx >> hb) << (hb + 1)) + j;
            float* cr = sr + col * FSTR;
            float* ci = si + col * FSTR;
            float ar = cr[pos],        ai = ci[pos];
            float br = cr[pos + half], bi = ci[pos + half];
            float wi, wr;
            __sincosf(th * (float)j, &wi, &wr);
            float tr = br * wr - bi * wi;
            float ti = br * wi + bi * wr;
            cr[pos] = ar + tr;         ci[pos] = ai + ti;
            cr[pos + half] = ar - tr;  ci[pos + half] = ai - ti;
        }
        __syncthreads();
    }

    for (int n = tid; n < 2048; n += 512) {
        size_t a = base + (size_t)n * DIMC;
        float4 rx = *(const float4*)(x1 + a);
        float4 o;
        o.x = rx.x + sr[0 * FSTR + n];
        o.y = rx.y + sr[1 * FSTR + n];
        o.z = rx.z + sr[2 * FSTR + n];
        o.w = rx.w + sr[3 * FSTR + n];
        *(float4*)(out + a) = o;
    }
}

// ---------------------------------------------------------------------------
// EinFFT MLP with DFT4/IDFT4 folded in.  x loads vectorized over dd (LDS.128).
// ---------------------------------------------------------------------------
__global__ void __launch_bounds__(256) einfft_mlp_kernel(
        float* __restrict__ fR, float* __restrict__ fI,
        const float* __restrict__ cw1, const float* __restrict__ cb1,
        const float* __restrict__ cw2, const float* __restrict__ cb2) {
    __shared__ __align__(16) float sR[2048], sI[2048];
    __shared__ __align__(16) float tR[2048], tI[2048];
    int row0 = blockIdx.x * 8;
    int tid = threadIdx.x;
    for (int i = tid; i < 2048; i += 256) {
        sR[i] = fR[(size_t)row0 * DIMC + i];
        sI[i] = fI[(size_t)row0 * DIMC + i];
    }
    __syncthreads();

    const float sc = SQRT_INV_8192;
    #pragma unroll
    for (int g = tid; g < 512; g += 256) {
        int r = g >> 6, s = g & 63;
        int p = r * 256 + s;
        float r0 = sR[p],       i0 = sI[p];
        float r1 = sR[p + 64],  i1 = sI[p + 64];
        float r2 = sR[p + 128], i2 = sI[p + 128];
        float r3 = sR[p + 192], i3 = sI[p + 192];
        sR[p]       = (r0 + r1 + r2 + r3) * sc;
        sI[p]       = (i0 + i1 + i2 + i3) * sc;
        sR[p + 64]  = (r0 + i1 - r2 - i3) * sc;
        sI[p + 64]  = (i0 - r1 - i2 + r3) * sc;
        sR[p + 128] = (r0 - r1 + r2 - r3) * sc;
        sI[p + 128] = (i0 - i1 + i2 - i3) * sc;
        sR[p + 192] = (r0 - i1 - r2 + i3) * sc;
        sI[p + 192] = (i0 + r1 - i2 - r3) * sc;
    }
    __syncthreads();

    int k = tid >> 6, o = tid & 63;

    {
        const float* w0 = cw1 + k * 4096;
        const float* w1 = cw1 + 16384 + k * 4096;
        float bR = cb1[k * 64 + o];
        float bI = cb1[256 + k * 64 + o];
        float aR[8], aI[8];
        #pragma unroll
        for (int r = 0; r < 8; r++) { aR[r] = bR; aI[r] = bI; }
        #pragma unroll 2
        for (int dd = 0; dd < 64; dd += 4) {
            float wa[4], wb[4];
            #pragma unroll
            for (int q = 0; q < 4; q++) {
                wa[q] = w0[(dd + q) * 64 + o];
                wb[q] = w1[(dd + q) * 64 + o];
            }
            int sb = k * 64 + dd;
            #pragma unroll
            for (int r = 0; r < 8; r++) {
                float4 xr = *(const float4*)&sR[r * 256 + sb];
                float4 xi = *(const float4*)&sI[r * 256 + sb];
                aR[r] = fmaf(xr.x, wa[0], fmaf(-xi.x, wb[0], aR[r]));
                aI[r] = fmaf(xr.x, wb[0], fmaf( xi.x, wa[0], aI[r]));
                aR[r] = fmaf(xr.y, wa[1], fmaf(-xi.y, wb[1], aR[r]));
                aI[r] = fmaf(xr.y, wb[1], fmaf( xi.y, wa[1], aI[r]));
                aR[r] = fmaf(xr.z, wa[2], fmaf(-xi.z, wb[2], aR[r]));
                aI[r] = fmaf(xr.z, wb[2], fmaf( xi.z, wa[2], aI[r]));
                aR[r] = fmaf(xr.w, wa[3], fmaf(-xi.w, wb[3], aR[r]));
                aI[r] = fmaf(xr.w, wb[3], fmaf( xi.w, wa[3], aI[r]));
            }
        }
        #pragma unroll
        for (int r = 0; r < 8; r++) {
            tR[r * 256 + tid] = fmaxf(aR[r], 0.0f);
            tI[r * 256 + tid] = fmaxf(aI[r], 0.0f);
        }
    }
    __syncthreads();

    {
        const float* w0 = cw2 + k * 4096;
        const float* w1 = cw2 + 16384 + k * 4096;
        float bR = cb2[k * 64 + o];
        float bI = cb2[256 + k * 64 + o];
        float aR[8], aI[8];
        #pragma unroll
        for (int r = 0; r < 8; r++) { aR[r] = bR; aI[r] = bI; }
        #pragma unroll 2
        for (int dd = 0; dd < 64; dd += 4) {
            float wa[4], wb[4];
            #pragma unroll
            for (int q = 0; q < 4; q++) {
                wa[q] = w0[(dd + q) * 64 + o];
                wb[q] = w1[(dd + q) * 64 + o];
            }
            int sb = k * 64 + dd;
            #pragma unroll
            for (int r = 0; r < 8; r++) {
                float4 xr = *(const float4*)&tR[r * 256 + sb];
                float4 xi = *(const float4*)&tI[r * 256 + sb];
                aR[r] = fmaf(xr.x, wa[0], fmaf(-xi.x, wb[0], aR[r]));
                aI[r] = fmaf(xr.x, wb[0], fmaf( xi.x, wa[0], aI[r]));
                aR[r] = fmaf(xr.y, wa[1], fmaf(-xi.y, wb[1], aR[r]));
                aI[r] = fmaf(xr.y, wb[1], fmaf( xi.y, wa[1], aI[r]));
                aR[r] = fmaf(xr.z, wa[2], fmaf(-xi.z, wb[2], aR[r]));
                aI[r] = fmaf(xr.z, wb[2], fmaf( xi.z, wa[2], aI[r]));
                aR[r] = fmaf(xr.w, wa[3], fmaf(-xi.w, wb[3], aR[r]));
                aI[r] = fmaf(xr.w, wb[3], fmaf( xi.w, wa[3], aI[r]));
            }
        }
        #pragma unroll
        for (int r = 0; r < 8; r++) {
            float vR = aR[r], vI = aI[r];
            vR = (vR > LAMBDA_SS) ? vR - LAMBDA_SS
                 : ((vR < -LAMBDA_SS) ? vR + LAMBDA_SS : 0.0f);
            vI = (vI > LAMBDA_SS) ? vI - LAMBDA_SS
                 : ((vI < -LAMBDA_SS) ? vI + LAMBDA_SS : 0.0f);
            sR[r * 256 + tid] = vR;
            sI[r * 256 + tid] = vI;
        }
    }
    __syncthreads();

    #pragma unroll
    for (int g = tid; g < 512; g += 256) {
        int r = g >> 6, s = g & 63;
        int p = r * 256 + s;
        float R0 = sR[p],       I0 = sI[p];
        float R1 = sR[p + 64],  I1 = sI[p + 64];
        float R2 = sR[p + 128], I2 = sI[p + 128];
        float R3 = sR[p + 192], I3 = sI[p + 192];
        sR[p]       = (R0 + R1 + R2 + R3) * sc;
        sI[p]       = (I0 + I1 + I2 + I3) * sc;
        sR[p + 64]  = (R0 - I1 - R2 + I3) * sc;
        sI[p + 64]  = (I0 + R1 - I2 - R3) * sc;
        sR[p + 128] = (R0 - R1 + R2 - R3) * sc;
        sI[p + 128] = (I0 - I1 + I2 - I3) * sc;
        sR[p + 192] = (R0 + I1 - R2 - I3) * sc;
        sI[p + 192] = (I0 - R1 - I2 + R3) * sc;
    }
    __syncthreads();

    for (int i = tid; i < 2048; i += 256) {
        fR[(size_t)row0 * DIMC + i] = sR[i];
        fI[(size_t)row0 * DIMC + i] = sI[i];
    }
}

// ---------------------------------------------------------------------------
// Launch
// ---------------------------------------------------------------------------
extern "C" void kernel_launch(void* const* d_in, const int* in_sizes, int n_in,
                              void* d_out, int out_size) {
    const float* x         = (const float*)d_in[0];
    const float* norm1_w   = (const float*)d_in[1];
    const float* norm1_b   = (const float*)d_in[2];
    const float* in_proj_w = (const float*)d_in[3];
    const float* conv_w    = (const float*)d_in[4];
    const float* conv_b    = (const float*)d_in[5];
    const float* x_proj_w  = (const float*)d_in[6];
    const float* dt_proj_w = (const float*)d_in[7];
    const float* dt_proj_b = (const float*)d_in[8];
    const float* A_log     = (const float*)d_in[9];
    const float* Dvec      = (const float*)d_in[10];
    const float* out_proj_w= (const float*)d_in[11];
    const float* norm2_w   = (const float*)d_in[12];
    const float* norm2_b   = (const float*)d_in[13];
    const float* cw1       = (const float*)d_in[14];
    const float* cb1       = (const float*)d_in[15];
    const float* cw2       = (const float*)d_in[16];
    const float* cb2       = (const float*)d_in[17];
    float* out = (float*)d_out;

    void* sp = nullptr;
    cudaGetSymbolAddress(&sp, SCRATCH);
    float* S = (float*)sp;
    float* s_xc   = S + O_XC;
    float* s_xdbl = S + O_XDBL;
    float* s_x1   = S + O_X1;
    float* s_xn2  = S + O_XN2;
    float* s_fr   = S + O_FR;
    float* s_fi   = S + O_FI;
    __nv_bfloat16* s_xzb  = (__nv_bfloat16*)(S + O_XZB);
    __nv_bfloat16* s_xnbf = (__nv_bfloat16*)(S + O_XNBF);
    __nv_bfloat16* s_xcbf = (__nv_bfloat16*)(S + O_XCBF);
    __nv_bfloat16* s_ybf  = (__nv_bfloat16*)(S + O_YBF);
    __nv_bfloat16* s_wbf  = (__nv_bfloat16*)(S + O_WBF);
    __nv_bfloat16* win_bf = s_wbf;
    __nv_bfloat16* wx_bf  = s_wbf + W_IN_SZ;
    __nv_bfloat16* wo_bf  = s_wbf + W_IN_SZ + W_X_SZ;

    static int attr_done = 0;
    if (!attr_done) {
        cudaFuncSetAttribute(fft_fwd_kernel,
                             cudaFuncAttributeMaxDynamicSharedMemorySize, FFT_SMEM);
        cudaFuncSetAttribute(fft_inv_kernel,
                             cudaFuncAttributeMaxDynamicSharedMemorySize, FFT_SMEM);
        cudaFuncSetAttribute(gemm_bf16,
                             cudaFuncAttributeMaxDynamicSharedMemorySize, GEMM_SMEM);
        cudaFuncSetAttribute(scan_kernel,
                             cudaFuncAttributeMaxDynamicSharedMemorySize, SCAN_SMEM);
        attr_done = 1;
    }

    // 0) convert weights fp32 -> bf16
    wcvt_kernel<<<296, 256>>>(in_proj_w, x_proj_w, out_proj_w, s_wbf);
    // 1) LN1 -> bf16 only
    ln_kernel<<<NTOK / 8, 256>>>(x, norm1_w, norm1_b, nullptr, s_xnbf);
    // 2) in_proj -> bf16 xz
    gemm_bf16<<<dim3((2 * DI) / GBN, NTOK / GBM), 256, GEMM_SMEM>>>(
        s_xnbf, win_bf, nullptr, nullptr, s_xzb, NTOK, 2 * DI, DIMC);
    // 3) conv + silu (bf16 in, x2 vectorized) -> fp32 xc + bf16 xcbf
    conv_silu_kernel<<<(NTOK * DI / 2) / 256, 256>>>(s_xzb, conv_w, conv_b, s_xc, s_xcbf);
    // 4) x_proj -> fp32 xdbl
    gemm_bf16<<<dim3((XDBLW + GBN - 1) / GBN, NTOK / GBM), 256, GEMM_SMEM>>>(
        s_xcbf, wx_bf, nullptr, s_xdbl, nullptr, NTOK, XDBLW, DI);
    // 5) selective scan (cp.async double-buffered) -> bf16 y
    scan_kernel<<<BATCH * (DI / 8), 256, SCAN_SMEM>>>(
        s_xdbl, s_xc, s_xzb, A_log, Dvec, dt_proj_w, dt_proj_b, s_ybf);
    // 6) out_proj + residual -> fp32 x1
    gemm_bf16<<<dim3(DIMC / GBN, NTOK / GBM), 256, GEMM_SMEM>>>(
        s_ybf, wo_bf, x, s_x1, nullptr, NTOK, DIMC, DI);
    // 7) LN2 -> fp32
    ln_kernel<<<NTOK / 8, 256>>>(s_x1, norm2_w, norm2_b, s_xn2, nullptr);
    // 8) forward FFT
    fft_fwd_kernel<<<128, 512, FFT_SMEM>>>(s_xn2, s_fr, s_fi);
    // 9) fused EinFFT MLP (vectorized LDS)
    einfft_mlp_kernel<<<NTOK / 8, 256>>>(s_fr, s_fi, cw1, cb1, cw2, cb2);
    // 10) inverse FFT + residual -> out
    fft_inv_kernel<<<128, 512, FFT_SMEM>>>(s_fr, s_fi, s_x1, out);
}

// round 14
// speedup vs baseline: 1.6487x; 1.0332x over previous
#include <cuda_runtime.h>
#include <cuda_bf16.h>
#include <stdint.h>
#include <math.h>

// ---------------------------------------------------------------------------
// Problem constants
// ---------------------------------------------------------------------------
#define BATCH   2
#define LSEQ    2048
#define DIMC    256
#define DI      512          // d_inner
#define DS      64           // d_state
#define DTR     16           // dt_rank
#define XDBLW   144          // dt_rank + 2*d_state
#define NTOK    (BATCH*LSEQ) // 4096
#define SQRT_INV_8192 0.011048543456039806f
#define LAMBDA_SS 0.01f
#define PI_F 3.14159265358979323846f

// weight sizes (elems)
#define W_IN_SZ (2*DI*DIMC)   // 262144
#define W_X_SZ  (XDBLW*DI)    // 73728
#define W_O_SZ  (DIMC*DI)     // 131072

// ---------------------------------------------------------------------------
// Scratch (single __device__ array; no allocations anywhere)
// Offsets in float units; bf16 regions use 2 elems per float slot.
// ---------------------------------------------------------------------------
#define O_XDBL  ((size_t)0)                                // fp32 NTOK*XDBLW
#define O_X1    (O_XDBL + (size_t)NTOK*XDBLW)              // fp32 NTOK*DIMC
#define O_XZB   (O_X1   + (size_t)NTOK*DIMC)               // bf16 NTOK*2*DI
#define O_XNBF  (O_XZB  + (size_t)NTOK*DI)                 // bf16 NTOK*DIMC
#define O_XCBF  (O_XNBF + (size_t)NTOK*DIMC/2)             // bf16 NTOK*DI
#define O_YBF   (O_XCBF + (size_t)NTOK*DI/2)               // bf16 NTOK*DI
#define O_XN2B  (O_YBF  + (size_t)NTOK*DI/2)               // bf16 NTOK*DIMC
#define O_FRB   (O_XN2B + (size_t)NTOK*DIMC/2)             // bf16 NTOK*DIMC
#define O_FIB   (O_FRB  + (size_t)NTOK*DIMC/2)             // bf16 NTOK*DIMC
#define O_WBF   (O_FIB  + (size_t)NTOK*DIMC/2)             // bf16 weights
#define O_END   (O_WBF  + (size_t)(W_IN_SZ+W_X_SZ+W_O_SZ)/2 + 64)

__device__ float SCRATCH[O_END];

// ---------------------------------------------------------------------------
// cp.async helpers
// ---------------------------------------------------------------------------
__device__ __forceinline__ void cp16(unsigned dst, const void* src, int sz) {
    asm volatile("cp.async.cg.shared.global [%0], [%1], 16, %2;"
                 :: "r"(dst), "l"(src), "r"(sz));
}
__device__ __forceinline__ void cp_commit() {
    asm volatile("cp.async.commit_group;" ::: "memory");
}
template <int N>
__device__ __forceinline__ void cp_wait() {
    asm volatile("cp.async.wait_group %0;" :: "n"(N) : "memory");
}

// ---------------------------------------------------------------------------
// LayerNorm body (one warp per token); writes fp32 and/or bf16.
// ---------------------------------------------------------------------------
__device__ __forceinline__ void ln_body(int t, int lane,
                                        const float* __restrict__ x,
                                        const float* __restrict__ w,
                                        const float* __restrict__ b,
                                        float* __restrict__ out,
                                        __nv_bfloat16* __restrict__ obf) {
    const float4* row = (const float4*)(x + (size_t)t * DIMC);
    float4 v0 = row[lane];
    float4 v1 = row[lane + 32];
    float s = v0.x + v0.y + v0.z + v0.w + v1.x + v1.y + v1.z + v1.w;
    #pragma unroll
    for (int off = 16; off; off >>= 1) s += __shfl_xor_sync(0xffffffffu, s, off);
    float m = s * (1.0f / 256.0f);
    float d0 = v0.x - m, d1 = v0.y - m, d2 = v0.z - m, d3 = v0.w - m;
    float d4 = v1.x - m, d5 = v1.y - m, d6 = v1.z - m, d7 = v1.w - m;
    float q = d0*d0 + d1*d1 + d2*d2 + d3*d3 + d4*d4 + d5*d5 + d6*d6 + d7*d7;
    #pragma unroll
    for (int off = 16; off; off >>= 1) q += __shfl_xor_sync(0xffffffffu, q, off);
    float inv = rsqrtf(q * (1.0f / 256.0f) + 1e-5f);
    const float4* w4 = (const float4*)w;
    const float4* b4 = (const float4*)b;
    float4 wa = w4[lane], ba = b4[lane];
    float4 wb = w4[lane + 32], bb = b4[lane + 32];
    float4 r0, r1;
    r0.x = d0*inv*wa.x + ba.x; r0.y = d1*inv*wa.y + ba.y;
    r0.z = d2*inv*wa.z + ba.z; r0.w = d3*inv*wa.w + ba.w;
    r1.x = d4*inv*wb.x + bb.x; r1.y = d5*inv*wb.y + bb.y;
    r1.z = d6*inv*wb.z + bb.z; r1.w = d7*inv*wb.w + bb.w;
    if (out) {
        float4* o4 = (float4*)(out + (size_t)t * DIMC);
        o4[lane] = r0; o4[lane + 32] = r1;
    }
    if (obf) {
        __nv_bfloat162* o2 = (__nv_bfloat162*)(obf + (size_t)t * DIMC);
        o2[lane*2]      = __nv_bfloat162(__float2bfloat16_rn(r0.x), __float2bfloat16_rn(r0.y));
        o2[lane*2 + 1]  = __nv_bfloat162(__float2bfloat16_rn(r0.z), __float2bfloat16_rn(r0.w));
        o2[64 + lane*2]     = __nv_bfloat162(__float2bfloat16_rn(r1.x), __float2bfloat16_rn(r1.y));
        o2[64 + lane*2 + 1] = __nv_bfloat162(__float2bfloat16_rn(r1.z), __float2bfloat16_rn(r1.w));
    }
}

// ---------------------------------------------------------------------------
// Prep: weight fp32->bf16 convert (blocks 0..295) + LN1 (blocks 296..807).
// ---------------------------------------------------------------------------
#define WCVT_BLOCKS 296
__global__ void prep_kernel(const float* __restrict__ w_in,
                            const float* __restrict__ w_x,
                            const float* __restrict__ w_o,
                            __nv_bfloat16* __restrict__ wdst,
                            const float* __restrict__ x,
                            const float* __restrict__ n1w,
                            const float* __restrict__ n1b,
                            __nv_bfloat16* __restrict__ xnbf) {
    if (blockIdx.x < WCVT_BLOCKS) {
        int total = W_IN_SZ + W_X_SZ + W_O_SZ;
        for (int i = blockIdx.x * 256 + threadIdx.x; i < total;
             i += WCVT_BLOCKS * 256) {
            float v;
            if (i < W_IN_SZ) v = w_in[i];
            else if (i < W_IN_SZ + W_X_SZ) v = w_x[i - W_IN_SZ];
            else v = w_o[i - W_IN_SZ - W_X_SZ];
            wdst[i] = __float2bfloat16_rn(v);
        }
    } else {
        int t = (blockIdx.x - WCVT_BLOCKS) * 8 + (threadIdx.x >> 5);
        ln_body(t, threadIdx.x & 31, x, n1w, n1b, nullptr, xnbf);
    }
}

// LN2 standalone
__global__ void ln_kernel(const float* __restrict__ x,
                          const float* __restrict__ w,
                          const float* __restrict__ b,
                          float* __restrict__ out,
                          __nv_bfloat16* __restrict__ obf) {
    ln_body(blockIdx.x * 8 + (threadIdx.x >> 5), threadIdx.x & 31,
            x, w, b, out, obf);
}

// ---------------------------------------------------------------------------
// bf16 tensor-core GEMM: out = A[M,K] * W[N,K]^T (+ R).  Output fp32 or bf16.
// 128x64 tile, BK=32, 8 warps, warp tile 32x32 via 2x4 m16n8k16.
// ---------------------------------------------------------------------------
#define GBM 128
#define GBN 64
#define BK  32
#define HSTR 40
#define GSTAGES 4
#define GEMM_SMEM (GSTAGES * (GBM + GBN) * HSTR * 2)

__device__ __forceinline__ void mma_bf16(float* c, const unsigned* a, const unsigned* b) {
    asm volatile(
        "mma.sync.aligned.m16n8k16.row.col.f32.bf16.bf16.f32 "
        "{%0,%1,%2,%3}, {%4,%5,%6,%7}, {%8,%9}, {%0,%1,%2,%3};"
        : "+f"(c[0]), "+f"(c[1]), "+f"(c[2]), "+f"(c[3])
        : "r"(a[0]), "r"(a[1]), "r"(a[2]), "r"(a[3]), "r"(b[0]), "r"(b[1]));
}

__global__ void __launch_bounds__(256) gemm_bf16(const __nv_bfloat16* __restrict__ A,
                                                 const __nv_bfloat16* __restrict__ W,
                                                 const float* __restrict__ R,
                                                 float* __restrict__ C,
                                                 __nv_bfloat16* __restrict__ Cbf,
                                                 int M, int N, int K) {
    extern __shared__ __nv_bfloat16 hsm[];
    __nv_bfloat16* As = hsm;
    __nv_bfloat16* Bs = hsm + GSTAGES * GBM * HSTR;
    unsigned smA = (unsigned)__cvta_generic_to_shared(As);
    unsigned smB = (unsigned)__cvta_generic_to_shared(Bs);

    int m0 = blockIdx.y * GBM;
    int n0 = blockIdx.x * GBN;
    int tid = threadIdx.x;
    int wid = tid >> 5, lane = tid & 31;
    int wm = (wid & 3) * 32;
    int wn = (wid >> 2) * 32;
    int gid = lane >> 2;
    int tig = lane & 3;
    int ar = tid >> 1, akq = (tid & 1) * 16;
    int br = tid >> 2, bkq = (tid & 3) * 8;

    const __nv_bfloat16* Abase = A + (size_t)(m0 + ar) * K + akq;
    bool bok = (n0 + br) < N;
    const __nv_bfloat16* Bbase = bok ? (W + (size_t)(n0 + br) * K + bkq) : W;
    int bsz = bok ? 16 : 0;
    unsigned adst = smA + (unsigned)(ar * HSTR + akq) * 2u;
    unsigned bdst = smB + (unsigned)(br * HSTR + bkq) * 2u;
    const unsigned aStage = GBM * HSTR * 2u;
    const unsigned bStage = GBN * HSTR * 2u;

    float acc[2][4][4];
    #pragma unroll
    for (int mi = 0; mi < 2; mi++)
        #pragma unroll
        for (int ni = 0; ni < 4; ni++)
            #pragma unroll
            for (int q = 0; q < 4; q++) acc[mi][ni][q] = 0.0f;

    int nIt = K / BK;
    #pragma unroll
    for (int s = 0; s < GSTAGES - 1; s++) {
        cp16(adst + s * aStage,      Abase + s * BK,     16);
        cp16(adst + s * aStage + 16, Abase + s * BK + 8, 16);
        cp16(bdst + s * bStage,      Bbase + (bok ? s * BK : 0), bsz);
        cp_commit();
    }

    for (int it = 0; it < nIt; it++) {
        cp_wait<GSTAGES - 2>();
        __syncthreads();
        int buf = it & (GSTAGES - 1);
        const __nv_bfloat16* Ab = As + buf * (GBM * HSTR);
        const __nv_bfloat16* Bb = Bs + buf * (GBN * HSTR);
        #pragma unroll
        for (int ks = 0; ks < 2; ks++) {
            int k16 = ks * 16;
            unsigned afr[2][4], bfr[4][2];
            #pragma unroll
            for (int mi = 0; mi < 2; mi++) {
                int rb = wm + mi * 16 + gid;
                afr[mi][0] = *(const unsigned*)(Ab + (rb)     * HSTR + k16 + tig * 2);
                afr[mi][1] = *(const unsigned*)(Ab + (rb + 8) * HSTR + k16 + tig * 2);
                afr[mi][2] = *(const unsigned*)(Ab + (rb)     * HSTR + k16 + tig * 2 + 8);
                afr[mi][3] = *(const unsigned*)(Ab + (rb + 8) * HSTR + k16 + tig * 2 + 8);
            }
            #pragma unroll
            for (int ni = 0; ni < 4; ni++) {
                int cb = wn + ni * 8 + gid;
                bfr[ni][0] = *(const unsigned*)(Bb + cb * HSTR + k16 + tig * 2);
                bfr[ni][1] = *(const unsigned*)(Bb + cb * HSTR + k16 + tig * 2 + 8);
            }
            #pragma unroll
            for (int mi = 0; mi < 2; mi++)
                #pragma unroll
                for (int ni = 0; ni < 4; ni++)
                    mma_bf16(acc[mi][ni], afr[mi], bfr[ni]);
        }
        int nx = it + GSTAGES - 1;
        if (nx < nIt) {
            int slot = nx & (GSTAGES - 1);
            cp16(adst + slot * aStage,      Abase + nx * BK,     16);
            cp16(adst + slot * aStage + 16, Abase + nx * BK + 8, 16);
            cp16(bdst + slot * bStage,      Bbase + (bok ? nx * BK : 0), bsz);
        }
        cp_commit();
    }

    #pragma unroll
    for (int mi = 0; mi < 2; mi++) {
        int row = m0 + wm + mi * 16 + gid;
        #pragma unroll
        for (int ni = 0; ni < 4; ni++) {
            int col = n0 + wn + ni * 8 + tig * 2;
            #pragma unroll
            for (int half = 0; half < 2; half++) {
                int rr = row + half * 8;
                float v0 = acc[mi][ni][half * 2];
                float v1 = acc[mi][ni][half * 2 + 1];
                if (col < N) {
                    if (Cbf) Cbf[(size_t)rr * N + col] = __float2bfloat16_rn(v0);
                    else {
                        if (R) v0 += R[(size_t)rr * N + col];
                        C[(size_t)rr * N + col] = v0;
                    }
                }
                if (col + 1 < N) {
                    if (Cbf) Cbf[(size_t)rr * N + col + 1] = __float2bfloat16_rn(v1);
                    else {
                        if (R) v1 += R[(size_t)rr * N + col + 1];
                        C[(size_t)rr * N + col + 1] = v1;
                    }
                }
            }
        }
    }
}

// ---------------------------------------------------------------------------
// Depthwise causal conv (k=4) + bias + SiLU, bf16 in -> bf16 out only.
// ---------------------------------------------------------------------------
__global__ void conv_silu_kernel(const __nv_bfloat16* __restrict__ xzb,
                                 const float* __restrict__ cw,
                                 const float* __restrict__ cb,
                                 __nv_bfloat16* __restrict__ xc_bf) {
    int idx = blockIdx.x * 256 + threadIdx.x;   // NTOK*DI
    int d = idx & (DI - 1);
    int bt = idx >> 9;
    int b = bt >> 11;
    int l = bt & (LSEQ - 1);
    float acc = cb[d];
    #pragma unroll
    for (int k = 0; k < 4; k++) {
        int ls = l + k - 3;
        if (ls >= 0)
            acc += __bfloat162float(xzb[((size_t)((b << 11) | ls)) * (2 * DI) + d])
                   * cw[d * 4 + k];
    }
    float v = acc / (1.0f + __expf(-acc));
    xc_bf[(size_t)bt * DI + d] = __float2bfloat16_rn(v);
}

// ---------------------------------------------------------------------------
// Selective scan: fused dt, deferred reduce-scatter, cp.async double-buffered.
// xc staged in bf16 (one cp16 per token covers all 8 channels).
// ---------------------------------------------------------------------------
#define TCHUNK 64
#define SXW 148
#define SCAN_F (2*64*SXW + 512 + 512 + 128 + 8)
#define SCAN_SMEM (SCAN_F * 4 + 2 * (2*64*8*2))

__global__ void __launch_bounds__(256) scan_kernel(
        const float* __restrict__ xdbl,
        const __nv_bfloat16* __restrict__ xcb,
        const __nv_bfloat16* __restrict__ xzb,
        const float* __restrict__ A_log,
        const float* __restrict__ Dvec,
        const float* __restrict__ dtw,
        const float* __restrict__ dtb,
        __nv_bfloat16* __restrict__ y_bf) {
    extern __shared__ float ssm[];
    float* sX   = ssm;                      // [2][64][SXW]
    float* sdt  = sX + 2 * 64 * SXW;        // [64][8]
    float* sy   = sdt + 512;                // [64][8]
    float* sw   = sy + 512;                 // [8][16]
    float* sbias= sw + 128;                 // [8]
    __nv_bfloat16* szb  = (__nv_bfloat16*)(sbias + 8);  // [2][64][8]
    __nv_bfloat16* sxcb = szb + 2 * 64 * 8;             // [2][64][8]
    unsigned aX  = (unsigned)__cvta_generic_to_shared(sX);
    unsigned aZ  = (unsigned)__cvta_generic_to_shared(szb);
    unsigned aXC = (unsigned)__cvta_generic_to_shared(sxcb);

    int b = blockIdx.x >> 6;
    int dbase = (blockIdx.x & 63) * 8;
    int wid = threadIdx.x >> 5;
    int lane = threadIdx.x & 31;
    int d = dbase + wid;
    int tid = threadIdx.x;

    if (tid < 128) {
        int di = tid >> 4, r = tid & 15;
        sw[di * 16 + r] = dtw[(dbase + di) * DTR + r];
        if (r == 0) sbias[di] = dtb[dbase + di];
    }
    float A0 = -__expf(A_log[d * DS + lane]);
    float A1 = -__expf(A_log[d * DS + lane + 32]);
    float Dd = Dvec[d];
    float h0 = 0.0f, h1 = 0.0f;

    auto stage = [&](int buf, int t0) {
        size_t rowbase = (size_t)(b * LSEQ + t0);
        for (int i = tid; i < 64 * 36; i += 256) {
            int tt = i / 36, q = i - tt * 36;
            cp16(aX + (unsigned)(((buf * 64 + tt) * SXW) + q * 4) * 4u,
                 xdbl + (rowbase + tt) * XDBLW + q * 4, 16);
        }
        if (tid < 128) {
            int tt = tid & 63;
            if (tid < 64)
                cp16(aXC + (unsigned)((buf * 64 + tt) * 8) * 2u,
                     xcb + (rowbase + tt) * DI + dbase, 16);
            else
                cp16(aZ + (unsigned)((buf * 64 + tt) * 8) * 2u,
                     xzb + (rowbase + tt) * (2 * DI) + DI + dbase, 16);
        }
    };

    stage(0, 0);
    cp_commit();

    for (int c = 0; c < LSEQ / TCHUNK; c++) {
        int buf = c & 1;
        cp_wait<0>();
        __syncthreads();
        if (c + 1 < LSEQ / TCHUNK) stage(buf ^ 1, (c + 1) * TCHUNK);
        cp_commit();

        for (int i = tid; i < 512; i += 256) {
            int tt = i >> 3, di = i & 7;
            const float* xr = sX + (buf * 64 + tt) * SXW;
            float acc = sbias[di];
            #pragma unroll
            for (int r = 0; r < 16; r++) acc = fmaf(xr[r], sw[di * 16 + r], acc);
            sdt[tt * 8 + di] = (acc > 20.0f) ? acc : __logf(1.0f + __expf(acc));
        }
        __syncthreads();

        #pragma unroll 1
        for (int g = 0; g < TCHUNK / 32; g++) {
            float part[32];
            #pragma unroll
            for (int j = 0; j < 32; j++) {
                int tt = g * 32 + j;
                const float* xr = sX + (buf * 64 + tt) * SXW;
                float dtv = sdt[tt * 8 + wid];
                float xcv = __bfloat162float(sxcb[(buf * 64 + tt) * 8 + wid]);
                float du = dtv * xcv;
                float dA0 = __expf(dtv * A0);
                float dA1 = __expf(dtv * A1);
                h0 = fmaf(dA0, h0, du * xr[16 + lane]);
                h1 = fmaf(dA1, h1, du * xr[48 + lane]);
                part[j] = fmaf(h0, xr[80 + lane], h1 * xr[112 + lane]);
            }
            #pragma unroll
            for (int s = 16; s >= 1; s >>= 1) {
                bool up = (lane & s) != 0;
                #pragma unroll
                for (int i2 = 0; i2 < 16; i2++) {
                    if (i2 >= s) break;
                    float keep = up ? part[i2 + s] : part[i2];
                    float send = up ? part[i2] : part[i2 + s];
                    part[i2] = keep + __shfl_xor_sync(0xffffffffu, send, s);
                }
            }
            int tt = g * 32 + lane;
            float xcv = __bfloat162float(sxcb[(buf * 64 + tt) * 8 + wid]);
            float zv = __bfloat162float(szb[(buf * 64 + tt) * 8 + wid]);
            float gate = zv / (1.0f + __expf(-zv));
            sy[tt * 8 + wid] = fmaf(xcv, Dd, part[0]) * gate;
        }
        __syncthreads();
        for (int i = tid; i < TCHUNK * 8; i += 256) {
            int tt = i >> 3, di = i & 7;
            y_bf[(size_t)(b * LSEQ + c * TCHUNK + tt) * DI + dbase + di] =
                __float2bfloat16_rn(sy[tt * 8 + di]);
        }
        __syncthreads();
    }
}

// ---------------------------------------------------------------------------
// Forward 2048-pt FFT (DIF), bf16 real input -> bf16 spectrum.
// 4 ch/block, padded stride 2049.
// ---------------------------------------------------------------------------
#define FSTR 2049
#define FFT_SMEM (2 * 4 * FSTR * 4)

__global__ void __launch_bounds__(512) fft_fwd_kernel(const __nv_bfloat16* __restrict__ xin,
                                                      __nv_bfloat16* __restrict__ dR,
                                                      __nv_bfloat16* __restrict__ dI) {
    extern __shared__ float sm[];
    float* sr = sm;
    float* si = sm + 4 * FSTR;
    int b = blockIdx.x >> 6;
    int c0 = (blockIdx.x & 63) * 4;
    size_t base = (size_t)b * LSEQ * DIMC + c0;
    int tid = threadIdx.x;

    for (int n = tid; n < 2048; n += 512) {
        const __nv_bfloat162* p = (const __nv_bfloat162*)(xin + base + (size_t)n * DIMC);
        __nv_bfloat162 a = p[0], bb = p[1];
        sr[0 * FSTR + n] = __bfloat162float(a.x);
        sr[1 * FSTR + n] = __bfloat162float(a.y);
        sr[2 * FSTR + n] = __bfloat162float(bb.x);
        sr[3 * FSTR + n] = __bfloat162float(bb.y);
        si[0 * FSTR + n] = 0.0f; si[1 * FSTR + n] = 0.0f;
        si[2 * FSTR + n] = 0.0f; si[3 * FSTR + n] = 0.0f;
    }
    __syncthreads();

    #pragma unroll
    for (int hb = 10; hb >= 0; hb--) {
        int half = 1 << hb;
        float th = -PI_F / (float)half;
        for (int e = tid; e < 4096; e += 512) {
            int col = e >> 10, idx = e & 1023;
            int j = idx & (half - 1);
            int pos = ((idx >> hb) << (hb + 1)) + j;
            float* cr = sr + col * FSTR;
            float* ci = si + col * FSTR;
            float ar = cr[pos],        ai = ci[pos];
            float br = cr[pos + half], bi = ci[pos + half];
            float wi, wr;
            __sincosf(th * (float)j, &wi, &wr);
            float xr = ar - br, xi = ai - bi;
            cr[pos] = ar + br;  ci[pos] = ai + bi;
            cr[pos + half] = xr * wr - xi * wi;
            ci[pos + half] = xr * wi + xi * wr;
        }
        __syncthreads();
    }

    for (int n = tid; n < 2048; n += 512) {
        __nv_bfloat162* pr = (__nv_bfloat162*)(dR + base + (size_t)n * DIMC);
        __nv_bfloat162* pi = (__nv_bfloat162*)(dI + base + (size_t)n * DIMC);
        pr[0] = __nv_bfloat162(__float2bfloat16_rn(sr[0 * FSTR + n]),
                               __float2bfloat16_rn(sr[1 * FSTR + n]));
        pr[1] = __nv_bfloat162(__float2bfloat16_rn(sr[2 * FSTR + n]),
                               __float2bfloat16_rn(sr[3 * FSTR + n]));
        pi[0] = __nv_bfloat162(__float2bfloat16_rn(si[0 * FSTR + n]),
                               __float2bfloat16_rn(si[1 * FSTR + n]));
        pi[1] = __nv_bfloat162(__float2bfloat16_rn(si[2 * FSTR + n]),
                               __float2bfloat16_rn(si[3 * FSTR + n]));
    }
}

// ---------------------------------------------------------------------------
// Inverse 2048-pt FFT (DIT) from bf16 spectrum; real part + fp32 residual.
// ---------------------------------------------------------------------------
__global__ void __launch_bounds__(512) fft_inv_kernel(const __nv_bfloat16* __restrict__ dR,
                                                      const __nv_bfloat16* __restrict__ dI,
                                                      const float* __restrict__ x1,
                                                      float* __restrict__ out) {
    extern __shared__ float sm[];
    float* sr = sm;
    float* si = sm + 4 * FSTR;
    int b = blockIdx.x >> 6;
    int c0 = (blockIdx.x & 63) * 4;
    size_t base = (size_t)b * LSEQ * DIMC + c0;
    int tid = threadIdx.x;

    for (int n = tid; n < 2048; n += 512) {
        const __nv_bfloat162* pr = (const __nv_bfloat162*)(dR + base + (size_t)n * DIMC);
        const __nv_bfloat162* pi = (const __nv_bfloat162*)(dI + base + (size_t)n * DIMC);
        __nv_bfloat162 r0 = pr[0], r1 = pr[1], i0 = pi[0], i1 = pi[1];
        sr[0 * FSTR + n] = __bfloat162float(r0.x);
        sr[1 * FSTR + n] = __bfloat162float(r0.y);
        sr[2 * FSTR + n] = __bfloat162float(r1.x);
        sr[3 * FSTR + n] = __bfloat162float(r1.y);
        si[0 * FSTR + n] = __bfloat162float(i0.x);
        si[1 * FSTR + n] = __bfloat162float(i0.y);
        si[2 * FSTR + n] = __bfloat162float(i1.x);
        si[3 * FSTR + n] = __bfloat162float(i1.y);
    }
    __syncthreads();

    #pragma unroll
    for (int hb = 0; hb <= 10; hb++) {
        int half = 1 << hb;
        float th = PI_F / (float)half;
        for (int e = tid; e < 4096; e += 512) {
            int col = e >> 10, idx = e & 1023;
            int j = idx & (half - 1);
            int pos = ((idx >> hb) << (hb + 1)) + j;
            float* cr = sr + col * FSTR;
            float* ci = si + col * FSTR;
            float ar = cr[pos],        ai = ci[pos];
            float br = cr[pos + half], bi = ci[pos + half];
            float wi, wr;
            __sincosf(th * (float)j, &wi, &wr);
            float tr = br * wr - bi * wi;
            float ti = br * wi + bi * wr;
            cr[pos] = ar + tr;         ci[pos] = ai + ti;
            cr[pos + half] = ar - tr;  ci[pos + half] = ai - ti;
        }
        __syncthreads();
    }

    for (int n = tid; n < 2048; n += 512) {
        size_t a = base + (size_t)n * DIMC;
        float4 rx = *(const float4*)(x1 + a);
        float4 o;
        o.x = rx.x + sr[0 * FSTR + n];
        o.y = rx.y + sr[1 * FSTR + n];
        o.z = rx.z + sr[2 * FSTR + n];
        o.w = rx.w + sr[3 * FSTR + n];
        *(float4*)(out + a) = o;
    }
}

// ---------------------------------------------------------------------------
// EinFFT MLP with DFT4/IDFT4 folded in; bf16 global I/O, fp32 smem compute.
// ---------------------------------------------------------------------------
__global__ void __launch_bounds__(256) einfft_mlp_kernel(
        __nv_bfloat16* __restrict__ fR, __nv_bfloat16* __restrict__ fI,
        const float* __restrict__ cw1, const float* __restrict__ cb1,
        const float* __restrict__ cw2, const float* __restrict__ cb2) {
    __shared__ __align__(16) float sR[2048], sI[2048];
    __shared__ __align__(16) float tR[2048], tI[2048];
    int row0 = blockIdx.x * 8;
    int tid = threadIdx.x;
    {
        const __nv_bfloat162* fr2 = (const __nv_bfloat162*)(fR + (size_t)row0 * DIMC);
        const __nv_bfloat162* fi2 = (const __nv_bfloat162*)(fI + (size_t)row0 * DIMC);
        for (int i = tid; i < 1024; i += 256) {
            __nv_bfloat162 r = fr2[i], m = fi2[i];
            sR[2*i] = __bfloat162float(r.x); sR[2*i+1] = __bfloat162float(r.y);
            sI[2*i] = __bfloat162float(m.x); sI[2*i+1] = __bfloat162float(m.y);
        }
    }
    __syncthreads();

    const float sc = SQRT_INV_8192;
    #pragma unroll
    for (int g = tid; g < 512; g += 256) {
        int r = g >> 6, s = g & 63;
        int p = r * 256 + s;
        float r0 = sR[p],       i0 = sI[p];
        float r1 = sR[p + 64],  i1 = sI[p + 64];
        float r2 = sR[p + 128], i2 = sI[p + 128];
        float r3 = sR[p + 192], i3 = sI[p + 192];
        sR[p]       = (r0 + r1 + r2 + r3) * sc;
        sI[p]       = (i0 + i1 + i2 + i3) * sc;
        sR[p + 64]  = (r0 + i1 - r2 - i3) * sc;
        sI[p + 64]  = (i0 - r1 - i2 + r3) * sc;
        sR[p + 128] = (r0 - r1 + r2 - r3) * sc;
        sI[p + 128] = (i0 - i1 + i2 - i3) * sc;
        sR[p + 192] = (r0 - i1 - r2 + i3) * sc;
        sI[p + 192] = (i0 + r1 - i2 - r3) * sc;
    }
    __syncthreads();

    int k = tid >> 6, o = tid & 63;

    {
        const float* w0 = cw1 + k * 4096;
        const float* w1 = cw1 + 16384 + k * 4096;
        float bR = cb1[k * 64 + o];
        float bI = cb1[256 + k * 64 + o];
        float aR[8], aI[8];
        #pragma unroll
        for (int r = 0; r < 8; r++) { aR[r] = bR; aI[r] = bI; }
        #pragma unroll 2
        for (int dd = 0; dd < 64; dd += 4) {
            float wa[4], wb[4];
            #pragma unroll
            for (int q = 0; q < 4; q++) {
                wa[q] = w0[(dd + q) * 64 + o];
                wb[q] = w1[(dd + q) * 64 + o];
            }
            int sb = k * 64 + dd;
            #pragma unroll
            for (int r = 0; r < 8; r++) {
                float4 xr = *(const float4*)&sR[r * 256 + sb];
                float4 xi = *(const float4*)&sI[r * 256 + sb];
                aR[r] = fmaf(xr.x, wa[0], fmaf(-xi.x, wb[0], aR[r]));
                aI[r] = fmaf(xr.x, wb[0], fmaf( xi.x, wa[0], aI[r]));
                aR[r] = fmaf(xr.y, wa[1], fmaf(-xi.y, wb[1], aR[r]));
                aI[r] = fmaf(xr.y, wb[1], fmaf( xi.y, wa[1], aI[r]));
                aR[r] = fmaf(xr.z, wa[2], fmaf(-xi.z, wb[2], aR[r]));
                aI[r] = fmaf(xr.z, wb[2], fmaf( xi.z, wa[2], aI[r]));
                aR[r] = fmaf(xr.w, wa[3], fmaf(-xi.w, wb[3], aR[r]));
                aI[r] = fmaf(xr.w, wb[3], fmaf( xi.w, wa[3], aI[r]));
            }
        }
        #pragma unroll
        for (int r = 0; r < 8; r++) {
            tR[r * 256 + tid] = fmaxf(aR[r], 0.0f);
            tI[r * 256 + tid] = fmaxf(aI[r], 0.0f);
        }
    }
    __syncthreads();

    {
        const float* w0 = cw2 + k * 4096;
        const float* w1 = cw2 + 16384 + k * 4096;
        float bR = cb2[k * 64 + o];
        float bI = cb2[256 + k * 64 + o];
        float aR[8], aI[8];
        #pragma unroll
        for (int r = 0; r < 8; r++) { aR[r] = bR; aI[r] = bI; }
        #pragma unroll 2
        for (int dd = 0; dd < 64; dd += 4) {
            float wa[4], wb[4];
            #pragma unroll
            for (int q = 0; q < 4; q++) {
                wa[q] = w0[(dd + q) * 64 + o];
                wb[q] = w1[(dd + q) * 64 + o];
            }
            int sb = k * 64 + dd;
            #pragma unroll
            for (int r = 0; r < 8; r++) {
                float4 xr = *(const float4*)&tR[r * 256 + sb];
                float4 xi = *(const float4*)&tI[r * 256 + sb];
                aR[r] = fmaf(xr.x, wa[0], fmaf(-xi.x, wb[0], aR[r]));
                aI[r] = fmaf(xr.x, wb[0], fmaf( xi.x, wa[0], aI[r]));
                aR[r] = fmaf(xr.y, wa[1], fmaf(-xi.y, wb[1], aR[r]));
                aI[r] = fmaf(xr.y, wb[1], fmaf( xi.y, wa[1], aI[r]));
                aR[r] = fmaf(xr.z, wa[2], fmaf(-xi.z, wb[2], aR[r]));
                aI[r] = fmaf(xr.z, wb[2], fmaf( xi.z, wa[2], aI[r]));
                aR[r] = fmaf(xr.w, wa[3], fmaf(-xi.w, wb[3], aR[r]));
                aI[r] = fmaf(xr.w, wb[3], fmaf( xi.w, wa[3], aI[r]));
            }
        }
        #pragma unroll
        for (int r = 0; r < 8; r++) {
            float vR = aR[r], vI = aI[r];
            vR = (vR > LAMBDA_SS) ? vR - LAMBDA_SS
                 : ((vR < -LAMBDA_SS) ? vR + LAMBDA_SS : 0.0f);
            vI = (vI > LAMBDA_SS) ? vI - LAMBDA_SS
                 : ((vI < -LAMBDA_SS) ? vI + LAMBDA_SS : 0.0f);
            sR[r * 256 + tid] = vR;
            sI[r * 256 + tid] = vI;
        }
    }
    __syncthreads();

    #pragma unroll
    for (int g = tid; g < 512; g += 256) {
        int r = g >> 6, s = g & 63;
        int p = r * 256 + s;
        float R0 = sR[p],       I0 = sI[p];
        float R1 = sR[p + 64],  I1 = sI[p + 64];
        float R2 = sR[p + 128], I2 = sI[p + 128];
        float R3 = sR[p + 192], I3 = sI[p + 192];
        sR[p]       = (R0 + R1 + R2 + R3) * sc;
        sI[p]       = (I0 + I1 + I2 + I3) * sc;
        sR[p + 64]  = (R0 - I1 - R2 + I3) * sc;
        sI[p + 64]  = (I0 + R1 - I2 - R3) * sc;
        sR[p + 128] = (R0 - R1 + R2 - R3) * sc;
        sI[p + 128] = (I0 - I1 + I2 - I3) * sc;
        sR[p + 192] = (R0 + I1 - R2 - I3) * sc;
        sI[p + 192] = (I0 - R1 - I2 + R3) * sc;
    }
    __syncthreads();

    {
        __nv_bfloat162* fr2 = (__nv_bfloat162*)(fR + (size_t)row0 * DIMC);
        __nv_bfloat162* fi2 = (__nv_bfloat162*)(fI + (size_t)row0 * DIMC);
        for (int i = tid; i < 1024; i += 256) {
            fr2[i] = __nv_bfloat162(__float2bfloat16_rn(sR[2*i]),
                                    __float2bfloat16_rn(sR[2*i+1]));
            fi2[i] = __nv_bfloat162(__float2bfloat16_rn(sI[2*i]),
                                    __float2bfloat16_rn(sI[2*i+1]));
        }
    }
}

// ---------------------------------------------------------------------------
// Launch
// ---------------------------------------------------------------------------
extern "C" void kernel_launch(void* const* d_in, const int* in_sizes, int n_in,
                              void* d_out, int out_size) {
    const float* x         = (const float*)d_in[0];
    const float* norm1_w   = (const float*)d_in[1];
    const float* norm1_b   = (const float*)d_in[2];
    const float* in_proj_w = (const float*)d_in[3];
    const float* conv_w    = (const float*)d_in[4];
    const float* conv_b    = (const float*)d_in[5];
    const float* x_proj_w  = (const float*)d_in[6];
    const float* dt_proj_w = (const float*)d_in[7];
    const float* dt_proj_b = (const float*)d_in[8];
    const float* A_log     = (const float*)d_in[9];
    const float* Dvec      = (const float*)d_in[10];
    const float* out_proj_w= (const float*)d_in[11];
    const float* norm2_w   = (const float*)d_in[12];
    const float* norm2_b   = (const float*)d_in[13];
    const float* cw1       = (const float*)d_in[14];
    const float* cb1       = (const float*)d_in[15];
    const float* cw2       = (const float*)d_in[16];
    const float* cb2       = (const float*)d_in[17];
    float* out = (float*)d_out;

    void* sp = nullptr;
    cudaGetSymbolAddress(&sp, SCRATCH);
    float* S = (float*)sp;
    float* s_xdbl = S + O_XDBL;
    float* s_x1   = S + O_X1;
    __nv_bfloat16* s_xzb  = (__nv_bfloat16*)(S + O_XZB);
    __nv_bfloat16* s_xnbf = (__nv_bfloat16*)(S + O_XNBF);
    __nv_bfloat16* s_xcbf = (__nv_bfloat16*)(S + O_XCBF);
    __nv_bfloat16* s_ybf  = (__nv_bfloat16*)(S + O_YBF);
    __nv_bfloat16* s_xn2b = (__nv_bfloat16*)(S + O_XN2B);
    __nv_bfloat16* s_frb  = (__nv_bfloat16*)(S + O_FRB);
    __nv_bfloat16* s_fib  = (__nv_bfloat16*)(S + O_FIB);
    __nv_bfloat16* s_wbf  = (__nv_bfloat16*)(S + O_WBF);
    __nv_bfloat16* win_bf = s_wbf;
    __nv_bfloat16* wx_bf  = s_wbf + W_IN_SZ;
    __nv_bfloat16* wo_bf  = s_wbf + W_IN_SZ + W_X_SZ;

    static int attr_done = 0;
    if (!attr_done) {
        cudaFuncSetAttribute(fft_fwd_kernel,
                             cudaFuncAttributeMaxDynamicSharedMemorySize, FFT_SMEM);
        cudaFuncSetAttribute(fft_inv_kernel,
                             cudaFuncAttributeMaxDynamicSharedMemorySize, FFT_SMEM);
        cudaFuncSetAttribute(gemm_bf16,
                             cudaFuncAttributeMaxDynamicSharedMemorySize, GEMM_SMEM);
        cudaFuncSetAttribute(scan_kernel,
                             cudaFuncAttributeMaxDynamicSharedMemorySize, SCAN_SMEM);
        attr_done = 1;
    }

    // 0) prep: weight convert + LN1 (merged, independent halves)
    prep_kernel<<<WCVT_BLOCKS + NTOK / 8, 256>>>(in_proj_w, x_proj_w, out_proj_w,
                                                 s_wbf, x, norm1_w, norm1_b, s_xnbf);
    // 1) in_proj -> bf16 xz
    gemm_bf16<<<dim3((2 * DI) / GBN, NTOK / GBM), 256, GEMM_SMEM>>>(
        s_xnbf, win_bf, nullptr, nullptr, s_xzb, NTOK, 2 * DI, DIMC);
    // 2) conv + silu -> bf16 xc only
    conv_silu_kernel<<<(NTOK * DI) / 256, 256>>>(s_xzb, conv_w, conv_b, s_xcbf);
    // 3) x_proj -> fp32 xdbl
    gemm_bf16<<<dim3((XDBLW + GBN - 1) / GBN, NTOK / GBM), 256, GEMM_SMEM>>>(
        s_xcbf, wx_bf, nullptr, s_xdbl, nullptr, NTOK, XDBLW, DI);
    // 4) selective scan -> bf16 y
    scan_kernel<<<BATCH * (DI / 8), 256, SCAN_SMEM>>>(
        s_xdbl, s_xcbf, s_xzb, A_log, Dvec, dt_proj_w, dt_proj_b, s_ybf);
    // 5) out_proj + residual -> fp32 x1
    gemm_bf16<<<dim3(DIMC / GBN, NTOK / GBM), 256, GEMM_SMEM>>>(
        s_ybf, wo_bf, x, s_x1, nullptr, NTOK, DIMC, DI);
    // 6) LN2 -> bf16
    ln_kernel<<<NTOK / 8, 256>>>(s_x1, norm2_w, norm2_b, nullptr, s_xn2b);
    // 7) forward FFT (bf16 in/out)
    fft_fwd_kernel<<<128, 512, FFT_SMEM>>>(s_xn2b, s_frb, s_fib);
    // 8) fused EinFFT MLP (bf16 global I/O)
    einfft_mlp_kernel<<<NTOK / 8, 256>>>(s_frb, s_fib, cw1, cb1, cw2, cb2);
    // 9) inverse FFT + residual -> out
    fft_inv_kernel<<<128, 512, FFT_SMEM>>>(s_frb, s_fib, s_x1, out);
}

// round 15
// speedup vs baseline: 1.6564x; 1.0047x over previous
#include <cuda_runtime.h>
#include <cuda_bf16.h>
#include <stdint.h>
#include <math.h>

// ---------------------------------------------------------------------------
// Problem constants
// ---------------------------------------------------------------------------
#define BATCH   2
#define LSEQ    2048
#define DIMC    256
#define DI      512          // d_inner
#define DS      64           // d_state
#define DTR     16           // dt_rank
#define XDBLW   144          // dt_rank + 2*d_state
#define NTOK    (BATCH*LSEQ) // 4096
#define SQRT_INV_8192 0.011048543456039806f
#define LAMBDA_SS 0.01f
#define PI_F 3.14159265358979323846f

// weight sizes (elems)
#define W_IN_SZ (2*DI*DIMC)   // 262144
#define W_X_SZ  (XDBLW*DI)    // 73728
#define W_O_SZ  (DIMC*DI)     // 131072

// ---------------------------------------------------------------------------
// Scratch (single __device__ array; no allocations anywhere)
// ---------------------------------------------------------------------------
#define O_XDBL  ((size_t)0)                                // fp32 NTOK*XDBLW
#define O_X1    (O_XDBL + (size_t)NTOK*XDBLW)              // fp32 NTOK*DIMC
#define O_XZB   (O_X1   + (size_t)NTOK*DIMC)               // bf16 NTOK*2*DI
#define O_XNBF  (O_XZB  + (size_t)NTOK*DI)                 // bf16 NTOK*DIMC
#define O_XCBF  (O_XNBF + (size_t)NTOK*DIMC/2)             // bf16 NTOK*DI
#define O_YBF   (O_XCBF + (size_t)NTOK*DI/2)               // bf16 NTOK*DI
#define O_XN2B  (O_YBF  + (size_t)NTOK*DI/2)               // bf16 NTOK*DIMC
#define O_FRB   (O_XN2B + (size_t)NTOK*DIMC/2)             // bf16 NTOK*DIMC
#define O_FIB   (O_FRB  + (size_t)NTOK*DIMC/2)             // bf16 NTOK*DIMC
#define O_WBF   (O_FIB  + (size_t)NTOK*DIMC/2)             // bf16 weights
#define O_END   (O_WBF  + (size_t)(W_IN_SZ+W_X_SZ+W_O_SZ)/2 + 64)

__device__ float SCRATCH[O_END];

// ---------------------------------------------------------------------------
// cp.async + f32x2 helpers
// ---------------------------------------------------------------------------
__device__ __forceinline__ void cp16(unsigned dst, const void* src, int sz) {
    asm volatile("cp.async.cg.shared.global [%0], [%1], 16, %2;"
                 :: "r"(dst), "l"(src), "r"(sz));
}
__device__ __forceinline__ void cp_commit() {
    asm volatile("cp.async.commit_group;" ::: "memory");
}
template <int N>
__device__ __forceinline__ void cp_wait() {
    asm volatile("cp.async.wait_group %0;" :: "n"(N) : "memory");
}

typedef unsigned long long u64;
__device__ __forceinline__ u64 packf2(float lo, float hi) {
    u64 r;
    asm("mov.b64 %0, {%1, %2};" : "=l"(r) : "f"(lo), "f"(hi));
    return r;
}
__device__ __forceinline__ void unpackf2(u64 v, float& lo, float& hi) {
    asm("mov.b64 {%0, %1}, %2;" : "=f"(lo), "=f"(hi) : "l"(v));
}
__device__ __forceinline__ void fma2(u64& d, u64 a, u64 b, u64 c) {
    asm("fma.rn.f32x2 %0, %1, %2, %3;" : "=l"(d) : "l"(a), "l"(b), "l"(c));
}

// ---------------------------------------------------------------------------
// LayerNorm body (one warp per token); writes fp32 and/or bf16.
// ---------------------------------------------------------------------------
__device__ __forceinline__ void ln_body(int t, int lane,
                                        const float* __restrict__ x,
                                        const float* __restrict__ w,
                                        const float* __restrict__ b,
                                        float* __restrict__ out,
                                        __nv_bfloat16* __restrict__ obf) {
    const float4* row = (const float4*)(x + (size_t)t * DIMC);
    float4 v0 = row[lane];
    float4 v1 = row[lane + 32];
    float s = v0.x + v0.y + v0.z + v0.w + v1.x + v1.y + v1.z + v1.w;
    #pragma unroll
    for (int off = 16; off; off >>= 1) s += __shfl_xor_sync(0xffffffffu, s, off);
    float m = s * (1.0f / 256.0f);
    float d0 = v0.x - m, d1 = v0.y - m, d2 = v0.z - m, d3 = v0.w - m;
    float d4 = v1.x - m, d5 = v1.y - m, d6 = v1.z - m, d7 = v1.w - m;
    float q = d0*d0 + d1*d1 + d2*d2 + d3*d3 + d4*d4 + d5*d5 + d6*d6 + d7*d7;
    #pragma unroll
    for (int off = 16; off; off >>= 1) q += __shfl_xor_sync(0xffffffffu, q, off);
    float inv = rsqrtf(q * (1.0f / 256.0f) + 1e-5f);
    const float4* w4 = (const float4*)w;
    const float4* b4 = (const float4*)b;
    float4 wa = w4[lane], ba = b4[lane];
    float4 wb = w4[lane + 32], bb = b4[lane + 32];
    float4 r0, r1;
    r0.x = d0*inv*wa.x + ba.x; r0.y = d1*inv*wa.y + ba.y;
    r0.z = d2*inv*wa.z + ba.z; r0.w = d3*inv*wa.w + ba.w;
    r1.x = d4*inv*wb.x + bb.x; r1.y = d5*inv*wb.y + bb.y;
    r1.z = d6*inv*wb.z + bb.z; r1.w = d7*inv*wb.w + bb.w;
    if (out) {
        float4* o4 = (float4*)(out + (size_t)t * DIMC);
        o4[lane] = r0; o4[lane + 32] = r1;
    }
    if (obf) {
        __nv_bfloat162* o2 = (__nv_bfloat162*)(obf + (size_t)t * DIMC);
        o2[lane*2]      = __nv_bfloat162(__float2bfloat16_rn(r0.x), __float2bfloat16_rn(r0.y));
        o2[lane*2 + 1]  = __nv_bfloat162(__float2bfloat16_rn(r0.z), __float2bfloat16_rn(r0.w));
        o2[64 + lane*2]     = __nv_bfloat162(__float2bfloat16_rn(r1.x), __float2bfloat16_rn(r1.y));
        o2[64 + lane*2 + 1] = __nv_bfloat162(__float2bfloat16_rn(r1.z), __float2bfloat16_rn(r1.w));
    }
}

// ---------------------------------------------------------------------------
// Prep: weight fp32->bf16 convert (blocks 0..295) + LN1 (blocks 296..807).
// ---------------------------------------------------------------------------
#define WCVT_BLOCKS 296
__global__ void prep_kernel(const float* __restrict__ w_in,
                            const float* __restrict__ w_x,
                            const float* __restrict__ w_o,
                            __nv_bfloat16* __restrict__ wdst,
                            const float* __restrict__ x,
                            const float* __restrict__ n1w,
                            const float* __restrict__ n1b,
                            __nv_bfloat16* __restrict__ xnbf) {
    if (blockIdx.x < WCVT_BLOCKS) {
        int total = W_IN_SZ + W_X_SZ + W_O_SZ;
        for (int i = blockIdx.x * 256 + threadIdx.x; i < total;
             i += WCVT_BLOCKS * 256) {
            float v;
            if (i < W_IN_SZ) v = w_in[i];
            else if (i < W_IN_SZ + W_X_SZ) v = w_x[i - W_IN_SZ];
            else v = w_o[i - W_IN_SZ - W_X_SZ];
            wdst[i] = __float2bfloat16_rn(v);
        }
    } else {
        int t = (blockIdx.x - WCVT_BLOCKS) * 8 + (threadIdx.x >> 5);
        ln_body(t, threadIdx.x & 31, x, n1w, n1b, nullptr, xnbf);
    }
}

// LN2 standalone
__global__ void ln_kernel(const float* __restrict__ x,
                          const float* __restrict__ w,
                          const float* __restrict__ b,
                          float* __restrict__ out,
                          __nv_bfloat16* __restrict__ obf) {
    ln_body(blockIdx.x * 8 + (threadIdx.x >> 5), threadIdx.x & 31,
            x, w, b, out, obf);
}

// ---------------------------------------------------------------------------
// bf16 tensor-core GEMM: out = A[M,K] * W[N,K]^T (+ R).  Output fp32 or bf16.
// ---------------------------------------------------------------------------
#define GBM 128
#define GBN 64
#define BK  32
#define HSTR 40
#define GSTAGES 4
#define GEMM_SMEM (GSTAGES * (GBM + GBN) * HSTR * 2)

__device__ __forceinline__ void mma_bf16(float* c, const unsigned* a, const unsigned* b) {
    asm volatile(
        "mma.sync.aligned.m16n8k16.row.col.f32.bf16.bf16.f32 "
        "{%0,%1,%2,%3}, {%4,%5,%6,%7}, {%8,%9}, {%0,%1,%2,%3};"
        : "+f"(c[0]), "+f"(c[1]), "+f"(c[2]), "+f"(c[3])
        : "r"(a[0]), "r"(a[1]), "r"(a[2]), "r"(a[3]), "r"(b[0]), "r"(b[1]));
}

__global__ void __launch_bounds__(256) gemm_bf16(const __nv_bfloat16* __restrict__ A,
                                                 const __nv_bfloat16* __restrict__ W,
                                                 const float* __restrict__ R,
                                                 float* __restrict__ C,
                                                 __nv_bfloat16* __restrict__ Cbf,
                                                 int M, int N, int K) {
    extern __shared__ __nv_bfloat16 hsm[];
    __nv_bfloat16* As = hsm;
    __nv_bfloat16* Bs = hsm + GSTAGES * GBM * HSTR;
    unsigned smA = (unsigned)__cvta_generic_to_shared(As);
    unsigned smB = (unsigned)__cvta_generic_to_shared(Bs);

    int m0 = blockIdx.y * GBM;
    int n0 = blockIdx.x * GBN;
    int tid = threadIdx.x;
    int wid = tid >> 5, lane = tid & 31;
    int wm = (wid & 3) * 32;
    int wn = (wid >> 2) * 32;
    int gid = lane >> 2;
    int tig = lane & 3;
    int ar = tid >> 1, akq = (tid & 1) * 16;
    int br = tid >> 2, bkq = (tid & 3) * 8;

    const __nv_bfloat16* Abase = A + (size_t)(m0 + ar) * K + akq;
    bool bok = (n0 + br) < N;
    const __nv_bfloat16* Bbase = bok ? (W + (size_t)(n0 + br) * K + bkq) : W;
    int bsz = bok ? 16 : 0;
    unsigned adst = smA + (unsigned)(ar * HSTR + akq) * 2u;
    unsigned bdst = smB + (unsigned)(br * HSTR + bkq) * 2u;
    const unsigned aStage = GBM * HSTR * 2u;
    const unsigned bStage = GBN * HSTR * 2u;

    float acc[2][4][4];
    #pragma unroll
    for (int mi = 0; mi < 2; mi++)
        #pragma unroll
        for (int ni = 0; ni < 4; ni++)
            #pragma unroll
            for (int q = 0; q < 4; q++) acc[mi][ni][q] = 0.0f;

    int nIt = K / BK;
    #pragma unroll
    for (int s = 0; s < GSTAGES - 1; s++) {
        cp16(adst + s * aStage,      Abase + s * BK,     16);
        cp16(adst + s * aStage + 16, Abase + s * BK + 8, 16);
        cp16(bdst + s * bStage,      Bbase + (bok ? s * BK : 0), bsz);
        cp_commit();
    }

    for (int it = 0; it < nIt; it++) {
        cp_wait<GSTAGES - 2>();
        __syncthreads();
        int buf = it & (GSTAGES - 1);
        const __nv_bfloat16* Ab = As + buf * (GBM * HSTR);
        const __nv_bfloat16* Bb = Bs + buf * (GBN * HSTR);
        #pragma unroll
        for (int ks = 0; ks < 2; ks++) {
            int k16 = ks * 16;
            unsigned afr[2][4], bfr[4][2];
            #pragma unroll
            for (int mi = 0; mi < 2; mi++) {
                int rb = wm + mi * 16 + gid;
                afr[mi][0] = *(const unsigned*)(Ab + (rb)     * HSTR + k16 + tig * 2);
                afr[mi][1] = *(const unsigned*)(Ab + (rb + 8) * HSTR + k16 + tig * 2);
                afr[mi][2] = *(const unsigned*)(Ab + (rb)     * HSTR + k16 + tig * 2 + 8);
                afr[mi][3] = *(const unsigned*)(Ab + (rb + 8) * HSTR + k16 + tig * 2 + 8);
            }
            #pragma unroll
            for (int ni = 0; ni < 4; ni++) {
                int cb = wn + ni * 8 + gid;
                bfr[ni][0] = *(const unsigned*)(Bb + cb * HSTR + k16 + tig * 2);
                bfr[ni][1] = *(const unsigned*)(Bb + cb * HSTR + k16 + tig * 2 + 8);
            }
            #pragma unroll
            for (int mi = 0; mi < 2; mi++)
                #pragma unroll
                for (int ni = 0; ni < 4; ni++)
                    mma_bf16(acc[mi][ni], afr[mi], bfr[ni]);
        }
        int nx = it + GSTAGES - 1;
        if (nx < nIt) {
            int slot = nx & (GSTAGES - 1);
            cp16(adst + slot * aStage,      Abase + nx * BK,     16);
            cp16(adst + slot * aStage + 16, Abase + nx * BK + 8, 16);
            cp16(bdst + slot * bStage,      Bbase + (bok ? nx * BK : 0), bsz);
        }
        cp_commit();
    }

    #pragma unroll
    for (int mi = 0; mi < 2; mi++) {
        int row = m0 + wm + mi * 16 + gid;
        #pragma unroll
        for (int ni = 0; ni < 4; ni++) {
            int col = n0 + wn + ni * 8 + tig * 2;
            #pragma unroll
            for (int half = 0; half < 2; half++) {
                int rr = row + half * 8;
                float v0 = acc[mi][ni][half * 2];
                float v1 = acc[mi][ni][half * 2 + 1];
                if (col < N) {
                    if (Cbf) Cbf[(size_t)rr * N + col] = __float2bfloat16_rn(v0);
                    else {
                        if (R) v0 += R[(size_t)rr * N + col];
                        C[(size_t)rr * N + col] = v0;
                    }
                }
                if (col + 1 < N) {
                    if (Cbf) Cbf[(size_t)rr * N + col + 1] = __float2bfloat16_rn(v1);
                    else {
                        if (R) v1 += R[(size_t)rr * N + col + 1];
                        C[(size_t)rr * N + col + 1] = v1;
                    }
                }
            }
        }
    }
}

// ---------------------------------------------------------------------------
// Depthwise causal conv (k=4) + bias + SiLU, bf16 in -> bf16 out only.
// ---------------------------------------------------------------------------
__global__ void conv_silu_kernel(const __nv_bfloat16* __restrict__ xzb,
                                 const float* __restrict__ cw,
                                 const float* __restrict__ cb,
                                 __nv_bfloat16* __restrict__ xc_bf) {
    int idx = blockIdx.x * 256 + threadIdx.x;
    int d = idx & (DI - 1);
    int bt = idx >> 9;
    int b = bt >> 11;
    int l = bt & (LSEQ - 1);
    float acc = cb[d];
    #pragma unroll
    for (int k = 0; k < 4; k++) {
        int ls = l + k - 3;
        if (ls >= 0)
            acc += __bfloat162float(xzb[((size_t)((b << 11) | ls)) * (2 * DI) + d])
                   * cw[d * 4 + k];
    }
    float v = acc / (1.0f + __expf(-acc));
    xc_bf[(size_t)bt * DI + d] = __float2bfloat16_rn(v);
}

// ---------------------------------------------------------------------------
// Selective scan: fused dt, deferred reduce-scatter, cp.async double-buffered.
// ---------------------------------------------------------------------------
#define TCHUNK 64
#define SXW 148
#define SCAN_F (2*64*SXW + 512 + 512 + 128 + 8)
#define SCAN_SMEM (SCAN_F * 4 + 2 * (2*64*8*2))

__global__ void __launch_bounds__(256) scan_kernel(
        const float* __restrict__ xdbl,
        const __nv_bfloat16* __restrict__ xcb,
        const __nv_bfloat16* __restrict__ xzb,
        const float* __restrict__ A_log,
        const float* __restrict__ Dvec,
        const float* __restrict__ dtw,
        const float* __restrict__ dtb,
        __nv_bfloat16* __restrict__ y_bf) {
    extern __shared__ float ssm[];
    float* sX   = ssm;                      // [2][64][SXW]
    float* sdt  = sX + 2 * 64 * SXW;        // [64][8]
    float* sy   = sdt + 512;                // [64][8]
    float* sw   = sy + 512;                 // [8][16]
    float* sbias= sw + 128;                 // [8]
    __nv_bfloat16* szb  = (__nv_bfloat16*)(sbias + 8);  // [2][64][8]
    __nv_bfloat16* sxcb = szb + 2 * 64 * 8;             // [2][64][8]
    unsigned aX  = (unsigned)__cvta_generic_to_shared(sX);
    unsigned aZ  = (unsigned)__cvta_generic_to_shared(szb);
    unsigned aXC = (unsigned)__cvta_generic_to_shared(sxcb);

    int b = blockIdx.x >> 6;
    int dbase = (blockIdx.x & 63) * 8;
    int wid = threadIdx.x >> 5;
    int lane = threadIdx.x & 31;
    int d = dbase + wid;
    int tid = threadIdx.x;

    if (tid < 128) {
        int di = tid >> 4, r = tid & 15;
        sw[di * 16 + r] = dtw[(dbase + di) * DTR + r];
        if (r == 0) sbias[di] = dtb[dbase + di];
    }
    float A0 = -__expf(A_log[d * DS + lane]);
    float A1 = -__expf(A_log[d * DS + lane + 32]);
    float Dd = Dvec[d];
    float h0 = 0.0f, h1 = 0.0f;

    auto stage = [&](int buf, int t0) {
        size_t rowbase = (size_t)(b * LSEQ + t0);
        for (int i = tid; i < 64 * 36; i += 256) {
            int tt = i / 36, q = i - tt * 36;
            cp16(aX + (unsigned)(((buf * 64 + tt) * SXW) + q * 4) * 4u,
                 xdbl + (rowbase + tt) * XDBLW + q * 4, 16);
        }
        if (tid < 128) {
            int tt = tid & 63;
            if (tid < 64)
                cp16(aXC + (unsigned)((buf * 64 + tt) * 8) * 2u,
                     xcb + (rowbase + tt) * DI + dbase, 16);
            else
                cp16(aZ + (unsigned)((buf * 64 + tt) * 8) * 2u,
                     xzb + (rowbase + tt) * (2 * DI) + DI + dbase, 16);
        }
    };

    stage(0, 0);
    cp_commit();

    for (int c = 0; c < LSEQ / TCHUNK; c++) {
        int buf = c & 1;
        cp_wait<0>();
        __syncthreads();
        if (c + 1 < LSEQ / TCHUNK) stage(buf ^ 1, (c + 1) * TCHUNK);
        cp_commit();

        for (int i = tid; i < 512; i += 256) {
            int tt = i >> 3, di = i & 7;
            const float* xr = sX + (buf * 64 + tt) * SXW;
            float acc = sbias[di];
            #pragma unroll
            for (int r = 0; r < 16; r++) acc = fmaf(xr[r], sw[di * 16 + r], acc);
            sdt[tt * 8 + di] = (acc > 20.0f) ? acc : __logf(1.0f + __expf(acc));
        }
        __syncthreads();

        #pragma unroll 1
        for (int g = 0; g < TCHUNK / 32; g++) {
            float part[32];
            #pragma unroll
            for (int j = 0; j < 32; j++) {
                int tt = g * 32 + j;
                const float* xr = sX + (buf * 64 + tt) * SXW;
                float dtv = sdt[tt * 8 + wid];
                float xcv = __bfloat162float(sxcb[(buf * 64 + tt) * 8 + wid]);
                float du = dtv * xcv;
                float dA0 = __expf(dtv * A0);
                float dA1 = __expf(dtv * A1);
                h0 = fmaf(dA0, h0, du * xr[16 + lane]);
                h1 = fmaf(dA1, h1, du * xr[48 + lane]);
                part[j] = fmaf(h0, xr[80 + lane], h1 * xr[112 + lane]);
            }
            #pragma unroll
            for (int s = 16; s >= 1; s >>= 1) {
                bool up = (lane & s) != 0;
                #pragma unroll
                for (int i2 = 0; i2 < 16; i2++) {
                    if (i2 >= s) break;
                    float keep = up ? part[i2 + s] : part[i2];
                    float send = up ? part[i2] : part[i2 + s];
                    part[i2] = keep + __shfl_xor_sync(0xffffffffu, send, s);
                }
            }
            int tt = g * 32 + lane;
            float xcv = __bfloat162float(sxcb[(buf * 64 + tt) * 8 + wid]);
            float zv = __bfloat162float(szb[(buf * 64 + tt) * 8 + wid]);
            float gate = zv / (1.0f + __expf(-zv));
            sy[tt * 8 + wid] = fmaf(xcv, Dd, part[0]) * gate;
        }
        __syncthreads();
        for (int i = tid; i < TCHUNK * 8; i += 256) {
            int tt = i >> 3, di = i & 7;
            y_bf[(size_t)(b * LSEQ + c * TCHUNK + tt) * DI + dbase + di] =
                __float2bfloat16_rn(sy[tt * 8 + di]);
        }
        __syncthreads();
    }
}

// ---------------------------------------------------------------------------
// Forward 2048-pt FFT (DIF), bf16 real input -> bf16 spectrum.
// ---------------------------------------------------------------------------
#define FSTR 2049
#define FFT_SMEM (2 * 4 * FSTR * 4)

__global__ void __launch_bounds__(512) fft_fwd_kernel(const __nv_bfloat16* __restrict__ xin,
                                                      __nv_bfloat16* __restrict__ dR,
                                                      __nv_bfloat16* __restrict__ dI) {
    extern __shared__ float sm[];
    float* sr = sm;
    float* si = sm + 4 * FSTR;
    int b = blockIdx.x >> 6;
    int c0 = (blockIdx.x & 63) * 4;
    size_t base = (size_t)b * LSEQ * DIMC + c0;
    int tid = threadIdx.x;

    for (int n = tid; n < 2048; n += 512) {
        const __nv_bfloat162* p = (const __nv_bfloat162*)(xin + base + (size_t)n * DIMC);
        __nv_bfloat162 a = p[0], bb = p[1];
        sr[0 * FSTR + n] = __bfloat162float(a.x);
        sr[1 * FSTR + n] = __bfloat162float(a.y);
        sr[2 * FSTR + n] = __bfloat162float(bb.x);
        sr[3 * FSTR + n] = __bfloat162float(bb.y);
        si[0 * FSTR + n] = 0.0f; si[1 * FSTR + n] = 0.0f;
        si[2 * FSTR + n] = 0.0f; si[3 * FSTR + n] = 0.0f;
    }
    __syncthreads();

    #pragma unroll
    for (int hb = 10; hb >= 0; hb--) {
        int half = 1 << hb;
        float th = -PI_F / (float)half;
        for (int e = tid; e < 4096; e += 512) {
            int col = e >> 10, idx = e & 1023;
            int j = idx & (half - 1);
            int pos = ((idx >> hb) << (hb + 1)) + j;
            float* cr = sr + col * FSTR;
            float* ci = si + col * FSTR;
            float ar = cr[pos],        ai = ci[pos];
            float br = cr[pos + half], bi = ci[pos + half];
            float wi, wr;
            __sincosf(th * (float)j, &wi, &wr);
            float xr = ar - br, xi = ai - bi;
            cr[pos] = ar + br;  ci[pos] = ai + bi;
            cr[pos + half] = xr * wr - xi * wi;
            ci[pos + half] = xr * wi + xi * wr;
        }
        __syncthreads();
    }

    for (int n = tid; n < 2048; n += 512) {
        __nv_bfloat162* pr = (__nv_bfloat162*)(dR + base + (size_t)n * DIMC);
        __nv_bfloat162* pi = (__nv_bfloat162*)(dI + base + (size_t)n * DIMC);
        pr[0] = __nv_bfloat162(__float2bfloat16_rn(sr[0 * FSTR + n]),
                               __float2bfloat16_rn(sr[1 * FSTR + n]));
        pr[1] = __nv_bfloat162(__float2bfloat16_rn(sr[2 * FSTR + n]),
                               __float2bfloat16_rn(sr[3 * FSTR + n]));
        pi[0] = __nv_bfloat162(__float2bfloat16_rn(si[0 * FSTR + n]),
                               __float2bfloat16_rn(si[1 * FSTR + n]));
        pi[1] = __nv_bfloat162(__float2bfloat16_rn(si[2 * FSTR + n]),
                               __float2bfloat16_rn(si[3 * FSTR + n]));
    }
}

// ---------------------------------------------------------------------------
// Inverse 2048-pt FFT (DIT) from bf16 spectrum; real part + fp32 residual.
// ---------------------------------------------------------------------------
__global__ void __launch_bounds__(512) fft_inv_kernel(const __nv_bfloat16* __restrict__ dR,
                                                      const __nv_bfloat16* __restrict__ dI,
                                                      const float* __restrict__ x1,
                                                      float* __restrict__ out) {
    extern __shared__ float sm[];
    float* sr = sm;
    float* si = sm + 4 * FSTR;
    int b = blockIdx.x >> 6;
    int c0 = (blockIdx.x & 63) * 4;
    size_t base = (size_t)b * LSEQ * DIMC + c0;
    int tid = threadIdx.x;

    for (int n = tid; n < 2048; n += 512) {
        const __nv_bfloat162* pr = (const __nv_bfloat162*)(dR + base + (size_t)n * DIMC);
        const __nv_bfloat162* pi = (const __nv_bfloat162*)(dI + base + (size_t)n * DIMC);
        __nv_bfloat162 r0 = pr[0], r1 = pr[1], i0 = pi[0], i1 = pi[1];
        sr[0 * FSTR + n] = __bfloat162float(r0.x);
        sr[1 * FSTR + n] = __bfloat162float(r0.y);
        sr[2 * FSTR + n] = __bfloat162float(r1.x);
        sr[3 * FSTR + n] = __bfloat162float(r1.y);
        si[0 * FSTR + n] = __bfloat162float(i0.x);
        si[1 * FSTR + n] = __bfloat162float(i0.y);
        si[2 * FSTR + n] = __bfloat162float(i1.x);
        si[3 * FSTR + n] = __bfloat162float(i1.y);
    }
    __syncthreads();

    #pragma unroll
    for (int hb = 0; hb <= 10; hb++) {
        int half = 1 << hb;
        float th = PI_F / (float)half;
        for (int e = tid; e < 4096; e += 512) {
            int col = e >> 10, idx = e & 1023;
            int j = idx & (half - 1);
            int pos = ((idx >> hb) << (hb + 1)) + j;
            float* cr = sr + col * FSTR;
            float* ci = si + col * FSTR;
            float ar = cr[pos],        ai = ci[pos];
            float br = cr[pos + half], bi = ci[pos + half];
            float wi, wr;
            __sincosf(th * (float)j, &wi, &wr);
            float tr = br * wr - bi * wi;
            float ti = br * wi + bi * wr;
            cr[pos] = ar + tr;         ci[pos] = ai + ti;
            cr[pos + half] = ar - tr;  ci[pos + half] = ai - ti;
        }
        __syncthreads();
    }

    for (int n = tid; n < 2048; n += 512) {
        size_t a = base + (size_t)n * DIMC;
        float4 rx = *(const float4*)(x1 + a);
        float4 o;
        o.x = rx.x + sr[0 * FSTR + n];
        o.y = rx.y + sr[1 * FSTR + n];
        o.z = rx.z + sr[2 * FSTR + n];
        o.w = rx.w + sr[3 * FSTR + n];
        *(float4*)(out + a) = o;
    }
}

// ---------------------------------------------------------------------------
// EinFFT MLP with DFT4/IDFT4 folded in; bf16 global I/O, f32x2 packed FMA
// over the dd dimension (pairs), fp32 accumulation.
// ---------------------------------------------------------------------------
__global__ void __launch_bounds__(256) einfft_mlp_kernel(
        __nv_bfloat16* __restrict__ fR, __nv_bfloat16* __restrict__ fI,
        const float* __restrict__ cw1, const float* __restrict__ cb1,
        const float* __restrict__ cw2, const float* __restrict__ cb2) {
    __shared__ __align__(16) float sR[2048], sI[2048];
    __shared__ __align__(16) float tR[2048], tI[2048];
    int row0 = blockIdx.x * 8;
    int tid = threadIdx.x;
    {
        const __nv_bfloat162* fr2 = (const __nv_bfloat162*)(fR + (size_t)row0 * DIMC);
        const __nv_bfloat162* fi2 = (const __nv_bfloat162*)(fI + (size_t)row0 * DIMC);
        for (int i = tid; i < 1024; i += 256) {
            __nv_bfloat162 r = fr2[i], m = fi2[i];
            sR[2*i] = __bfloat162float(r.x); sR[2*i+1] = __bfloat162float(r.y);
            sI[2*i] = __bfloat162float(m.x); sI[2*i+1] = __bfloat162float(m.y);
        }
    }
    __syncthreads();

    const float sc = SQRT_INV_8192;
    #pragma unroll
    for (int g = tid; g < 512; g += 256) {
        int r = g >> 6, s = g & 63;
        int p = r * 256 + s;
        float r0 = sR[p],       i0 = sI[p];
        float r1 = sR[p + 64],  i1 = sI[p + 64];
        float r2 = sR[p + 128], i2 = sI[p + 128];
        float r3 = sR[p + 192], i3 = sI[p + 192];
        sR[p]       = (r0 + r1 + r2 + r3) * sc;
        sI[p]       = (i0 + i1 + i2 + i3) * sc;
        sR[p + 64]  = (r0 + i1 - r2 - i3) * sc;
        sI[p + 64]  = (i0 - r1 - i2 + r3) * sc;
        sR[p + 128] = (r0 - r1 + r2 - r3) * sc;
        sI[p + 128] = (i0 - i1 + i2 - i3) * sc;
        sR[p + 192] = (r0 - i1 - r2 + i3) * sc;
        sI[p + 192] = (i0 + r1 - i2 - r3) * sc;
    }
    __syncthreads();

    int k = tid >> 6, o = tid & 63;

    // ---- layer 1 (relu), f32x2 over dd pairs ----
    {
        const float* w0 = cw1 + k * 4096;
        const float* w1 = cw1 + 16384 + k * 4096;
        float bR = cb1[k * 64 + o];
        float bI = cb1[256 + k * 64 + o];
        u64 aRp[8], aIp[8];
        #pragma unroll
        for (int r = 0; r < 8; r++) {
            aRp[r] = packf2(bR, 0.0f);
            aIp[r] = packf2(bI, 0.0f);
        }
        #pragma unroll 4
        for (int dd = 0; dd < 64; dd += 2) {
            float wa0 = w0[dd * 64 + o], wa1 = w0[(dd + 1) * 64 + o];
            float wb0 = w1[dd * 64 + o], wb1 = w1[(dd + 1) * 64 + o];
            u64 wa_p  = packf2(wa0, wa1);
            u64 wb_p  = packf2(wb0, wb1);
            u64 wbn_p = packf2(-wb0, -wb1);
            int sb = k * 64 + dd;
            #pragma unroll
            for (int r = 0; r < 8; r++) {
                float2 xr2 = *(const float2*)&sR[r * 256 + sb];
                float2 xi2 = *(const float2*)&sI[r * 256 + sb];
                u64 xr_p = packf2(xr2.x, xr2.y);
                u64 xi_p = packf2(xi2.x, xi2.y);
                fma2(aRp[r], xr_p, wa_p, aRp[r]);
                fma2(aRp[r], xi_p, wbn_p, aRp[r]);
                fma2(aIp[r], xr_p, wb_p, aIp[r]);
                fma2(aIp[r], xi_p, wa_p, aIp[r]);
            }
        }
        #pragma unroll
        for (int r = 0; r < 8; r++) {
            float lo, hi;
            unpackf2(aRp[r], lo, hi);
            tR[r * 256 + tid] = fmaxf(lo + hi, 0.0f);
            unpackf2(aIp[r], lo, hi);
            tI[r * 256 + tid] = fmaxf(lo + hi, 0.0f);
        }
    }
    __syncthreads();

    // ---- layer 2 (softshrink), f32x2 over dd pairs ----
    {
        const float* w0 = cw2 + k * 4096;
        const float* w1 = cw2 + 16384 + k * 4096;
        float bR = cb2[k * 64 + o];
        float bI = cb2[256 + k * 64 + o];
        u64 aRp[8], aIp[8];
        #pragma unroll
        for (int r = 0; r < 8; r++) {
            aRp[r] = packf2(bR, 0.0f);
            aIp[r] = packf2(bI, 0.0f);
        }
        #pragma unroll 4
        for (int dd = 0; dd < 64; dd += 2) {
            float wa0 = w0[dd * 64 + o], wa1 = w0[(dd + 1) * 64 + o];
            float wb0 = w1[dd * 64 + o], wb1 = w1[(dd + 1) * 64 + o];
            u64 wa_p  = packf2(wa0, wa1);
            u64 wb_p  = packf2(wb0, wb1);
            u64 wbn_p = packf2(-wb0, -wb1);
            int sb = k * 64 + dd;
            #pragma unroll
            for (int r = 0; r < 8; r++) {
                float2 xr2 = *(const float2*)&tR[r * 256 + sb];
                float2 xi2 = *(const float2*)&tI[r * 256 + sb];
                u64 xr_p = packf2(xr2.x, xr2.y);
                u64 xi_p = packf2(xi2.x, xi2.y);
                fma2(aRp[r], xr_p, wa_p, aRp[r]);
                fma2(aRp[r], xi_p, wbn_p, aRp[r]);
                fma2(aIp[r], xr_p, wb_p, aIp[r]);
                fma2(aIp[r], xi_p, wa_p, aIp[r]);
            }
        }
        #pragma unroll
        for (int r = 0; r < 8; r++) {
            float lo, hi;
            unpackf2(aRp[r], lo, hi);
            float vR = lo + hi;
            unpackf2(aIp[r], lo, hi);
            float vI = lo + hi;
            vR = (vR > LAMBDA_SS) ? vR - LAMBDA_SS
                 : ((vR < -LAMBDA_SS) ? vR + LAMBDA_SS : 0.0f);
            vI = (vI > LAMBDA_SS) ? vI - LAMBDA_SS
                 : ((vI < -LAMBDA_SS) ? vI + LAMBDA_SS : 0.0f);
            sR[r * 256 + tid] = vR;
            sI[r * 256 + tid] = vI;
        }
    }
    __syncthreads();

    #pragma unroll
    for (int g = tid; g < 512; g += 256) {
        int r = g >> 6, s = g & 63;
        int p = r * 256 + s;
        float R0 = sR[p],       I0 = sI[p];
        float R1 = sR[p + 64],  I1 = sI[p + 64];
        float R2 = sR[p + 128], I2 = sI[p + 128];
        float R3 = sR[p + 192], I3 = sI[p + 192];
        sR[p]       = (R0 + R1 + R2 + R3) * sc;
        sI[p]       = (I0 + I1 + I2 + I3) * sc;
        sR[p + 64]  = (R0 - I1 - R2 + I3) * sc;
        sI[p + 64]  = (I0 + R1 - I2 - R3) * sc;
        sR[p + 128] = (R0 - R1 + R2 - R3) * sc;
        sI[p + 128] = (I0 - I1 + I2 - I3) * sc;
        sR[p + 192] = (R0 + I1 - R2 - I3) * sc;
        sI[p + 192] = (I0 - R1 - I2 + R3) * sc;
    }
    __syncthreads();

    {
        __nv_bfloat162* fr2 = (__nv_bfloat162*)(fR + (size_t)row0 * DIMC);
        __nv_bfloat162* fi2 = (__nv_bfloat162*)(fI + (size_t)row0 * DIMC);
        for (int i = tid; i < 1024; i += 256) {
            fr2[i] = __nv_bfloat162(__float2bfloat16_rn(sR[2*i]),
                                    __float2bfloat16_rn(sR[2*i+1]));
            fi2[i] = __nv_bfloat162(__float2bfloat16_rn(sI[2*i]),
                                    __float2bfloat16_rn(sI[2*i+1]));
        }
    }
}

// ---------------------------------------------------------------------------
// Launch
// ---------------------------------------------------------------------------
extern "C" void kernel_launch(void* const* d_in, const int* in_sizes, int n_in,
                              void* d_out, int out_size) {
    const float* x         = (const float*)d_in[0];
    const float* norm1_w   = (const float*)d_in[1];
    const float* norm1_b   = (const float*)d_in[2];
    const float* in_proj_w = (const float*)d_in[3];
    const float* conv_w    = (const float*)d_in[4];
    const float* conv_b    = (const float*)d_in[5];
    const float* x_proj_w  = (const float*)d_in[6];
    const float* dt_proj_w = (const float*)d_in[7];
    const float* dt_proj_b = (const float*)d_in[8];
    const float* A_log     = (const float*)d_in[9];
    const float* Dvec      = (const float*)d_in[10];
    const float* out_proj_w= (const float*)d_in[11];
    const float* norm2_w   = (const float*)d_in[12];
    const float* norm2_b   = (const float*)d_in[13];
    const float* cw1       = (const float*)d_in[14];
    const float* cb1       = (const float*)d_in[15];
    const float* cw2       = (const float*)d_in[16];
    const float* cb2       = (const float*)d_in[17];
    float* out = (float*)d_out;

    void* sp = nullptr;
    cudaGetSymbolAddress(&sp, SCRATCH);
    float* S = (float*)sp;
    float* s_xdbl = S + O_XDBL;
    float* s_x1   = S + O_X1;
    __nv_bfloat16* s_xzb  = (__nv_bfloat16*)(S + O_XZB);
    __nv_bfloat16* s_xnbf = (__nv_bfloat16*)(S + O_XNBF);
    __nv_bfloat16* s_xcbf = (__nv_bfloat16*)(S + O_XCBF);
    __nv_bfloat16* s_ybf  = (__nv_bfloat16*)(S + O_YBF);
    __nv_bfloat16* s_xn2b = (__nv_bfloat16*)(S + O_XN2B);
    __nv_bfloat16* s_frb  = (__nv_bfloat16*)(S + O_FRB);
    __nv_bfloat16* s_fib  = (__nv_bfloat16*)(S + O_FIB);
    __nv_bfloat16* s_wbf  = (__nv_bfloat16*)(S + O_WBF);
    __nv_bfloat16* win_bf = s_wbf;
    __nv_bfloat16* wx_bf  = s_wbf + W_IN_SZ;
    __nv_bfloat16* wo_bf  = s_wbf + W_IN_SZ + W_X_SZ;

    static int attr_done = 0;
    if (!attr_done) {
        cudaFuncSetAttribute(fft_fwd_kernel,
                             cudaFuncAttributeMaxDynamicSharedMemorySize, FFT_SMEM);
        cudaFuncSetAttribute(fft_inv_kernel,
                             cudaFuncAttributeMaxDynamicSharedMemorySize, FFT_SMEM);
        cudaFuncSetAttribute(gemm_bf16,
                             cudaFuncAttributeMaxDynamicSharedMemorySize, GEMM_SMEM);
        cudaFuncSetAttribute(scan_kernel,
                             cudaFuncAttributeMaxDynamicSharedMemorySize, SCAN_SMEM);
        attr_done = 1;
    }

    // 0) prep: weight convert + LN1 (merged)
    prep_kernel<<<WCVT_BLOCKS + NTOK / 8, 256>>>(in_proj_w, x_proj_w, out_proj_w,
                                                 s_wbf, x, norm1_w, norm1_b, s_xnbf);
    // 1) in_proj -> bf16 xz
    gemm_bf16<<<dim3((2 * DI) / GBN, NTOK / GBM), 256, GEMM_SMEM>>>(
        s_xnbf, win_bf, nullptr, nullptr, s_xzb, NTOK, 2 * DI, DIMC);
    // 2) conv + silu -> bf16 xc
    conv_silu_kernel<<<(NTOK * DI) / 256, 256>>>(s_xzb, conv_w, conv_b, s_xcbf);
    // 3) x_proj -> fp32 xdbl
    gemm_bf16<<<dim3((XDBLW + GBN - 1) / GBN, NTOK / GBM), 256, GEMM_SMEM>>>(
        s_xcbf, wx_bf, nullptr, s_xdbl, nullptr, NTOK, XDBLW, DI);
    // 4) selective scan -> bf16 y
    scan_kernel<<<BATCH * (DI / 8), 256, SCAN_SMEM>>>(
        s_xdbl, s_xcbf, s_xzb, A_log, Dvec, dt_proj_w, dt_proj_b, s_ybf);
    // 5) out_proj + residual -> fp32 x1
    gemm_bf16<<<dim3(DIMC / GBN, NTOK / GBM), 256, GEMM_SMEM>>>(
        s_ybf, wo_bf, x, s_x1, nullptr, NTOK, DIMC, DI);
    // 6) LN2 -> bf16
    ln_kernel<<<NTOK / 8, 256>>>(s_x1, norm2_w, norm2_b, nullptr, s_xn2b);
    // 7) forward FFT (bf16 in/out)
    fft_fwd_kernel<<<128, 512, FFT_SMEM>>>(s_xn2b, s_frb, s_fib);
    // 8) fused EinFFT MLP (f32x2 packed FMA)
    einfft_mlp_kernel<<<NTOK / 8, 256>>>(s_frb, s_fib, cw1, cb1, cw2, cb2);
    // 9) inverse FFT + residual -> out
    fft_inv_kernel<<<128, 512, FFT_SMEM>>>(s_frb, s_fib, s_x1, out);
}

// round 16
// speedup vs baseline: 1.6882x; 1.0192x over previous
#include <cuda_runtime.h>
#include <cuda_bf16.h>
#include <stdint.h>
#include <math.h>

// ---------------------------------------------------------------------------
// Problem constants
// ---------------------------------------------------------------------------
#define BATCH   2
#define LSEQ    2048
#define DIMC    256
#define DI      512          // d_inner
#define DS      64           // d_state
#define DTR     16           // dt_rank
#define XDBLW   144          // dt_rank + 2*d_state
#define NTOK    (BATCH*LSEQ) // 4096
#define SQRT_INV_8192 0.011048543456039806f
#define LAMBDA_SS 0.01f
#define PI_F 3.14159265358979323846f

// weight sizes (elems)
#define W_IN_SZ (2*DI*DIMC)   // 262144
#define W_X_SZ  (XDBLW*DI)    // 73728
#define W_O_SZ  (DIMC*DI)     // 131072

// ---------------------------------------------------------------------------
// Scratch (single __device__ array; no allocations anywhere)
// ---------------------------------------------------------------------------
#define O_XDBL  ((size_t)0)                                // fp32 NTOK*XDBLW
#define O_X1    (O_XDBL + (size_t)NTOK*XDBLW)              // fp32 NTOK*DIMC
#define O_XZB   (O_X1   + (size_t)NTOK*DIMC)               // bf16 NTOK*2*DI
#define O_XNBF  (O_XZB  + (size_t)NTOK*DI)                 // bf16 NTOK*DIMC
#define O_XCBF  (O_XNBF + (size_t)NTOK*DIMC/2)             // bf16 NTOK*DI
#define O_YBF   (O_XCBF + (size_t)NTOK*DI/2)               // bf16 NTOK*DI
#define O_XN2B  (O_YBF  + (size_t)NTOK*DI/2)               // bf16 NTOK*DIMC
#define O_FRB   (O_XN2B + (size_t)NTOK*DIMC/2)             // bf16 NTOK*DIMC
#define O_FIB   (O_FRB  + (size_t)NTOK*DIMC/2)             // bf16 NTOK*DIMC
#define O_WBF   (O_FIB  + (size_t)NTOK*DIMC/2)             // bf16 weights
#define O_END   (O_WBF  + (size_t)(W_IN_SZ+W_X_SZ+W_O_SZ)/2 + 64)

__device__ float SCRATCH[O_END];

// ---------------------------------------------------------------------------
// cp.async + f32x2 helpers
// ---------------------------------------------------------------------------
__device__ __forceinline__ void cp16(unsigned dst, const void* src, int sz) {
    asm volatile("cp.async.cg.shared.global [%0], [%1], 16, %2;"
                 :: "r"(dst), "l"(src), "r"(sz));
}
__device__ __forceinline__ void cp_commit() {
    asm volatile("cp.async.commit_group;" ::: "memory");
}
template <int N>
__device__ __forceinline__ void cp_wait() {
    asm volatile("cp.async.wait_group %0;" :: "n"(N) : "memory");
}

typedef unsigned long long u64;
__device__ __forceinline__ u64 packf2(float lo, float hi) {
    u64 r;
    asm("mov.b64 %0, {%1, %2};" : "=l"(r) : "f"(lo), "f"(hi));
    return r;
}
__device__ __forceinline__ void unpackf2(u64 v, float& lo, float& hi) {
    asm("mov.b64 {%0, %1}, %2;" : "=f"(lo), "=f"(hi) : "l"(v));
}
__device__ __forceinline__ void fma2(u64& d, u64 a, u64 b, u64 c) {
    asm("fma.rn.f32x2 %0, %1, %2, %3;" : "=l"(d) : "l"(a), "l"(b), "l"(c));
}
// 11-bit bit reversal (positions 0..2047)
__device__ __forceinline__ int rev11(int p) {
    return (int)(__brev((unsigned)p) >> 21);
}

// ---------------------------------------------------------------------------
// LayerNorm body (one warp per token); writes fp32 and/or bf16.
// ---------------------------------------------------------------------------
__device__ __forceinline__ void ln_body(int t, int lane,
                                        const float* __restrict__ x,
                                        const float* __restrict__ w,
                                        const float* __restrict__ b,
                                        float* __restrict__ out,
                                        __nv_bfloat16* __restrict__ obf) {
    const float4* row = (const float4*)(x + (size_t)t * DIMC);
    float4 v0 = row[lane];
    float4 v1 = row[lane + 32];
    float s = v0.x + v0.y + v0.z + v0.w + v1.x + v1.y + v1.z + v1.w;
    #pragma unroll
    for (int off = 16; off; off >>= 1) s += __shfl_xor_sync(0xffffffffu, s, off);
    float m = s * (1.0f / 256.0f);
    float d0 = v0.x - m, d1 = v0.y - m, d2 = v0.z - m, d3 = v0.w - m;
    float d4 = v1.x - m, d5 = v1.y - m, d6 = v1.z - m, d7 = v1.w - m;
    float q = d0*d0 + d1*d1 + d2*d2 + d3*d3 + d4*d4 + d5*d5 + d6*d6 + d7*d7;
    #pragma unroll
    for (int off = 16; off; off >>= 1) q += __shfl_xor_sync(0xffffffffu, q, off);
    float inv = rsqrtf(q * (1.0f / 256.0f) + 1e-5f);
    const float4* w4 = (const float4*)w;
    const float4* b4 = (const float4*)b;
    float4 wa = w4[lane], ba = b4[lane];
    float4 wb = w4[lane + 32], bb = b4[lane + 32];
    float4 r0, r1;
    r0.x = d0*inv*wa.x + ba.x; r0.y = d1*inv*wa.y + ba.y;
    r0.z = d2*inv*wa.z + ba.z; r0.w = d3*inv*wa.w + ba.w;
    r1.x = d4*inv*wb.x + bb.x; r1.y = d5*inv*wb.y + bb.y;
    r1.z = d6*inv*wb.z + bb.z; r1.w = d7*inv*wb.w + bb.w;
    if (out) {
        float4* o4 = (float4*)(out + (size_t)t * DIMC);
        o4[lane] = r0; o4[lane + 32] = r1;
    }
    if (obf) {
        __nv_bfloat162* o2 = (__nv_bfloat162*)(obf + (size_t)t * DIMC);
        o2[lane*2]      = __nv_bfloat162(__float2bfloat16_rn(r0.x), __float2bfloat16_rn(r0.y));
        o2[lane*2 + 1]  = __nv_bfloat162(__float2bfloat16_rn(r0.z), __float2bfloat16_rn(r0.w));
        o2[64 + lane*2]     = __nv_bfloat162(__float2bfloat16_rn(r1.x), __float2bfloat16_rn(r1.y));
        o2[64 + lane*2 + 1] = __nv_bfloat162(__float2bfloat16_rn(r1.z), __float2bfloat16_rn(r1.w));
    }
}

// ---------------------------------------------------------------------------
// Prep: weight fp32->bf16 convert (blocks 0..295) + LN1 (blocks 296..807).
// ---------------------------------------------------------------------------
#define WCVT_BLOCKS 296
__global__ void prep_kernel(const float* __restrict__ w_in,
                            const float* __restrict__ w_x,
                            const float* __restrict__ w_o,
                            __nv_bfloat16* __restrict__ wdst,
                            const float* __restrict__ x,
                            const float* __restrict__ n1w,
                            const float* __restrict__ n1b,
                            __nv_bfloat16* __restrict__ xnbf) {
    if (blockIdx.x < WCVT_BLOCKS) {
        int total = W_IN_SZ + W_X_SZ + W_O_SZ;
        for (int i = blockIdx.x * 256 + threadIdx.x; i < total;
             i += WCVT_BLOCKS * 256) {
            float v;
            if (i < W_IN_SZ) v = w_in[i];
            else if (i < W_IN_SZ + W_X_SZ) v = w_x[i - W_IN_SZ];
            else v = w_o[i - W_IN_SZ - W_X_SZ];
            wdst[i] = __float2bfloat16_rn(v);
        }
    } else {
        int t = (blockIdx.x - WCVT_BLOCKS) * 8 + (threadIdx.x >> 5);
        ln_body(t, threadIdx.x & 31, x, n1w, n1b, nullptr, xnbf);
    }
}

// LN2 standalone
__global__ void ln_kernel(const float* __restrict__ x,
                          const float* __restrict__ w,
                          const float* __restrict__ b,
                          float* __restrict__ out,
                          __nv_bfloat16* __restrict__ obf) {
    ln_body(blockIdx.x * 8 + (threadIdx.x >> 5), threadIdx.x & 31,
            x, w, b, out, obf);
}

// ---------------------------------------------------------------------------
// bf16 tensor-core GEMM: out = A[M,K] * W[N,K]^T (+ R).  Output fp32 or bf16.
// ---------------------------------------------------------------------------
#define GBM 128
#define GBN 64
#define BK  32
#define HSTR 40
#define GSTAGES 4
#define GEMM_SMEM (GSTAGES * (GBM + GBN) * HSTR * 2)

__device__ __forceinline__ void mma_bf16(float* c, const unsigned* a, const unsigned* b) {
    asm volatile(
        "mma.sync.aligned.m16n8k16.row.col.f32.bf16.bf16.f32 "
        "{%0,%1,%2,%3}, {%4,%5,%6,%7}, {%8,%9}, {%0,%1,%2,%3};"
        : "+f"(c[0]), "+f"(c[1]), "+f"(c[2]), "+f"(c[3])
        : "r"(a[0]), "r"(a[1]), "r"(a[2]), "r"(a[3]), "r"(b[0]), "r"(b[1]));
}

__global__ void __launch_bounds__(256) gemm_bf16(const __nv_bfloat16* __restrict__ A,
                                                 const __nv_bfloat16* __restrict__ W,
                                                 const float* __restrict__ R,
                                                 float* __restrict__ C,
                                                 __nv_bfloat16* __restrict__ Cbf,
                                                 int M, int N, int K) {
    extern __shared__ __nv_bfloat16 hsm[];
    __nv_bfloat16* As = hsm;
    __nv_bfloat16* Bs = hsm + GSTAGES * GBM * HSTR;
    unsigned smA = (unsigned)__cvta_generic_to_shared(As);
    unsigned smB = (unsigned)__cvta_generic_to_shared(Bs);

    int m0 = blockIdx.y * GBM;
    int n0 = blockIdx.x * GBN;
    int tid = threadIdx.x;
    int wid = tid >> 5, lane = tid & 31;
    int wm = (wid & 3) * 32;
    int wn = (wid >> 2) * 32;
    int gid = lane >> 2;
    int tig = lane & 3;
    int ar = tid >> 1, akq = (tid & 1) * 16;
    int br = tid >> 2, bkq = (tid & 3) * 8;

    const __nv_bfloat16* Abase = A + (size_t)(m0 + ar) * K + akq;
    bool bok = (n0 + br) < N;
    const __nv_bfloat16* Bbase = bok ? (W + (size_t)(n0 + br) * K + bkq) : W;
    int bsz = bok ? 16 : 0;
    unsigned adst = smA + (unsigned)(ar * HSTR + akq) * 2u;
    unsigned bdst = smB + (unsigned)(br * HSTR + bkq) * 2u;
    const unsigned aStage = GBM * HSTR * 2u;
    const unsigned bStage = GBN * HSTR * 2u;

    float acc[2][4][4];
    #pragma unroll
    for (int mi = 0; mi < 2; mi++)
        #pragma unroll
        for (int ni = 0; ni < 4; ni++)
            #pragma unroll
            for (int q = 0; q < 4; q++) acc[mi][ni][q] = 0.0f;

    int nIt = K / BK;
    #pragma unroll
    for (int s = 0; s < GSTAGES - 1; s++) {
        cp16(adst + s * aStage,      Abase + s * BK,     16);
        cp16(adst + s * aStage + 16, Abase + s * BK + 8, 16);
        cp16(bdst + s * bStage,      Bbase + (bok ? s * BK : 0), bsz);
        cp_commit();
    }

    for (int it = 0; it < nIt; it++) {
        cp_wait<GSTAGES - 2>();
        __syncthreads();
        int buf = it & (GSTAGES - 1);
        const __nv_bfloat16* Ab = As + buf * (GBM * HSTR);
        const __nv_bfloat16* Bb = Bs + buf * (GBN * HSTR);
        #pragma unroll
        for (int ks = 0; ks < 2; ks++) {
            int k16 = ks * 16;
            unsigned afr[2][4], bfr[4][2];
            #pragma unroll
            for (int mi = 0; mi < 2; mi++) {
                int rb = wm + mi * 16 + gid;
                afr[mi][0] = *(const unsigned*)(Ab + (rb)     * HSTR + k16 + tig * 2);
                afr[mi][1] = *(const unsigned*)(Ab + (rb + 8) * HSTR + k16 + tig * 2);
                afr[mi][2] = *(const unsigned*)(Ab + (rb)     * HSTR + k16 + tig * 2 + 8);
                afr[mi][3] = *(const unsigned*)(Ab + (rb + 8) * HSTR + k16 + tig * 2 + 8);
            }
            #pragma unroll
            for (int ni = 0; ni < 4; ni++) {
                int cb = wn + ni * 8 + gid;
                bfr[ni][0] = *(const unsigned*)(Bb + cb * HSTR + k16 + tig * 2);
                bfr[ni][1] = *(const unsigned*)(Bb + cb * HSTR + k16 + tig * 2 + 8);
            }
            #pragma unroll
            for (int mi = 0; mi < 2; mi++)
                #pragma unroll
                for (int ni = 0; ni < 4; ni++)
                    mma_bf16(acc[mi][ni], afr[mi], bfr[ni]);
        }
        int nx = it + GSTAGES - 1;
        if (nx < nIt) {
            int slot = nx & (GSTAGES - 1);
            cp16(adst + slot * aStage,      Abase + nx * BK,     16);
            cp16(adst + slot * aStage + 16, Abase + nx * BK + 8, 16);
            cp16(bdst + slot * bStage,      Bbase + (bok ? nx * BK : 0), bsz);
        }
        cp_commit();
    }

    #pragma unroll
    for (int mi = 0; mi < 2; mi++) {
        int row = m0 + wm + mi * 16 + gid;
        #pragma unroll
        for (int ni = 0; ni < 4; ni++) {
            int col = n0 + wn + ni * 8 + tig * 2;
            #pragma unroll
            for (int half = 0; half < 2; half++) {
                int rr = row + half * 8;
                float v0 = acc[mi][ni][half * 2];
                float v1 = acc[mi][ni][half * 2 + 1];
                if (col < N) {
                    if (Cbf) Cbf[(size_t)rr * N + col] = __float2bfloat16_rn(v0);
                    else {
                        if (R) v0 += R[(size_t)rr * N + col];
                        C[(size_t)rr * N + col] = v0;
                    }
                }
                if (col + 1 < N) {
                    if (Cbf) Cbf[(size_t)rr * N + col + 1] = __float2bfloat16_rn(v1);
                    else {
                        if (R) v1 += R[(size_t)rr * N + col + 1];
                        C[(size_t)rr * N + col + 1] = v1;
                    }
                }
            }
        }
    }
}

// ---------------------------------------------------------------------------
// Depthwise causal conv (k=4) + bias + SiLU, bf16 in -> bf16 out only.
// ---------------------------------------------------------------------------
__global__ void conv_silu_kernel(const __nv_bfloat16* __restrict__ xzb,
                                 const float* __restrict__ cw,
                                 const float* __restrict__ cb,
                                 __nv_bfloat16* __restrict__ xc_bf) {
    int idx = blockIdx.x * 256 + threadIdx.x;
    int d = idx & (DI - 1);
    int bt = idx >> 9;
    int b = bt >> 11;
    int l = bt & (LSEQ - 1);
    float acc = cb[d];
    #pragma unroll
    for (int k = 0; k < 4; k++) {
        int ls = l + k - 3;
        if (ls >= 0)
            acc += __bfloat162float(xzb[((size_t)((b << 11) | ls)) * (2 * DI) + d])
                   * cw[d * 4 + k];
    }
    float v = acc / (1.0f + __expf(-acc));
    xc_bf[(size_t)bt * DI + d] = __float2bfloat16_rn(v);
}

// ---------------------------------------------------------------------------
// Selective scan: fused dt, deferred reduce-scatter, cp.async double-buffered.
// ---------------------------------------------------------------------------
#define TCHUNK 64
#define SXW 148
#define SCAN_F (2*64*SXW + 512 + 512 + 128 + 8)
#define SCAN_SMEM (SCAN_F * 4 + 2 * (2*64*8*2))

__global__ void __launch_bounds__(256) scan_kernel(
        const float* __restrict__ xdbl,
        const __nv_bfloat16* __restrict__ xcb,
        const __nv_bfloat16* __restrict__ xzb,
        const float* __restrict__ A_log,
        const float* __restrict__ Dvec,
        const float* __restrict__ dtw,
        const float* __restrict__ dtb,
        __nv_bfloat16* __restrict__ y_bf) {
    extern __shared__ float ssm[];
    float* sX   = ssm;                      // [2][64][SXW]
    float* sdt  = sX + 2 * 64 * SXW;        // [64][8]
    float* sy   = sdt + 512;                // [64][8]
    float* sw   = sy + 512;                 // [8][16]
    float* sbias= sw + 128;                 // [8]
    __nv_bfloat16* szb  = (__nv_bfloat16*)(sbias + 8);  // [2][64][8]
    __nv_bfloat16* sxcb = szb + 2 * 64 * 8;             // [2][64][8]
    unsigned aX  = (unsigned)__cvta_generic_to_shared(sX);
    unsigned aZ  = (unsigned)__cvta_generic_to_shared(szb);
    unsigned aXC = (unsigned)__cvta_generic_to_shared(sxcb);

    int b = blockIdx.x >> 6;
    int dbase = (blockIdx.x & 63) * 8;
    int wid = threadIdx.x >> 5;
    int lane = threadIdx.x & 31;
    int d = dbase + wid;
    int tid = threadIdx.x;

    if (tid < 128) {
        int di = tid >> 4, r = tid & 15;
        sw[di * 16 + r] = dtw[(dbase + di) * DTR + r];
        if (r == 0) sbias[di] = dtb[dbase + di];
    }
    float A0 = -__expf(A_log[d * DS + lane]);
    float A1 = -__expf(A_log[d * DS + lane + 32]);
    float Dd = Dvec[d];
    float h0 = 0.0f, h1 = 0.0f;

    auto stage = [&](int buf, int t0) {
        size_t rowbase = (size_t)(b * LSEQ + t0);
        for (int i = tid; i < 64 * 36; i += 256) {
            int tt = i / 36, q = i - tt * 36;
            cp16(aX + (unsigned)(((buf * 64 + tt) * SXW) + q * 4) * 4u,
                 xdbl + (rowbase + tt) * XDBLW + q * 4, 16);
        }
        if (tid < 128) {
            int tt = tid & 63;
            if (tid < 64)
                cp16(aXC + (unsigned)((buf * 64 + tt) * 8) * 2u,
                     xcb + (rowbase + tt) * DI + dbase, 16);
            else
                cp16(aZ + (unsigned)((buf * 64 + tt) * 8) * 2u,
                     xzb + (rowbase + tt) * (2 * DI) + DI + dbase, 16);
        }
    };

    stage(0, 0);
    cp_commit();

    for (int c = 0; c < LSEQ / TCHUNK; c++) {
        int buf = c & 1;
        cp_wait<0>();
        __syncthreads();
        if (c + 1 < LSEQ / TCHUNK) stage(buf ^ 1, (c + 1) * TCHUNK);
        cp_commit();

        for (int i = tid; i < 512; i += 256) {
            int tt = i >> 3, di = i & 7;
            const float* xr = sX + (buf * 64 + tt) * SXW;
            float acc = sbias[di];
            #pragma unroll
            for (int r = 0; r < 16; r++) acc = fmaf(xr[r], sw[di * 16 + r], acc);
            sdt[tt * 8 + di] = (acc > 20.0f) ? acc : __logf(1.0f + __expf(acc));
        }
        __syncthreads();

        #pragma unroll 1
        for (int g = 0; g < TCHUNK / 32; g++) {
            float part[32];
            #pragma unroll
            for (int j = 0; j < 32; j++) {
                int tt = g * 32 + j;
                const float* xr = sX + (buf * 64 + tt) * SXW;
                float dtv = sdt[tt * 8 + wid];
                float xcv = __bfloat162float(sxcb[(buf * 64 + tt) * 8 + wid]);
                float du = dtv * xcv;
                float dA0 = __expf(dtv * A0);
                float dA1 = __expf(dtv * A1);
                h0 = fmaf(dA0, h0, du * xr[16 + lane]);
                h1 = fmaf(dA1, h1, du * xr[48 + lane]);
                part[j] = fmaf(h0, xr[80 + lane], h1 * xr[112 + lane]);
            }
            #pragma unroll
            for (int s = 16; s >= 1; s >>= 1) {
                bool up = (lane & s) != 0;
                #pragma unroll
                for (int i2 = 0; i2 < 16; i2++) {
                    if (i2 >= s) break;
                    float keep = up ? part[i2 + s] : part[i2];
                    float send = up ? part[i2] : part[i2 + s];
                    part[i2] = keep + __shfl_xor_sync(0xffffffffu, send, s);
                }
            }
            int tt = g * 32 + lane;
            float xcv = __bfloat162float(sxcb[(buf * 64 + tt) * 8 + wid]);
            float zv = __bfloat162float(szb[(buf * 64 + tt) * 8 + wid]);
            float gate = zv / (1.0f + __expf(-zv));
            sy[tt * 8 + wid] = fmaf(xcv, Dd, part[0]) * gate;
        }
        __syncthreads();
        for (int i = tid; i < TCHUNK * 8; i += 256) {
            int tt = i >> 3, di = i & 7;
            y_bf[(size_t)(b * LSEQ + c * TCHUNK + tt) * DI + dbase + di] =
                __float2bfloat16_rn(sy[tt * 8 + di]);
        }
        __syncthreads();
    }
}

// ---------------------------------------------------------------------------
// Forward packed-real 2048-pt FFT (DIF, natural -> bit-reversed).
// 4 channels per block packed as 2 complex FFTs (z = ch_even + i*ch_odd),
// then Hermitian separation into 4 bf16 spectra (bit-reversed positions).
// ---------------------------------------------------------------------------
#define FSTR 2049
#define FFTF_SMEM (4 * FSTR * 4)          // 2 cols x (re, im)
#define FFTI_SMEM (12 * FSTR * 4)         // 4ch spectra (8 arrays) + 2col Z (4)

__global__ void __launch_bounds__(512) fft_fwd_kernel(const __nv_bfloat16* __restrict__ xin,
                                                      __nv_bfloat16* __restrict__ dR,
                                                      __nv_bfloat16* __restrict__ dI) {
    extern __shared__ float sm[];
    float* zr = sm;                // [2][FSTR]
    float* zi = sm + 2 * FSTR;     // [2][FSTR]
    int b = blockIdx.x >> 6;
    int c0 = (blockIdx.x & 63) * 4;
    size_t base = (size_t)b * LSEQ * DIMC + c0;
    int tid = threadIdx.x;

    // pack: col0 = ch0 + i*ch1, col1 = ch2 + i*ch3
    for (int n = tid; n < 2048; n += 512) {
        const __nv_bfloat162* p = (const __nv_bfloat162*)(xin + base + (size_t)n * DIMC);
        __nv_bfloat162 a = p[0], bb = p[1];
        zr[0 * FSTR + n] = __bfloat162float(a.x);
        zi[0 * FSTR + n] = __bfloat162float(a.y);
        zr[1 * FSTR + n] = __bfloat162float(bb.x);
        zi[1 * FSTR + n] = __bfloat162float(bb.y);
    }
    __syncthreads();

    #pragma unroll
    for (int hb = 10; hb >= 0; hb--) {
        int half = 1 << hb;
        float th = -PI_F / (float)half;
        for (int e = tid; e < 2048; e += 512) {
            int col = e >> 10, idx = e & 1023;
            int j = idx & (half - 1);
            int pos = ((idx >> hb) << (hb + 1)) + j;
            float* cr = zr + col * FSTR;
            float* ci = zi + col * FSTR;
            float ar = cr[pos],        ai = ci[pos];
            float br = cr[pos + half], bi = ci[pos + half];
            float wi, wr;
            __sincosf(th * (float)j, &wi, &wr);
            float xr = ar - br, xi = ai - bi;
            cr[pos] = ar + br;  ci[pos] = ai + bi;
            cr[pos + half] = xr * wr - xi * wi;
            ci[pos + half] = xr * wi + xi * wr;
        }
        __syncthreads();
    }

    // Hermitian separation: position p holds natural freq k = rev11(p);
    // partner (natural N-k) sits at pp = rev11((2048 - k) & 2047).
    for (int e = tid; e < 4096; e += 512) {
        int col = e >> 11, p = e & 2047;
        int k = rev11(p);
        int pp = rev11((2048 - k) & 2047);
        float ar = zr[col * FSTR + p],  ai = zi[col * FSTR + p];
        float br = zr[col * FSTR + pp], bi = zi[col * FSTR + pp];
        float f0r = 0.5f * (ar + br), f0i = 0.5f * (ai - bi);
        float f1r = 0.5f * (ai + bi), f1i = 0.5f * (br - ar);
        __nv_bfloat162* pr = (__nv_bfloat162*)(dR + base + (size_t)p * DIMC + 2 * col);
        __nv_bfloat162* pi = (__nv_bfloat162*)(dI + base + (size_t)p * DIMC + 2 * col);
        *pr = __nv_bfloat162(__float2bfloat16_rn(f0r), __float2bfloat16_rn(f1r));
        *pi = __nv_bfloat162(__float2bfloat16_rn(f0i), __float2bfloat16_rn(f1i));
    }
}

// ---------------------------------------------------------------------------
// Inverse packed-real 2048-pt FFT: Hermitian-symmetrize 4 spectra, pack into
// 2 complex columns, one DIT IFFT each (bit-reversed -> natural); Re -> even
// channel, Im -> odd channel; + fp32 residual.
// ---------------------------------------------------------------------------
__global__ void __launch_bounds__(512) fft_inv_kernel(const __nv_bfloat16* __restrict__ dR,
                                                      const __nv_bfloat16* __restrict__ dI,
                                                      const float* __restrict__ x1,
                                                      float* __restrict__ out) {
    extern __shared__ float sm[];
    float* fr = sm;                 // [4][FSTR]
    float* fi = sm + 4 * FSTR;      // [4][FSTR]
    float* zr = sm + 8 * FSTR;      // [2][FSTR]
    float* zi = sm + 10 * FSTR;     // [2][FSTR]
    int b = blockIdx.x >> 6;
    int c0 = (blockIdx.x & 63) * 4;
    size_t base = (size_t)b * LSEQ * DIMC + c0;
    int tid = threadIdx.x;

    for (int n = tid; n < 2048; n += 512) {
        const __nv_bfloat162* pr = (const __nv_bfloat162*)(dR + base + (size_t)n * DIMC);
        const __nv_bfloat162* pi = (const __nv_bfloat162*)(dI + base + (size_t)n * DIMC);
        __nv_bfloat162 r0 = pr[0], r1 = pr[1], i0 = pi[0], i1 = pi[1];
        fr[0 * FSTR + n] = __bfloat162float(r0.x);
        fr[1 * FSTR + n] = __bfloat162float(r0.y);
        fr[2 * FSTR + n] = __bfloat162float(r1.x);
        fr[3 * FSTR + n] = __bfloat162float(r1.y);
        fi[0 * FSTR + n] = __bfloat162float(i0.x);
        fi[1 * FSTR + n] = __bfloat162float(i0.y);
        fi[2 * FSTR + n] = __bfloat162float(i1.x);
        fi[3 * FSTR + n] = __bfloat162float(i1.y);
    }
    __syncthreads();

    // Z[p] = H_even[p] + i*H_odd[p],  H_c[p] = 0.5*(F_c[p] + conj(F_c[pp]))
    for (int e = tid; e < 4096; e += 512) {
        int col = e >> 11, p = e & 2047;
        int pp = rev11((2048 - rev11(p)) & 2047);
        int ca = 2 * col, cb = 2 * col + 1;
        float Zr = 0.5f * (fr[ca * FSTR + p] + fr[ca * FSTR + pp])
                 - 0.5f * (fi[cb * FSTR + p] - fi[cb * FSTR + pp]);
        float Zi = 0.5f * (fi[ca * FSTR + p] - fi[ca * FSTR + pp])
                 + 0.5f * (fr[cb * FSTR + p] + fr[cb * FSTR + pp]);
        zr[col * FSTR + p] = Zr;
        zi[col * FSTR + p] = Zi;
    }
    __syncthreads();

    #pragma unroll
    for (int hb = 0; hb <= 10; hb++) {
        int half = 1 << hb;
        float th = PI_F / (float)half;
        for (int e = tid; e < 2048; e += 512) {
            int col = e >> 10, idx = e & 1023;
            int j = idx & (half - 1);
            int pos = ((idx >> hb) << (hb + 1)) + j;
            float* cr = zr + col * FSTR;
            float* ci = zi + col * FSTR;
            float ar = cr[pos],        ai = ci[pos];
            float br = cr[pos + half], bi = ci[pos + half];
            float wi, wr;
            __sincosf(th * (float)j, &wi, &wr);
            float tr = br * wr - bi * wi;
            float ti = br * wi + bi * wr;
            cr[pos] = ar + tr;         ci[pos] = ai + ti;
            cr[pos + half] = ar - tr;  ci[pos + half] = ai - ti;
        }
        __syncthreads();
    }

    for (int n = tid; n < 2048; n += 512) {
        size_t a = base + (size_t)n * DIMC;
        float4 rx = *(const float4*)(x1 + a);
        float4 o;
        o.x = rx.x + zr[0 * FSTR + n];
        o.y = rx.y + zi[0 * FSTR + n];
        o.z = rx.z + zr[1 * FSTR + n];
        o.w = rx.w + zi[1 * FSTR + n];
        *(float4*)(out + a) = o;
    }
}

// ---------------------------------------------------------------------------
// EinFFT MLP with DFT4/IDFT4 folded in; bf16 global I/O, f32x2 packed FMA.
// ---------------------------------------------------------------------------
__global__ void __launch_bounds__(256) einfft_mlp_kernel(
        __nv_bfloat16* __restrict__ fR, __nv_bfloat16* __restrict__ fI,
        const float* __restrict__ cw1, const float* __restrict__ cb1,
        const float* __restrict__ cw2, const float* __restrict__ cb2) {
    __shared__ __align__(16) float sR[2048], sI[2048];
    __shared__ __align__(16) float tR[2048], tI[2048];
    int row0 = blockIdx.x * 8;
    int tid = threadIdx.x;
    {
        const __nv_bfloat162* fr2 = (const __nv_bfloat162*)(fR + (size_t)row0 * DIMC);
        const __nv_bfloat162* fi2 = (const __nv_bfloat162*)(fI + (size_t)row0 * DIMC);
        for (int i = tid; i < 1024; i += 256) {
            __nv_bfloat162 r = fr2[i], m = fi2[i];
            sR[2*i] = __bfloat162float(r.x); sR[2*i+1] = __bfloat162float(r.y);
            sI[2*i] = __bfloat162float(m.x); sI[2*i+1] = __bfloat162float(m.y);
        }
    }
    __syncthreads();

    const float sc = SQRT_INV_8192;
    #pragma unroll
    for (int g = tid; g < 512; g += 256) {
        int r = g >> 6, s = g & 63;
        int p = r * 256 + s;
        float r0 = sR[p],       i0 = sI[p];
        float r1 = sR[p + 64],  i1 = sI[p + 64];
        float r2 = sR[p + 128], i2 = sI[p + 128];
        float r3 = sR[p + 192], i3 = sI[p + 192];
        sR[p]       = (r0 + r1 + r2 + r3) * sc;
        sI[p]       = (i0 + i1 + i2 + i3) * sc;
        sR[p + 64]  = (r0 + i1 - r2 - i3) * sc;
        sI[p + 64]  = (i0 - r1 - i2 + r3) * sc;
        sR[p + 128] = (r0 - r1 + r2 - r3) * sc;
        sI[p + 128] = (i0 - i1 + i2 - i3) * sc;
        sR[p + 192] = (r0 - i1 - r2 + i3) * sc;
        sI[p + 192] = (i0 + r1 - i2 - r3) * sc;
    }
    __syncthreads();

    int k = tid >> 6, o = tid & 63;

    // ---- layer 1 (relu), f32x2 over dd pairs ----
    {
        const float* w0 = cw1 + k * 4096;
        const float* w1 = cw1 + 16384 + k * 4096;
        float bR = cb1[k * 64 + o];
        float bI = cb1[256 + k * 64 + o];
        u64 aRp[8], aIp[8];
        #pragma unroll
        for (int r = 0; r < 8; r++) {
            aRp[r] = packf2(bR, 0.0f);
            aIp[r] = packf2(bI, 0.0f);
        }
        #pragma unroll 4
        for (int dd = 0; dd < 64; dd += 2) {
            float wa0 = w0[dd * 64 + o], wa1 = w0[(dd + 1) * 64 + o];
            float wb0 = w1[dd * 64 + o], wb1 = w1[(dd + 1) * 64 + o];
            u64 wa_p  = packf2(wa0, wa1);
            u64 wb_p  = packf2(wb0, wb1);
            u64 wbn_p = packf2(-wb0, -wb1);
            int sb = k * 64 + dd;
            #pragma unroll
            for (int r = 0; r < 8; r++) {
                float2 xr2 = *(const float2*)&sR[r * 256 + sb];
                float2 xi2 = *(const float2*)&sI[r * 256 + sb];
                u64 xr_p = packf2(xr2.x, xr2.y);
                u64 xi_p = packf2(xi2.x, xi2.y);
                fma2(aRp[r], xr_p, wa_p, aRp[r]);
                fma2(aRp[r], xi_p, wbn_p, aRp[r]);
                fma2(aIp[r], xr_p, wb_p, aIp[r]);
                fma2(aIp[r], xi_p, wa_p, aIp[r]);
            }
        }
        #pragma unroll
        for (int r = 0; r < 8; r++) {
            float lo, hi;
            unpackf2(aRp[r], lo, hi);
            tR[r * 256 + tid] = fmaxf(lo + hi, 0.0f);
            unpackf2(aIp[r], lo, hi);
            tI[r * 256 + tid] = fmaxf(lo + hi, 0.0f);
        }
    }
    __syncthreads();

    // ---- layer 2 (softshrink), f32x2 over dd pairs ----
    {
        const float* w0 = cw2 + k * 4096;
        const float* w1 = cw2 + 16384 + k * 4096;
        float bR = cb2[k * 64 + o];
        float bI = cb2[256 + k * 64 + o];
        u64 aRp[8], aIp[8];
        #pragma unroll
        for (int r = 0; r < 8; r++) {
            aRp[r] = packf2(bR, 0.0f);
            aIp[r] = packf2(bI, 0.0f);
        }
        #pragma unroll 4
        for (int dd = 0; dd < 64; dd += 2) {
            float wa0 = w0[dd * 64 + o], wa1 = w0[(dd + 1) * 64 + o];
            float wb0 = w1[dd * 64 + o], wb1 = w1[(dd + 1) * 64 + o];
            u64 wa_p  = packf2(wa0, wa1);
            u64 wb_p  = packf2(wb0, wb1);
            u64 wbn_p = packf2(-wb0, -wb1);
            int sb = k * 64 + dd;
            #pragma unroll
            for (int r = 0; r < 8; r++) {
                float2 xr2 = *(const float2*)&tR[r * 256 + sb];
                float2 xi2 = *(const float2*)&tI[r * 256 + sb];
                u64 xr_p = packf2(xr2.x, xr2.y);
                u64 xi_p = packf2(xi2.x, xi2.y);
                fma2(aRp[r], xr_p, wa_p, aRp[r]);
                fma2(aRp[r], xi_p, wbn_p, aRp[r]);
                fma2(aIp[r], xr_p, wb_p, aIp[r]);
                fma2(aIp[r], xi_p, wa_p, aIp[r]);
            }
        }
        #pragma unroll
        for (int r = 0; r < 8; r++) {
            float lo, hi;
            unpackf2(aRp[r], lo, hi);
            float vR = lo + hi;
            unpackf2(aIp[r], lo, hi);
            float vI = lo + hi;
            vR = (vR > LAMBDA_SS) ? vR - LAMBDA_SS
                 : ((vR < -LAMBDA_SS) ? vR + LAMBDA_SS : 0.0f);
            vI = (vI > LAMBDA_SS) ? vI - LAMBDA_SS
                 : ((vI < -LAMBDA_SS) ? vI + LAMBDA_SS : 0.0f);
            sR[r * 256 + tid] = vR;
            sI[r * 256 + tid] = vI;
        }
    }
    __syncthreads();

    #pragma unroll
    for (int g = tid; g < 512; g += 256) {
        int r = g >> 6, s = g & 63;
        int p = r * 256 + s;
        float R0 = sR[p],       I0 = sI[p];
        float R1 = sR[p + 64],  I1 = sI[p + 64];
        float R2 = sR[p + 128], I2 = sI[p + 128];
        float R3 = sR[p + 192], I3 = sI[p + 192];
        sR[p]       = (R0 + R1 + R2 + R3) * sc;
        sI[p]       = (I0 + I1 + I2 + I3) * sc;
        sR[p + 64]  = (R0 - I1 - R2 + I3) * sc;
        sI[p + 64]  = (I0 + R1 - I2 - R3) * sc;
        sR[p + 128] = (R0 - R1 + R2 - R3) * sc;
        sI[p + 128] = (I0 - I1 + I2 - I3) * sc;
        sR[p + 192] = (R0 + I1 - R2 - I3) * sc;
        sI[p + 192] = (I0 - R1 - I2 + R3) * sc;
    }
    __syncthreads();

    {
        __nv_bfloat162* fr2 = (__nv_bfloat162*)(fR + (size_t)row0 * DIMC);
        __nv_bfloat162* fi2 = (__nv_bfloat162*)(fI + (size_t)row0 * DIMC);
        for (int i = tid; i < 1024; i += 256) {
            fr2[i] = __nv_bfloat162(__float2bfloat16_rn(sR[2*i]),
                                    __float2bfloat16_rn(sR[2*i+1]));
            fi2[i] = __nv_bfloat162(__float2bfloat16_rn(sI[2*i]),
                                    __float2bfloat16_rn(sI[2*i+1]));
        }
    }
}

// ---------------------------------------------------------------------------
// Launch
// ---------------------------------------------------------------------------
extern "C" void kernel_launch(void* const* d_in, const int* in_sizes, int n_in,
                              void* d_out, int out_size) {
    const float* x         = (const float*)d_in[0];
    const float* norm1_w   = (const float*)d_in[1];
    const float* norm1_b   = (const float*)d_in[2];
    const float* in_proj_w = (const float*)d_in[3];
    const float* conv_w    = (const float*)d_in[4];
    const float* conv_b    = (const float*)d_in[5];
    const float* x_proj_w  = (const float*)d_in[6];
    const float* dt_proj_w = (const float*)d_in[7];
    const float* dt_proj_b = (const float*)d_in[8];
    const float* A_log     = (const float*)d_in[9];
    const float* Dvec      = (const float*)d_in[10];
    const float* out_proj_w= (const float*)d_in[11];
    const float* norm2_w   = (const float*)d_in[12];
    const float* norm2_b   = (const float*)d_in[13];
    const float* cw1       = (const float*)d_in[14];
    const float* cb1       = (const float*)d_in[15];
    const float* cw2       = (const float*)d_in[16];
    const float* cb2       = (const float*)d_in[17];
    float* out = (float*)d_out;

    void* sp = nullptr;
    cudaGetSymbolAddress(&sp, SCRATCH);
    float* S = (float*)sp;
    float* s_xdbl = S + O_XDBL;
    float* s_x1   = S + O_X1;
    __nv_bfloat16* s_xzb  = (__nv_bfloat16*)(S + O_XZB);
    __nv_bfloat16* s_xnbf = (__nv_bfloat16*)(S + O_XNBF);
    __nv_bfloat16* s_xcbf = (__nv_bfloat16*)(S + O_XCBF);
    __nv_bfloat16* s_ybf  = (__nv_bfloat16*)(S + O_YBF);
    __nv_bfloat16* s_xn2b = (__nv_bfloat16*)(S + O_XN2B);
    __nv_bfloat16* s_frb  = (__nv_bfloat16*)(S + O_FRB);
    __nv_bfloat16* s_fib  = (__nv_bfloat16*)(S + O_FIB);
    __nv_bfloat16* s_wbf  = (__nv_bfloat16*)(S + O_WBF);
    __nv_bfloat16* win_bf = s_wbf;
    __nv_bfloat16* wx_bf  = s_wbf + W_IN_SZ;
    __nv_bfloat16* wo_bf  = s_wbf + W_IN_SZ + W_X_SZ;

    static int attr_done = 0;
    if (!attr_done) {
        cudaFuncSetAttribute(fft_fwd_kernel,
                             cudaFuncAttributeMaxDynamicSharedMemorySize, FFTF_SMEM);
        cudaFuncSetAttribute(fft_inv_kernel,
                             cudaFuncAttributeMaxDynamicSharedMemorySize, FFTI_SMEM);
        cudaFuncSetAttribute(gemm_bf16,
                             cudaFuncAttributeMaxDynamicSharedMemorySize, GEMM_SMEM);
        cudaFuncSetAttribute(scan_kernel,
                             cudaFuncAttributeMaxDynamicSharedMemorySize, SCAN_SMEM);
        attr_done = 1;
    }

    // 0) prep: weight convert + LN1 (merged)
    prep_kernel<<<WCVT_BLOCKS + NTOK / 8, 256>>>(in_proj_w, x_proj_w, out_proj_w,
                                                 s_wbf, x, norm1_w, norm1_b, s_xnbf);
    // 1) in_proj -> bf16 xz
    gemm_bf16<<<dim3((2 * DI) / GBN, NTOK / GBM), 256, GEMM_SMEM>>>(
        s_xnbf, win_bf, nullptr, nullptr, s_xzb, NTOK, 2 * DI, DIMC);
    // 2) conv + silu -> bf16 xc
    conv_silu_kernel<<<(NTOK * DI) / 256, 256>>>(s_xzb, conv_w, conv_b, s_xcbf);
    // 3) x_proj -> fp32 xdbl
    gemm_bf16<<<dim3((XDBLW + GBN - 1) / GBN, NTOK / GBM), 256, GEMM_SMEM>>>(
        s_xcbf, wx_bf, nullptr, s_xdbl, nullptr, NTOK, XDBLW, DI);
    // 4) selective scan -> bf16 y
    scan_kernel<<<BATCH * (DI / 8), 256, SCAN_SMEM>>>(
        s_xdbl, s_xcbf, s_xzb, A_log, Dvec, dt_proj_w, dt_proj_b, s_ybf);
    // 5) out_proj + residual -> fp32 x1
    gemm_bf16<<<dim3(DIMC / GBN, NTOK / GBM), 256, GEMM_SMEM>>>(
        s_ybf, wo_bf, x, s_x1, nullptr, NTOK, DIMC, DI);
    // 6) LN2 -> bf16
    ln_kernel<<<NTOK / 8, 256>>>(s_x1, norm2_w, norm2_b, nullptr, s_xn2b);
    // 7) forward packed-real FFT (bf16 in/out, 2 complex FFTs per 4 channels)
    fft_fwd_kernel<<<128, 512, FFTF_SMEM>>>(s_xn2b, s_frb, s_fib);
    // 8) fused EinFFT MLP
    einfft_mlp_kernel<<<NTOK / 8, 256>>>(s_frb, s_fib, cw1, cb1, cw2, cb2);
    // 9) inverse packed-real FFT + residual -> out
    fft_inv_kernel<<<128, 512, FFTI_SMEM>>>(s_frb, s_fib, s_x1, out);
}